// round 2
// baseline (speedup 1.0000x reference)
#include <cuda_runtime.h>
#include <math.h>

#define DEV_INLINE __device__ __forceinline__

// Problem constants
constexpr int Mdim = 768;
constexpr int Vv   = 32000;
constexpr int Rr   = 48;
constexpr int Nn   = 16;
constexpr int Kk   = 4;
constexpr int Ll   = 2;
constexpr int Hh   = 1536;      // 2*M
constexpr int Bb   = 2;
constexpr int Ss   = 1024;
constexpr int BS   = Bb * Ss;   // 2048 rows
constexpr int H2   = 2 * Hh;    // 3072
constexpr int XD   = Rr + 2 * Nn; // 80

// ---------------- scratch (device globals; no allocation allowed) ----------
__device__ float g_x   [BS * Mdim];   // residual stream
__device__ float g_xr  [BS * H2];     // lin_in output (xh | residual)
__device__ float g_u   [BS * Hh];     // post conv+silu (u)
__device__ float g_xdbl[BS * XD];     // delta_part | B | C
__device__ float g_delta[BS * Hh];    // softplus(delta)
__device__ float g_y   [BS * Hh];     // scan output, then gated in-place
__device__ float g_mo  [BS * Mdim];   // mamba layer output (pre-norm)
__device__ float g_xn  [BS * Mdim];   // final normed x

// ---------------- helpers ----------------
DEV_INLINE float siluf(float v)     { return v / (1.f + expf(-v)); }
DEV_INLINE float softplusf(float v) { return v > 20.f ? v : log1pf(expf(v)); }

DEV_INLINE float warp_sum(float v) {
    #pragma unroll
    for (int o = 16; o; o >>= 1) v += __shfl_xor_sync(0xffffffffu, v, o);
    return v;
}

// ---------------- embedding gather ----------------
__global__ void embed_kernel(const int* __restrict__ ids,
                             const float* __restrict__ emb,
                             float* __restrict__ x) {
    int idx = blockIdx.x * blockDim.x + threadIdx.x;
    if (idx >= BS * Mdim) return;
    int row = idx / Mdim;
    int m   = idx - row * Mdim;
    x[idx] = emb[ids[row] * Mdim + m];
}

// ---------------- generic NT GEMM: C[i,j] = sum_k A[i,k]*W[j,k] + bias[j] ---
// A: lda row stride. W: [NN, KK] contiguous. ACT: 0=none, 1=softplus
template<int BM, int BN, int BK, int TM, int TN, int ACT>
__global__ __launch_bounds__((BM/TM)*(BN/TN))
void gemm_nt_kernel(const float* __restrict__ A, int lda,
                    const float* __restrict__ W,
                    const float* __restrict__ bias,
                    float* __restrict__ C, int ldc,
                    int MM, int NN, int KK) {
    constexpr int NTX = BN / TN;
    constexpr int NTY = BM / TM;
    constexpr int NT  = NTX * NTY;
    __shared__ float As[BK][BM];
    __shared__ float Ws[BK][BN];

    const int tid = threadIdx.x;
    const int tx  = tid % NTX;
    const int ty  = tid / NTX;
    const int i0  = blockIdx.y * BM;
    const int j0  = blockIdx.x * BN;

    float acc[TM][TN];
    #pragma unroll
    for (int m = 0; m < TM; m++)
        #pragma unroll
        for (int n = 0; n < TN; n++) acc[m][n] = 0.f;

    for (int k0 = 0; k0 < KK; k0 += BK) {
        #pragma unroll
        for (int idx = tid; idx < BM * BK; idx += NT) {
            int i = idx / BK, k = idx % BK;
            int gi = i0 + i, gk = k0 + k;
            As[k][i] = (gi < MM && gk < KK) ? A[gi * lda + gk] : 0.f;
        }
        #pragma unroll
        for (int idx = tid; idx < BN * BK; idx += NT) {
            int j = idx / BK, k = idx % BK;
            int gj = j0 + j, gk = k0 + k;
            Ws[k][j] = (gj < NN && gk < KK) ? W[gj * KK + gk] : 0.f;
        }
        __syncthreads();

        #pragma unroll
        for (int kk = 0; kk < BK; kk++) {
            float ra[TM], rb[TN];
            #pragma unroll
            for (int m = 0; m < TM; m++) ra[m] = As[kk][ty * TM + m];
            #pragma unroll
            for (int n = 0; n < TN; n++) rb[n] = Ws[kk][tx * TN + n];
            #pragma unroll
            for (int m = 0; m < TM; m++)
                #pragma unroll
                for (int n = 0; n < TN; n++) acc[m][n] += ra[m] * rb[n];
        }
        __syncthreads();
    }

    #pragma unroll
    for (int m = 0; m < TM; m++) {
        int gi = i0 + ty * TM + m;
        if (gi >= MM) continue;
        #pragma unroll
        for (int n = 0; n < TN; n++) {
            int gj = j0 + tx * TN + n;
            if (gj >= NN) continue;
            float v = acc[m][n] + bias[gj];
            if (ACT == 1) v = softplusf(v);
            C[gi * ldc + gj] = v;
        }
    }
}

// ---------------- depthwise causal conv (K=4) + silu ----------------
__global__ void conv_silu_kernel(const float* __restrict__ xr,
                                 const float* __restrict__ cw,
                                 const float* __restrict__ cb,
                                 float* __restrict__ u) {
    int idx = blockIdx.x * blockDim.x + threadIdx.x;
    if (idx >= BS * Hh) return;
    int h   = idx % Hh;
    int row = idx / Hh;
    int s   = row % Ss;
    int b   = row / Ss;
    float acc = cb[h];
    #pragma unroll
    for (int k = 0; k < Kk; k++) {
        int sp = s - (Kk - 1) + k;
        if (sp >= 0)
            acc += cw[h * Kk + k] * xr[(b * Ss + sp) * H2 + h];
    }
    u[idx] = siluf(acc);
}

// ---------------- selective scan: warp per (b,h), lanes over n --------------
__global__ void scan_kernel(const float* __restrict__ delta,
                            const float* __restrict__ u,
                            const float* __restrict__ xdbl,
                            const float* __restrict__ Dp,
                            float* __restrict__ y) {
    int gwarp = (blockIdx.x * blockDim.x + threadIdx.x) >> 5;
    if (gwarp >= Bb * Hh) return;
    int lane = threadIdx.x & 31;
    int n    = lane & 15;                 // lanes 16..31 duplicate 0..15
    int b    = gwarp / Hh;
    int h    = gwarp - b * Hh;

    const float An = -(float)(n + 1);
    const float Dh = Dp[h];
    float state = 0.f;

    int base = b * Ss;
    for (int s = 0; s < Ss; s++) {
        int row = base + s;
        float dv = __ldg(delta + row * Hh + h);
        float uv = __ldg(u + row * Hh + h);
        float Bn = __ldg(xdbl + row * XD + Rr + n);
        float Cn = __ldg(xdbl + row * XD + Rr + Nn + n);
        float dA = expf(dv * An);
        state = dA * state + dv * Bn * uv;
        float val = state * Cn;
        val += __shfl_xor_sync(0xffffffffu, val, 8);
        val += __shfl_xor_sync(0xffffffffu, val, 4);
        val += __shfl_xor_sync(0xffffffffu, val, 2);
        val += __shfl_xor_sync(0xffffffffu, val, 1);
        if (lane == 0) y[row * Hh + h] = val + uv * Dh;
    }
}

// ---------------- gate: y *= silu(residual) ----------------
__global__ void gate_kernel(float* __restrict__ y,
                            const float* __restrict__ xr) {
    int idx = blockIdx.x * blockDim.x + threadIdx.x;
    if (idx >= BS * Hh) return;
    int h   = idx % Hh;
    int row = idx / Hh;
    y[idx] *= siluf(xr[row * H2 + Hh + h]);
}

// ---------------- x += rmsnorm(mo) * w ----------------
__global__ void rmsnorm_add_kernel(float* __restrict__ x,
                                   const float* __restrict__ mo,
                                   const float* __restrict__ w) {
    int row = blockIdx.x;
    const float* r = mo + row * Mdim;
    float ss = 0.f;
    for (int m = threadIdx.x; m < Mdim; m += blockDim.x) {
        float v = r[m];
        ss += v * v;
    }
    __shared__ float sh[8];
    ss = warp_sum(ss);
    int wid = threadIdx.x >> 5, lane = threadIdx.x & 31;
    if (lane == 0) sh[wid] = ss;
    __syncthreads();
    if (wid == 0) {
        float v = (lane < (int)(blockDim.x >> 5)) ? sh[lane] : 0.f;
        v = warp_sum(v);
        if (lane == 0) sh[0] = v;
    }
    __syncthreads();
    float scale = rsqrtf(sh[0] / (float)Mdim + 1e-15f);
    float* xp = x + row * Mdim;
    for (int m = threadIdx.x; m < Mdim; m += blockDim.x)
        xp[m] += r[m] * scale * w[m];
}

// ---------------- xn = rmsnorm(x) * w ----------------
__global__ void rmsnorm_final_kernel(const float* __restrict__ x,
                                     const float* __restrict__ w,
                                     float* __restrict__ xn) {
    int row = blockIdx.x;
    const float* r = x + row * Mdim;
    float ss = 0.f;
    for (int m = threadIdx.x; m < Mdim; m += blockDim.x) {
        float v = r[m];
        ss += v * v;
    }
    __shared__ float sh[8];
    ss = warp_sum(ss);
    int wid = threadIdx.x >> 5, lane = threadIdx.x & 31;
    if (lane == 0) sh[wid] = ss;
    __syncthreads();
    if (wid == 0) {
        float v = (lane < (int)(blockDim.x >> 5)) ? sh[lane] : 0.f;
        v = warp_sum(v);
        if (lane == 0) sh[0] = v;
    }
    __syncthreads();
    float scale = rsqrtf(sh[0] / (float)Mdim + 1e-15f);
    float* op = xn + row * Mdim;
    for (int m = threadIdx.x; m < Mdim; m += blockDim.x)
        op[m] = r[m] * scale * w[m];
}

// ---------------- launch ----------------
extern "C" void kernel_launch(void* const* d_in, const int* in_sizes, int n_in,
                              void* d_out, int out_size) {
    const int*   ids = (const int*)  d_in[0];
    const float* emb = (const float*)d_in[1];
    const float* liw = (const float*)d_in[2];
    const float* lib = (const float*)d_in[3];
    const float* cw  = (const float*)d_in[4];
    const float* cb  = (const float*)d_in[5];
    const float* lxw = (const float*)d_in[6];
    const float* lxb = (const float*)d_in[7];
    const float* ldw = (const float*)d_in[8];
    const float* ldb = (const float*)d_in[9];
    const float* low = (const float*)d_in[10];
    const float* lob = (const float*)d_in[11];
    const float* Dp  = (const float*)d_in[12];
    const float* bnw = (const float*)d_in[13];
    const float* fnw = (const float*)d_in[14];
    const float* hw  = (const float*)d_in[15];
    const float* hb  = (const float*)d_in[16];
    float* out = (float*)d_out;

    float *x, *xr, *u, *xdbl, *delta, *y, *mo, *xn;
    cudaGetSymbolAddress((void**)&x,     g_x);
    cudaGetSymbolAddress((void**)&xr,    g_xr);
    cudaGetSymbolAddress((void**)&u,     g_u);
    cudaGetSymbolAddress((void**)&xdbl,  g_xdbl);
    cudaGetSymbolAddress((void**)&delta, g_delta);
    cudaGetSymbolAddress((void**)&y,     g_y);
    cudaGetSymbolAddress((void**)&mo,    g_mo);
    cudaGetSymbolAddress((void**)&xn,    g_xn);

    embed_kernel<<<(BS * Mdim + 255) / 256, 256>>>(ids, emb, x);

    for (int l = 0; l < Ll; l++) {
        // lin_in: [BS, M] x [3072, M]^T -> xr [BS, 3072]
        gemm_nt_kernel<128,128,8,8,8,0><<<dim3(H2/128, BS/128), 256>>>(
            x, Mdim, liw + (size_t)l * H2 * Mdim, lib + (size_t)l * H2,
            xr, H2, BS, H2, Mdim);

        // depthwise conv + silu -> u
        conv_silu_kernel<<<(BS * Hh + 255) / 256, 256>>>(
            xr, cw + (size_t)l * Hh * Kk, cb + (size_t)l * Hh, u);

        // lin_x: [BS, H] x [80, H]^T -> xdbl [BS, 80]
        gemm_nt_kernel<64,64,8,4,4,0><<<dim3((XD + 63)/64, BS/64), 256>>>(
            u, Hh, lxw + (size_t)l * XD * Hh, lxb + (size_t)l * XD,
            xdbl, XD, BS, XD, Hh);

        // lin_dt + softplus: [BS, 48](stride 80) x [1536, 48]^T -> delta [BS, 1536]
        gemm_nt_kernel<128,128,8,8,8,1><<<dim3(Hh/128, BS/128), 256>>>(
            xdbl, XD, ldw + (size_t)l * Hh * Rr, ldb + (size_t)l * Hh,
            delta, Hh, BS, Hh, Rr);

        // selective scan -> y
        scan_kernel<<<(Bb * Hh * 32 + 255) / 256, 256>>>(
            delta, u, xdbl, Dp + (size_t)l * Hh, y);

        // gate: y *= silu(residual)
        gate_kernel<<<(BS * Hh + 255) / 256, 256>>>(y, xr);

        // lin_out: [BS, H] x [768, H]^T -> mo [BS, 768]
        gemm_nt_kernel<128,128,8,8,8,0><<<dim3(Mdim/128, BS/128), 256>>>(
            y, Hh, low + (size_t)l * Mdim * Hh, lob + (size_t)l * Mdim,
            mo, Mdim, BS, Mdim, Hh);

        // x += rmsnorm(mo) * block_norm_w
        rmsnorm_add_kernel<<<BS, 256>>>(x, mo, bnw + (size_t)l * Mdim);
    }

    // final rmsnorm
    rmsnorm_final_kernel<<<BS, 256>>>(x, fnw, xn);

    // head: [BS, M] x [32000, M]^T -> out [BS, 32000]
    gemm_nt_kernel<128,128,8,8,8,0><<<dim3(Vv/128, BS/128), 256>>>(
        xn, Mdim, hw, hb, out, Vv, BS, Vv, Mdim);
}

// round 3
// speedup vs baseline: 1.9481x; 1.9481x over previous
#include <cuda_runtime.h>
#include <math.h>
#include <stdint.h>

#define DEV_INLINE __device__ __forceinline__

// Problem constants
constexpr int Mdim = 768;
constexpr int Vv   = 32000;
constexpr int Rr   = 48;
constexpr int Nn   = 16;
constexpr int Kk   = 4;
constexpr int Ll   = 2;
constexpr int Hh   = 1536;      // 2*M
constexpr int Bb   = 2;
constexpr int Ss   = 1024;
constexpr int BS   = Bb * Ss;   // 2048 rows
constexpr int H2   = 2 * Hh;    // 3072
constexpr int XD   = Rr + 2 * Nn; // 80

// ---------------- scratch (device globals; no allocation allowed) ----------
__device__ float g_x   [BS * Mdim];
__device__ float g_xr  [BS * H2];
__device__ float g_u   [BS * Hh];
__device__ float g_xdbl[BS * XD];
__device__ float g_delta[BS * Hh];
__device__ float g_y   [BS * Hh];
__device__ float g_mo  [BS * Mdim];
__device__ float g_xn  [BS * Mdim];

// ---------------- helpers ----------------
DEV_INLINE float siluf(float v)     { return v / (1.f + expf(-v)); }
DEV_INLINE float softplusf(float v) { return v > 20.f ? v : log1pf(expf(v)); }

DEV_INLINE float warp_sum(float v) {
    #pragma unroll
    for (int o = 16; o; o >>= 1) v += __shfl_xor_sync(0xffffffffu, v, o);
    return v;
}

DEV_INLINE uint32_t f2tf32(float f) {
    uint32_t u;
    asm("cvt.rna.tf32.f32 %0, %1;" : "=r"(u) : "f"(f));
    return u;
}

DEV_INLINE void mma_tf32(float* d, const uint32_t* a, const uint32_t* b) {
    asm volatile(
        "mma.sync.aligned.m16n8k8.row.col.f32.tf32.tf32.f32 "
        "{%0,%1,%2,%3}, {%4,%5,%6,%7}, {%8,%9}, {%0,%1,%2,%3};"
        : "+f"(d[0]), "+f"(d[1]), "+f"(d[2]), "+f"(d[3])
        : "r"(a[0]), "r"(a[1]), "r"(a[2]), "r"(a[3]),
          "r"(b[0]), "r"(b[1]));
}

// ---------------- embedding gather ----------------
__global__ void embed_kernel(const int* __restrict__ ids,
                             const float* __restrict__ emb,
                             float* __restrict__ x) {
    int idx = blockIdx.x * blockDim.x + threadIdx.x;
    if (idx >= BS * Mdim) return;
    int row = idx / Mdim;
    int m   = idx - row * Mdim;
    x[idx] = emb[ids[row] * Mdim + m];
}

// ---------------- TF32 tensor-core NT GEMM ----------------
// C[i,j] = sum_k A[i,k]*W[j,k] + bias[j];  A row-major (lda), W [NN,KK] K-contig.
// Requires: MM % BM == 0, NN % BN == 0, KK % 16 == 0. 256 threads, warps 2x4.
template<int BM, int BN, int ACT>
__global__ __launch_bounds__(256)
void gemm_tf32(const float* __restrict__ A, int lda,
               const float* __restrict__ W,
               const float* __restrict__ bias,
               float* __restrict__ C, int ldc, int KK) {
    constexpr int BK = 16;
    constexpr int WM = 2, WN = 4;
    constexpr int MT = BM / (WM * 16);   // m16 tiles per warp
    constexpr int NT = BN / (WN * 8);    // n8 tiles per warp

    __shared__ uint32_t As[BK][BM + 1];
    __shared__ uint32_t Ws[BK][BN + 1];

    const int tid  = threadIdx.x;
    const int lane = tid & 31;
    const int wid  = tid >> 5;
    const int wm   = wid / WN;
    const int wn   = wid % WN;
    const int i0   = blockIdx.y * BM;
    const int j0   = blockIdx.x * BN;
    const int lq   = lane & 3;   // quad lane
    const int lg   = lane >> 2;  // group id

    float acc[MT][NT][4];
    #pragma unroll
    for (int m = 0; m < MT; m++)
        #pragma unroll
        for (int n = 0; n < NT; n++)
            #pragma unroll
            for (int c = 0; c < 4; c++) acc[m][n][c] = 0.f;

    for (int k0 = 0; k0 < KK; k0 += BK) {
        // ---- load A tile (BM x BK) -> As[k][m], tf32 converted ----
        #pragma unroll
        for (int it = 0; it < (BM * BK) / (256 * 4); it++) {
            int idx = (it * 256 + tid) * 4;
            int r = idx >> 4, c = idx & 15;
            float4 v = *(const float4*)(A + (size_t)(i0 + r) * lda + k0 + c);
            As[c + 0][r] = f2tf32(v.x);
            As[c + 1][r] = f2tf32(v.y);
            As[c + 2][r] = f2tf32(v.z);
            As[c + 3][r] = f2tf32(v.w);
        }
        // ---- load W tile (BN x BK) -> Ws[k][n] ----
        #pragma unroll
        for (int it = 0; it < (BN * BK) / (256 * 4); it++) {
            int idx = (it * 256 + tid) * 4;
            int r = idx >> 4, c = idx & 15;
            float4 v = *(const float4*)(W + (size_t)(j0 + r) * KK + k0 + c);
            Ws[c + 0][r] = f2tf32(v.x);
            Ws[c + 1][r] = f2tf32(v.y);
            Ws[c + 2][r] = f2tf32(v.z);
            Ws[c + 3][r] = f2tf32(v.w);
        }
        __syncthreads();

        #pragma unroll
        for (int ks = 0; ks < 2; ks++) {
            const int kk = ks * 8;
            uint32_t af[MT][4], bf[NT][2];
            #pragma unroll
            for (int m = 0; m < MT; m++) {
                int mb = wm * (MT * 16) + m * 16 + lg;
                af[m][0] = As[kk + lq    ][mb    ];
                af[m][1] = As[kk + lq    ][mb + 8];
                af[m][2] = As[kk + lq + 4][mb    ];
                af[m][3] = As[kk + lq + 4][mb + 8];
            }
            #pragma unroll
            for (int n = 0; n < NT; n++) {
                int nb = wn * (NT * 8) + n * 8 + lg;
                bf[n][0] = Ws[kk + lq    ][nb];
                bf[n][1] = Ws[kk + lq + 4][nb];
            }
            #pragma unroll
            for (int m = 0; m < MT; m++)
                #pragma unroll
                for (int n = 0; n < NT; n++)
                    mma_tf32(acc[m][n], af[m], bf[n]);
        }
        __syncthreads();
    }

    // ---- epilogue ----
    #pragma unroll
    for (int m = 0; m < MT; m++) {
        int gi = i0 + wm * (MT * 16) + m * 16 + lg;
        #pragma unroll
        for (int n = 0; n < NT; n++) {
            int gj = j0 + wn * (NT * 8) + n * 8 + 2 * lq;
            float b0 = bias[gj], b1 = bias[gj + 1];
            float v0 = acc[m][n][0] + b0;
            float v1 = acc[m][n][1] + b1;
            float v2 = acc[m][n][2] + b0;
            float v3 = acc[m][n][3] + b1;
            if (ACT == 1) {
                v0 = softplusf(v0); v1 = softplusf(v1);
                v2 = softplusf(v2); v3 = softplusf(v3);
            }
            *(float2*)(C + (size_t)gi * ldc + gj)       = make_float2(v0, v1);
            *(float2*)(C + (size_t)(gi + 8) * ldc + gj) = make_float2(v2, v3);
        }
    }
}

// ---------------- lin_x: [BS,1536] x [80,1536]^T, warp-reduction ----------
// block = 8 warps: 8 consecutive rows, same 4-col chunk (W rows L1-resident).
__global__ __launch_bounds__(256)
void linx_kernel(const float* __restrict__ u,
                 const float* __restrict__ w,
                 const float* __restrict__ bias,
                 float* __restrict__ xdbl) {
    int ig = blockIdx.x / 20;      // row group (8 rows)
    int jc = blockIdx.x % 20;      // col chunk (4 cols)
    int wid  = threadIdx.x >> 5;
    int lane = threadIdx.x & 31;
    int i  = ig * 8 + wid;
    int j0 = jc * 4;

    const float4* u4 = (const float4*)(u + (size_t)i * Hh);
    const float4* w0 = (const float4*)(w + (size_t)(j0 + 0) * Hh);
    const float4* w1 = (const float4*)(w + (size_t)(j0 + 1) * Hh);
    const float4* w2 = (const float4*)(w + (size_t)(j0 + 2) * Hh);
    const float4* w3 = (const float4*)(w + (size_t)(j0 + 3) * Hh);

    float p0 = 0.f, p1 = 0.f, p2 = 0.f, p3 = 0.f;
    #pragma unroll
    for (int t = 0; t < Hh / 128; t++) {   // 12 float4 steps per lane
        int k = t * 32 + lane;
        float4 uv = u4[k];
        float4 a  = w0[k];
        p0 += uv.x * a.x + uv.y * a.y + uv.z * a.z + uv.w * a.w;
        a = w1[k];
        p1 += uv.x * a.x + uv.y * a.y + uv.z * a.z + uv.w * a.w;
        a = w2[k];
        p2 += uv.x * a.x + uv.y * a.y + uv.z * a.z + uv.w * a.w;
        a = w3[k];
        p3 += uv.x * a.x + uv.y * a.y + uv.z * a.z + uv.w * a.w;
    }
    p0 = warp_sum(p0); p1 = warp_sum(p1);
    p2 = warp_sum(p2); p3 = warp_sum(p3);
    if (lane == 0) {
        float* o = xdbl + (size_t)i * XD + j0;
        o[0] = p0 + bias[j0];
        o[1] = p1 + bias[j0 + 1];
        o[2] = p2 + bias[j0 + 2];
        o[3] = p3 + bias[j0 + 3];
    }
}

// ---------------- depthwise causal conv (K=4) + silu ----------------
__global__ void conv_silu_kernel(const float* __restrict__ xr,
                                 const float* __restrict__ cw,
                                 const float* __restrict__ cb,
                                 float* __restrict__ u) {
    int idx = blockIdx.x * blockDim.x + threadIdx.x;
    if (idx >= BS * Hh) return;
    int h   = idx % Hh;
    int row = idx / Hh;
    int s   = row % Ss;
    int b   = row / Ss;
    float acc = cb[h];
    #pragma unroll
    for (int k = 0; k < Kk; k++) {
        int sp = s - (Kk - 1) + k;
        if (sp >= 0)
            acc += cw[h * Kk + k] * xr[(b * Ss + sp) * H2 + h];
    }
    u[idx] = siluf(acc);
}

// ---------------- selective scan: warp per (b,h), lanes over n -------------
__global__ void scan_kernel(const float* __restrict__ delta,
                            const float* __restrict__ u,
                            const float* __restrict__ xdbl,
                            const float* __restrict__ Dp,
                            float* __restrict__ y) {
    int gwarp = (blockIdx.x * blockDim.x + threadIdx.x) >> 5;
    if (gwarp >= Bb * Hh) return;
    int lane = threadIdx.x & 31;
    int n    = lane & 15;
    int b    = gwarp / Hh;
    int h    = gwarp - b * Hh;

    const float An = -(float)(n + 1);
    const float Dh = Dp[h];
    float state = 0.f;

    int base = b * Ss;
    for (int s = 0; s < Ss; s++) {
        int row = base + s;
        float dv = __ldg(delta + row * Hh + h);
        float uv = __ldg(u + row * Hh + h);
        float Bn = __ldg(xdbl + row * XD + Rr + n);
        float Cn = __ldg(xdbl + row * XD + Rr + Nn + n);
        float dA = expf(dv * An);
        state = dA * state + dv * Bn * uv;
        float val = state * Cn;
        val += __shfl_xor_sync(0xffffffffu, val, 8);
        val += __shfl_xor_sync(0xffffffffu, val, 4);
        val += __shfl_xor_sync(0xffffffffu, val, 2);
        val += __shfl_xor_sync(0xffffffffu, val, 1);
        if (lane == 0) y[row * Hh + h] = val + uv * Dh;
    }
}

// ---------------- gate: y *= silu(residual) ----------------
__global__ void gate_kernel(float* __restrict__ y,
                            const float* __restrict__ xr) {
    int idx = blockIdx.x * blockDim.x + threadIdx.x;
    if (idx >= BS * Hh) return;
    int h   = idx % Hh;
    int row = idx / Hh;
    y[idx] *= siluf(xr[row * H2 + Hh + h]);
}

// ---------------- x += rmsnorm(mo) * w ----------------
__global__ void rmsnorm_add_kernel(float* __restrict__ x,
                                   const float* __restrict__ mo,
                                   const float* __restrict__ w) {
    int row = blockIdx.x;
    const float* r = mo + row * Mdim;
    float ss = 0.f;
    for (int m = threadIdx.x; m < Mdim; m += blockDim.x) {
        float v = r[m];
        ss += v * v;
    }
    __shared__ float sh[8];
    ss = warp_sum(ss);
    int wid = threadIdx.x >> 5, lane = threadIdx.x & 31;
    if (lane == 0) sh[wid] = ss;
    __syncthreads();
    if (wid == 0) {
        float v = (lane < (int)(blockDim.x >> 5)) ? sh[lane] : 0.f;
        v = warp_sum(v);
        if (lane == 0) sh[0] = v;
    }
    __syncthreads();
    float scale = rsqrtf(sh[0] / (float)Mdim + 1e-15f);
    float* xp = x + row * Mdim;
    for (int m = threadIdx.x; m < Mdim; m += blockDim.x)
        xp[m] += r[m] * scale * w[m];
}

// ---------------- xn = rmsnorm(x) * w ----------------
__global__ void rmsnorm_final_kernel(const float* __restrict__ x,
                                     const float* __restrict__ w,
                                     float* __restrict__ xn) {
    int row = blockIdx.x;
    const float* r = x + row * Mdim;
    float ss = 0.f;
    for (int m = threadIdx.x; m < Mdim; m += blockDim.x) {
        float v = r[m];
        ss += v * v;
    }
    __shared__ float sh[8];
    ss = warp_sum(ss);
    int wid = threadIdx.x >> 5, lane = threadIdx.x & 31;
    if (lane == 0) sh[wid] = ss;
    __syncthreads();
    if (wid == 0) {
        float v = (lane < (int)(blockDim.x >> 5)) ? sh[lane] : 0.f;
        v = warp_sum(v);
        if (lane == 0) sh[0] = v;
    }
    __syncthreads();
    float scale = rsqrtf(sh[0] / (float)Mdim + 1e-15f);
    float* op = xn + row * Mdim;
    for (int m = threadIdx.x; m < Mdim; m += blockDim.x)
        op[m] = r[m] * scale * w[m];
}

// ---------------- launch ----------------
extern "C" void kernel_launch(void* const* d_in, const int* in_sizes, int n_in,
                              void* d_out, int out_size) {
    const int*   ids = (const int*)  d_in[0];
    const float* emb = (const float*)d_in[1];
    const float* liw = (const float*)d_in[2];
    const float* lib = (const float*)d_in[3];
    const float* cw  = (const float*)d_in[4];
    const float* cb  = (const float*)d_in[5];
    const float* lxw = (const float*)d_in[6];
    const float* lxb = (const float*)d_in[7];
    const float* ldw = (const float*)d_in[8];
    const float* ldb = (const float*)d_in[9];
    const float* low = (const float*)d_in[10];
    const float* lob = (const float*)d_in[11];
    const float* Dp  = (const float*)d_in[12];
    const float* bnw = (const float*)d_in[13];
    const float* fnw = (const float*)d_in[14];
    const float* hw  = (const float*)d_in[15];
    const float* hb  = (const float*)d_in[16];
    float* out = (float*)d_out;

    float *x, *xr, *u, *xdbl, *delta, *y, *mo, *xn;
    cudaGetSymbolAddress((void**)&x,     g_x);
    cudaGetSymbolAddress((void**)&xr,    g_xr);
    cudaGetSymbolAddress((void**)&u,     g_u);
    cudaGetSymbolAddress((void**)&xdbl,  g_xdbl);
    cudaGetSymbolAddress((void**)&delta, g_delta);
    cudaGetSymbolAddress((void**)&y,     g_y);
    cudaGetSymbolAddress((void**)&mo,    g_mo);
    cudaGetSymbolAddress((void**)&xn,    g_xn);

    embed_kernel<<<(BS * Mdim + 255) / 256, 256>>>(ids, emb, x);

    for (int l = 0; l < Ll; l++) {
        // lin_in: [2048,768] x [3072,768]^T -> xr
        gemm_tf32<128, 128, 0><<<dim3(H2 / 128, BS / 128), 256>>>(
            x, Mdim, liw + (size_t)l * H2 * Mdim, lib + (size_t)l * H2,
            xr, H2, Mdim);

        conv_silu_kernel<<<(BS * Hh + 255) / 256, 256>>>(
            xr, cw + (size_t)l * Hh * Kk, cb + (size_t)l * Hh, u);

        // lin_x: [2048,1536] x [80,1536]^T -> xdbl
        linx_kernel<<<(BS / 8) * (XD / 4), 256>>>(
            u, lxw + (size_t)l * XD * Hh, lxb + (size_t)l * XD, xdbl);

        // lin_dt + softplus: [2048,48](lda=80) x [1536,48]^T -> delta
        gemm_tf32<128, 128, 1><<<dim3(Hh / 128, BS / 128), 256>>>(
            xdbl, XD, ldw + (size_t)l * Hh * Rr, ldb + (size_t)l * Hh,
            delta, Hh, Rr);

        scan_kernel<<<(Bb * Hh * 32 + 255) / 256, 256>>>(
            delta, u, xdbl, Dp + (size_t)l * Hh, y);

        gate_kernel<<<(BS * Hh + 255) / 256, 256>>>(y, xr);

        // lin_out: [2048,1536] x [768,1536]^T -> mo  (BN=64 for grid size)
        gemm_tf32<128, 64, 0><<<dim3(Mdim / 64, BS / 128), 256>>>(
            y, Hh, low + (size_t)l * Mdim * Hh, lob + (size_t)l * Mdim,
            mo, Mdim, Hh);

        rmsnorm_add_kernel<<<BS, 256>>>(x, mo, bnw + (size_t)l * Mdim);
    }

    rmsnorm_final_kernel<<<BS, 256>>>(x, fnw, xn);

    // head: [2048,768] x [32000,768]^T -> out
    gemm_tf32<128, 128, 0><<<dim3(Vv / 128, BS / 128), 256>>>(
        xn, Mdim, hw, hb, out, Vv, Mdim);
}

// round 4
// speedup vs baseline: 2.0091x; 1.0313x over previous
#include <cuda_runtime.h>
#include <cuda_bf16.h>
#include <math.h>
#include <stdint.h>

#define DEV_INLINE __device__ __forceinline__

// Problem constants
constexpr int Mdim = 768;
constexpr int Vv   = 32000;
constexpr int Rr   = 48;
constexpr int Nn   = 16;
constexpr int Kk   = 4;
constexpr int Ll   = 2;
constexpr int Hh   = 1536;      // 2*M
constexpr int Bb   = 2;
constexpr int Ss   = 1024;
constexpr int BS   = Bb * Ss;   // 2048 rows
constexpr int H2   = 2 * Hh;    // 3072
constexpr int XD   = Rr + 2 * Nn; // 80

// k2 (bf16-pair) counts, padded to multiples of 8
constexpr int K2_M  = Mdim / 2;         // 384
constexpr int K2_H  = Hh / 2;           // 768
constexpr int K2_DT = 32;               // 48/2=24 -> pad 32

// ---------------- fp32 scratch ----------------
__device__ float g_x    [BS * Mdim];
__device__ float g_xr   [BS * H2];
__device__ float g_u    [BS * Hh];
__device__ float g_xdbl [BS * XD];
__device__ float g_delta[BS * Hh];
__device__ float g_y    [BS * Hh];
__device__ float g_mo   [BS * Mdim];
__device__ float g_xn   [BS * Mdim];

// ---------------- bf16x2 hi/lo planes ----------------
// activations (reused sequentially; max K2 = 768)
__device__ __align__(16) uint32_t g_act_h[BS * K2_H];
__device__ __align__(16) uint32_t g_act_l[BS * K2_H];
// weights
__device__ __align__(16) uint32_t g_liw_h[Ll * H2 * K2_M];
__device__ __align__(16) uint32_t g_liw_l[Ll * H2 * K2_M];
__device__ __align__(16) uint32_t g_ldw_h[Ll * Hh * K2_DT];
__device__ __align__(16) uint32_t g_ldw_l[Ll * Hh * K2_DT];
__device__ __align__(16) uint32_t g_low_h[Ll * Mdim * K2_H];
__device__ __align__(16) uint32_t g_low_l[Ll * Mdim * K2_H];
__device__ __align__(16) uint32_t g_hw_h [Vv * K2_M];
__device__ __align__(16) uint32_t g_hw_l [Vv * K2_M];

// ---------------- helpers ----------------
DEV_INLINE float siluf(float v)     { return v / (1.f + expf(-v)); }
DEV_INLINE float softplusf(float v) { return v > 20.f ? v : log1pf(expf(v)); }

DEV_INLINE float warp_sum(float v) {
    #pragma unroll
    for (int o = 16; o; o >>= 1) v += __shfl_xor_sync(0xffffffffu, v, o);
    return v;
}

DEV_INLINE uint32_t packsplit(float f0, float f1, uint32_t& lo) {
    __nv_bfloat16 h0 = __float2bfloat16(f0);
    __nv_bfloat16 h1 = __float2bfloat16(f1);
    __nv_bfloat16 l0 = __float2bfloat16(f0 - __bfloat162float(h0));
    __nv_bfloat16 l1 = __float2bfloat16(f1 - __bfloat162float(h1));
    lo = (uint32_t)__bfloat16_as_ushort(l0) | ((uint32_t)__bfloat16_as_ushort(l1) << 16);
    return (uint32_t)__bfloat16_as_ushort(h0) | ((uint32_t)__bfloat16_as_ushort(h1) << 16);
}

DEV_INLINE void mma_bf16(float* d, const uint32_t* a, const uint32_t* b) {
    asm volatile(
        "mma.sync.aligned.m16n8k16.row.col.f32.bf16.bf16.f32 "
        "{%0,%1,%2,%3}, {%4,%5,%6,%7}, {%8,%9}, {%0,%1,%2,%3};"
        : "+f"(d[0]), "+f"(d[1]), "+f"(d[2]), "+f"(d[3])
        : "r"(a[0]), "r"(a[1]), "r"(a[2]), "r"(a[3]),
          "r"(b[0]), "r"(b[1]));
}

DEV_INLINE void cp_async16(uint32_t dst, const void* src) {
    asm volatile("cp.async.cg.shared.global [%0], [%1], 16;" :: "r"(dst), "l"(src));
}
DEV_INLINE void cp_commit() { asm volatile("cp.async.commit_group;"); }
template<int N> DEV_INLINE void cp_wait() {
    asm volatile("cp.async.wait_group %0;" :: "n"(N));
}

// ---------------- split float -> (hi,lo) bf16-pair planes ----------------
__global__ void split_kernel(const float* __restrict__ in, int in_ld, int K,
                             int K2p, int total,
                             uint32_t* __restrict__ hi, uint32_t* __restrict__ lo) {
    int idx = blockIdx.x * blockDim.x + threadIdx.x;
    if (idx >= total) return;
    int r = idx / K2p, j = idx - r * K2p;
    int k = 2 * j;
    float f0 = (k     < K) ? in[(size_t)r * in_ld + k]     : 0.f;
    float f1 = (k + 1 < K) ? in[(size_t)r * in_ld + k + 1] : 0.f;
    uint32_t l;
    uint32_t h = packsplit(f0, f1, l);
    hi[idx] = h;
    lo[idx] = l;
}

// ---------------- embedding gather ----------------
__global__ void embed_kernel(const int* __restrict__ ids,
                             const float* __restrict__ emb,
                             float* __restrict__ x) {
    int idx = blockIdx.x * blockDim.x + threadIdx.x;
    if (idx >= BS * Mdim) return;
    int row = idx / Mdim;
    int m   = idx - row * Mdim;
    x[idx] = emb[ids[row] * Mdim + m];
}

// ---------------- bf16x3 tensor-core GEMM, cp.async double-buffered -------
// C[i,j] = sum_k A[i,k]*W[j,k] + bias[j]
// Operands pre-split into hi/lo bf16x2 planes [rows][K2] (K2 = padded K/2, %8==0).
// BM=BN=128, BK2=8 (k=16 per stage). 256 threads, warps 2x4, warp tile 64x32.
template<int ACT>
__global__ __launch_bounds__(256)
void gemm_bf16x3(const uint32_t* __restrict__ Ah, const uint32_t* __restrict__ Al,
                 const uint32_t* __restrict__ Wh, const uint32_t* __restrict__ Wl,
                 int K2,
                 const float* __restrict__ bias,
                 float* __restrict__ C, int ldc) {
    // [stage][plane: Ah,Al,Wh,Wl][row 0..127][k2 0..7 (+4 pad)]
    __shared__ __align__(16) uint32_t sm[2][4][128][12];
    constexpr uint32_t PS = 128 * 12 * 4;   // plane stride bytes
    constexpr uint32_t SS = 4 * PS;         // stage stride bytes

    const int tid  = threadIdx.x;
    const int lane = tid & 31;
    const int wid  = tid >> 5;
    const int wm   = wid >> 2;      // 0..1
    const int wn   = wid & 3;       // 0..3
    const int i0   = blockIdx.y * 128;
    const int j0   = blockIdx.x * 128;
    const int lq   = lane & 3;
    const int lg   = lane >> 2;

    // cp.async assignment: each thread copies one 16B chunk per plane per stage
    const int crow  = tid >> 1;         // 0..127
    const int chalf = tid & 1;          // 0..1
    const uint32_t* sAh = Ah + (size_t)(i0 + crow) * K2 + chalf * 4;
    const uint32_t* sAl = Al + (size_t)(i0 + crow) * K2 + chalf * 4;
    const uint32_t* sWh = Wh + (size_t)(j0 + crow) * K2 + chalf * 4;
    const uint32_t* sWl = Wl + (size_t)(j0 + crow) * K2 + chalf * 4;
    const uint32_t dst0 =
        (uint32_t)__cvta_generic_to_shared(&sm[0][0][crow][chalf * 4]);

    float acc[4][4][4];
    #pragma unroll
    for (int m = 0; m < 4; m++)
        #pragma unroll
        for (int n = 0; n < 4; n++)
            #pragma unroll
            for (int c = 0; c < 4; c++) acc[m][n][c] = 0.f;

    const int nIter = K2 >> 3;

    // prefetch stage 0
    {
        uint32_t d = dst0;
        cp_async16(d + 0 * PS, sAh);
        cp_async16(d + 1 * PS, sAl);
        cp_async16(d + 2 * PS, sWh);
        cp_async16(d + 3 * PS, sWl);
        cp_commit();
    }

    for (int t = 0; t < nIter; t++) {
        if (t + 1 < nIter) {
            uint32_t d = dst0 + ((t + 1) & 1) * SS;
            int ko = (t + 1) * 8;
            cp_async16(d + 0 * PS, sAh + ko);
            cp_async16(d + 1 * PS, sAl + ko);
            cp_async16(d + 2 * PS, sWh + ko);
            cp_async16(d + 3 * PS, sWl + ko);
            cp_commit();
            cp_wait<1>();
        } else {
            cp_wait<0>();
        }
        __syncthreads();

        const int cur = t & 1;
        const uint32_t (*pAh)[12] = sm[cur][0];
        const uint32_t (*pAl)[12] = sm[cur][1];
        const uint32_t (*pWh)[12] = sm[cur][2];
        const uint32_t (*pWl)[12] = sm[cur][3];

        uint32_t ah[4][4], al[4][4], bh[4][2], bl[4][2];
        #pragma unroll
        for (int m = 0; m < 4; m++) {
            int mb = wm * 64 + m * 16 + lg;
            ah[m][0] = pAh[mb][lq];     ah[m][1] = pAh[mb + 8][lq];
            ah[m][2] = pAh[mb][lq + 4]; ah[m][3] = pAh[mb + 8][lq + 4];
            al[m][0] = pAl[mb][lq];     al[m][1] = pAl[mb + 8][lq];
            al[m][2] = pAl[mb][lq + 4]; al[m][3] = pAl[mb + 8][lq + 4];
        }
        #pragma unroll
        for (int n = 0; n < 4; n++) {
            int nb = wn * 32 + n * 8 + lg;
            bh[n][0] = pWh[nb][lq]; bh[n][1] = pWh[nb][lq + 4];
            bl[n][0] = pWl[nb][lq]; bl[n][1] = pWl[nb][lq + 4];
        }

        #pragma unroll
        for (int m = 0; m < 4; m++)
            #pragma unroll
            for (int n = 0; n < 4; n++)
                mma_bf16(acc[m][n], ah[m], bh[n]);
        #pragma unroll
        for (int m = 0; m < 4; m++)
            #pragma unroll
            for (int n = 0; n < 4; n++)
                mma_bf16(acc[m][n], ah[m], bl[n]);
        #pragma unroll
        for (int m = 0; m < 4; m++)
            #pragma unroll
            for (int n = 0; n < 4; n++)
                mma_bf16(acc[m][n], al[m], bh[n]);

        __syncthreads();
    }

    // epilogue
    #pragma unroll
    for (int m = 0; m < 4; m++) {
        int gi = i0 + wm * 64 + m * 16 + lg;
        #pragma unroll
        for (int n = 0; n < 4; n++) {
            int gj = j0 + wn * 32 + n * 8 + 2 * lq;
            float b0 = bias[gj], b1 = bias[gj + 1];
            float v0 = acc[m][n][0] + b0;
            float v1 = acc[m][n][1] + b1;
            float v2 = acc[m][n][2] + b0;
            float v3 = acc[m][n][3] + b1;
            if (ACT == 1) {
                v0 = softplusf(v0); v1 = softplusf(v1);
                v2 = softplusf(v2); v3 = softplusf(v3);
            }
            *(float2*)(C + (size_t)gi * ldc + gj)       = make_float2(v0, v1);
            *(float2*)(C + (size_t)(gi + 8) * ldc + gj) = make_float2(v2, v3);
        }
    }
}

// ---------------- lin_x: [BS,1536] x [80,1536]^T, warp-reduction ----------
__global__ __launch_bounds__(256)
void linx_kernel(const float* __restrict__ u,
                 const float* __restrict__ w,
                 const float* __restrict__ bias,
                 float* __restrict__ xdbl) {
    int ig = blockIdx.x / 20;
    int jc = blockIdx.x % 20;
    int wid  = threadIdx.x >> 5;
    int lane = threadIdx.x & 31;
    int i  = ig * 8 + wid;
    int j0 = jc * 4;

    const float4* u4 = (const float4*)(u + (size_t)i * Hh);
    const float4* w0 = (const float4*)(w + (size_t)(j0 + 0) * Hh);
    const float4* w1 = (const float4*)(w + (size_t)(j0 + 1) * Hh);
    const float4* w2 = (const float4*)(w + (size_t)(j0 + 2) * Hh);
    const float4* w3 = (const float4*)(w + (size_t)(j0 + 3) * Hh);

    float p0 = 0.f, p1 = 0.f, p2 = 0.f, p3 = 0.f;
    #pragma unroll
    for (int t = 0; t < Hh / 128; t++) {
        int k = t * 32 + lane;
        float4 uv = u4[k];
        float4 a  = w0[k];
        p0 += uv.x * a.x + uv.y * a.y + uv.z * a.z + uv.w * a.w;
        a = w1[k];
        p1 += uv.x * a.x + uv.y * a.y + uv.z * a.z + uv.w * a.w;
        a = w2[k];
        p2 += uv.x * a.x + uv.y * a.y + uv.z * a.z + uv.w * a.w;
        a = w3[k];
        p3 += uv.x * a.x + uv.y * a.y + uv.z * a.z + uv.w * a.w;
    }
    p0 = warp_sum(p0); p1 = warp_sum(p1);
    p2 = warp_sum(p2); p3 = warp_sum(p3);
    if (lane == 0) {
        float* o = xdbl + (size_t)i * XD + j0;
        o[0] = p0 + bias[j0];
        o[1] = p1 + bias[j0 + 1];
        o[2] = p2 + bias[j0 + 2];
        o[3] = p3 + bias[j0 + 3];
    }
}

// ---------------- depthwise causal conv (K=4) + silu ----------------
__global__ void conv_silu_kernel(const float* __restrict__ xr,
                                 const float* __restrict__ cw,
                                 const float* __restrict__ cb,
                                 float* __restrict__ u) {
    int idx = blockIdx.x * blockDim.x + threadIdx.x;
    if (idx >= BS * Hh) return;
    int h   = idx % Hh;
    int row = idx / Hh;
    int s   = row % Ss;
    int b   = row / Ss;
    float acc = cb[h];
    #pragma unroll
    for (int k = 0; k < Kk; k++) {
        int sp = s - (Kk - 1) + k;
        if (sp >= 0)
            acc += cw[h * Kk + k] * xr[(b * Ss + sp) * H2 + h];
    }
    u[idx] = siluf(acc);
}

// ---------------- selective scan + gate fused ----------------
__global__ void scan_gate_kernel(const float* __restrict__ delta,
                                 const float* __restrict__ u,
                                 const float* __restrict__ xdbl,
                                 const float* __restrict__ Dp,
                                 const float* __restrict__ xr,
                                 float* __restrict__ y) {
    int gwarp = (blockIdx.x * blockDim.x + threadIdx.x) >> 5;
    if (gwarp >= Bb * Hh) return;
    int lane = threadIdx.x & 31;
    int n    = lane & 15;
    int b    = gwarp / Hh;
    int h    = gwarp - b * Hh;

    const float An = -(float)(n + 1);
    const float Dh = Dp[h];
    float state = 0.f;

    int base = b * Ss;
    for (int s = 0; s < Ss; s++) {
        int row = base + s;
        float dv = __ldg(delta + row * Hh + h);
        float uv = __ldg(u + row * Hh + h);
        float Bn = __ldg(xdbl + row * XD + Rr + n);
        float Cn = __ldg(xdbl + row * XD + Rr + Nn + n);
        float dA = expf(dv * An);
        state = dA * state + dv * Bn * uv;
        float val = state * Cn;
        val += __shfl_xor_sync(0xffffffffu, val, 8);
        val += __shfl_xor_sync(0xffffffffu, val, 4);
        val += __shfl_xor_sync(0xffffffffu, val, 2);
        val += __shfl_xor_sync(0xffffffffu, val, 1);
        if (lane == 0) {
            float res = xr[(size_t)row * H2 + Hh + h];
            y[row * Hh + h] = (val + uv * Dh) * siluf(res);
        }
    }
}

// ---------------- x += rmsnorm(mo) * w ----------------
__global__ void rmsnorm_add_kernel(float* __restrict__ x,
                                   const float* __restrict__ mo,
                                   const float* __restrict__ w) {
    int row = blockIdx.x;
    const float* r = mo + row * Mdim;
    float ss = 0.f;
    for (int m = threadIdx.x; m < Mdim; m += blockDim.x) {
        float v = r[m];
        ss += v * v;
    }
    __shared__ float sh[8];
    ss = warp_sum(ss);
    int wid = threadIdx.x >> 5, lane = threadIdx.x & 31;
    if (lane == 0) sh[wid] = ss;
    __syncthreads();
    if (wid == 0) {
        float v = (lane < (int)(blockDim.x >> 5)) ? sh[lane] : 0.f;
        v = warp_sum(v);
        if (lane == 0) sh[0] = v;
    }
    __syncthreads();
    float scale = rsqrtf(sh[0] / (float)Mdim + 1e-15f);
    float* xp = x + row * Mdim;
    for (int m = threadIdx.x; m < Mdim; m += blockDim.x)
        xp[m] += r[m] * scale * w[m];
}

// ---------------- xn = rmsnorm(x) * w ----------------
__global__ void rmsnorm_final_kernel(const float* __restrict__ x,
                                     const float* __restrict__ w,
                                     float* __restrict__ xn) {
    int row = blockIdx.x;
    const float* r = x + row * Mdim;
    float ss = 0.f;
    for (int m = threadIdx.x; m < Mdim; m += blockDim.x) {
        float v = r[m];
        ss += v * v;
    }
    __shared__ float sh[8];
    ss = warp_sum(ss);
    int wid = threadIdx.x >> 5, lane = threadIdx.x & 31;
    if (lane == 0) sh[wid] = ss;
    __syncthreads();
    if (wid == 0) {
        float v = (lane < (int)(blockDim.x >> 5)) ? sh[lane] : 0.f;
        v = warp_sum(v);
        if (lane == 0) sh[0] = v;
    }
    __syncthreads();
    float scale = rsqrtf(sh[0] / (float)Mdim + 1e-15f);
    float* op = xn + row * Mdim;
    for (int m = threadIdx.x; m < Mdim; m += blockDim.x)
        op[m] = r[m] * scale * w[m];
}

// ---------------- launch ----------------
static void split_launch(const float* in, int in_ld, int K, int K2p, int rows,
                         uint32_t* hi, uint32_t* lo) {
    int total = rows * K2p;
    split_kernel<<<(total + 255) / 256, 256>>>(in, in_ld, K, K2p, total, hi, lo);
}

extern "C" void kernel_launch(void* const* d_in, const int* in_sizes, int n_in,
                              void* d_out, int out_size) {
    const int*   ids = (const int*)  d_in[0];
    const float* emb = (const float*)d_in[1];
    const float* liw = (const float*)d_in[2];
    const float* lib = (const float*)d_in[3];
    const float* cw  = (const float*)d_in[4];
    const float* cb  = (const float*)d_in[5];
    const float* lxw = (const float*)d_in[6];
    const float* lxb = (const float*)d_in[7];
    const float* ldw = (const float*)d_in[8];
    const float* ldb = (const float*)d_in[9];
    const float* low = (const float*)d_in[10];
    const float* lob = (const float*)d_in[11];
    const float* Dp  = (const float*)d_in[12];
    const float* bnw = (const float*)d_in[13];
    const float* fnw = (const float*)d_in[14];
    const float* hw  = (const float*)d_in[15];
    const float* hb  = (const float*)d_in[16];
    float* out = (float*)d_out;

    float *x, *xr, *u, *xdbl, *delta, *y, *mo, *xn;
    cudaGetSymbolAddress((void**)&x,     g_x);
    cudaGetSymbolAddress((void**)&xr,    g_xr);
    cudaGetSymbolAddress((void**)&u,     g_u);
    cudaGetSymbolAddress((void**)&xdbl,  g_xdbl);
    cudaGetSymbolAddress((void**)&delta, g_delta);
    cudaGetSymbolAddress((void**)&y,     g_y);
    cudaGetSymbolAddress((void**)&mo,    g_mo);
    cudaGetSymbolAddress((void**)&xn,    g_xn);

    uint32_t *act_h, *act_l, *liw_h, *liw_l, *ldw_h, *ldw_l,
             *low_h, *low_l, *hw_h, *hw_l;
    cudaGetSymbolAddress((void**)&act_h, g_act_h);
    cudaGetSymbolAddress((void**)&act_l, g_act_l);
    cudaGetSymbolAddress((void**)&liw_h, g_liw_h);
    cudaGetSymbolAddress((void**)&liw_l, g_liw_l);
    cudaGetSymbolAddress((void**)&ldw_h, g_ldw_h);
    cudaGetSymbolAddress((void**)&ldw_l, g_ldw_l);
    cudaGetSymbolAddress((void**)&low_h, g_low_h);
    cudaGetSymbolAddress((void**)&low_l, g_low_l);
    cudaGetSymbolAddress((void**)&hw_h,  g_hw_h);
    cudaGetSymbolAddress((void**)&hw_l,  g_hw_l);

    embed_kernel<<<(BS * Mdim + 255) / 256, 256>>>(ids, emb, x);

    // pre-split all weights
    for (int l = 0; l < Ll; l++) {
        split_launch(liw + (size_t)l * H2 * Mdim, Mdim, Mdim, K2_M, H2,
                     liw_h + (size_t)l * H2 * K2_M, liw_l + (size_t)l * H2 * K2_M);
        split_launch(ldw + (size_t)l * Hh * Rr, Rr, Rr, K2_DT, Hh,
                     ldw_h + (size_t)l * Hh * K2_DT, ldw_l + (size_t)l * Hh * K2_DT);
        split_launch(low + (size_t)l * Mdim * Hh, Hh, Hh, K2_H, Mdim,
                     low_h + (size_t)l * Mdim * K2_H, low_l + (size_t)l * Mdim * K2_H);
    }
    split_launch(hw, Mdim, Mdim, K2_M, Vv, hw_h, hw_l);

    for (int l = 0; l < Ll; l++) {
        // lin_in: x [2048,768] x liw [3072,768]^T -> xr
        split_launch(x, Mdim, Mdim, K2_M, BS, act_h, act_l);
        gemm_bf16x3<0><<<dim3(H2 / 128, BS / 128), 256>>>(
            act_h, act_l,
            liw_h + (size_t)l * H2 * K2_M, liw_l + (size_t)l * H2 * K2_M,
            K2_M, lib + (size_t)l * H2, xr, H2);

        conv_silu_kernel<<<(BS * Hh + 255) / 256, 256>>>(
            xr, cw + (size_t)l * Hh * Kk, cb + (size_t)l * Hh, u);

        linx_kernel<<<(BS / 8) * (XD / 4), 256>>>(
            u, lxw + (size_t)l * XD * Hh, lxb + (size_t)l * XD, xdbl);

        // lin_dt + softplus: xdbl[:, :48] x ldw [1536,48]^T -> delta
        split_launch(xdbl, XD, Rr, K2_DT, BS, act_h, act_l);
        gemm_bf16x3<1><<<dim3(Hh / 128, BS / 128), 256>>>(
            act_h, act_l,
            ldw_h + (size_t)l * Hh * K2_DT, ldw_l + (size_t)l * Hh * K2_DT,
            K2_DT, ldb + (size_t)l * Hh, delta, Hh);

        scan_gate_kernel<<<(Bb * Hh * 32 + 255) / 256, 256>>>(
            delta, u, xdbl, Dp + (size_t)l * Hh, xr, y);

        // lin_out: y [2048,1536] x low [768,1536]^T -> mo
        split_launch(y, Hh, Hh, K2_H, BS, act_h, act_l);
        gemm_bf16x3<0><<<dim3(Mdim / 128, BS / 128), 256>>>(
            act_h, act_l,
            low_h + (size_t)l * Mdim * K2_H, low_l + (size_t)l * Mdim * K2_H,
            K2_H, lob + (size_t)l * Mdim, mo, Mdim);

        rmsnorm_add_kernel<<<BS, 256>>>(x, mo, bnw + (size_t)l * Mdim);
    }

    rmsnorm_final_kernel<<<BS, 256>>>(x, fnw, xn);

    // head: xn [2048,768] x hw [32000,768]^T -> out
    split_launch(xn, Mdim, Mdim, K2_M, BS, act_h, act_l);
    gemm_bf16x3<0><<<dim3(Vv / 128, BS / 128), 256>>>(
        act_h, act_l, hw_h, hw_l, K2_M, hb, out, Vv);
}

// round 6
// speedup vs baseline: 2.1685x; 1.0793x over previous
#include <cuda_runtime.h>
#include <cuda_bf16.h>
#include <math.h>
#include <stdint.h>

#define DEV_INLINE __device__ __forceinline__

// Problem constants
constexpr int Mdim = 768;
constexpr int Vv   = 32000;
constexpr int Rr   = 48;
constexpr int Nn   = 16;
constexpr int Kk   = 4;
constexpr int Ll   = 2;
constexpr int Hh   = 1536;
constexpr int Bb   = 2;
constexpr int Ss   = 1024;
constexpr int BS   = Bb * Ss;     // 2048
constexpr int H2   = 2 * Hh;      // 3072
constexpr int XD   = Rr + 2 * Nn; // 80

// packed bf16-pair (u32) K extents, multiples of 8 (k16 granule)
constexpr int K2_M  = Mdim / 2;   // 384
constexpr int K2_H  = Hh / 2;     // 768
constexpr int K2_DT = 32;         // 48/2=24 -> pad 32

// ---------------- fp32 scratch ----------------
__device__ float g_x    [BS * Mdim];
__device__ float g_xr   [BS * H2];
__device__ float g_u    [BS * Hh];
__device__ float g_xdbl [BS * XD];
__device__ float g_delta[BS * Hh];
__device__ float g_mo   [BS * Mdim];

// ---------------- bf16x2 hi/lo planes ----------------
__device__ __align__(16) uint32_t g_xp_h [BS * K2_M];
__device__ __align__(16) uint32_t g_xp_l [BS * K2_M];
__device__ __align__(16) uint32_t g_act_h[BS * K2_H];
__device__ __align__(16) uint32_t g_act_l[BS * K2_H];
__device__ __align__(16) uint32_t g_liw_h[Ll * H2 * K2_M];
__device__ __align__(16) uint32_t g_liw_l[Ll * H2 * K2_M];
__device__ __align__(16) uint32_t g_ldw_h[Ll * Hh * K2_DT];
__device__ __align__(16) uint32_t g_ldw_l[Ll * Hh * K2_DT];
__device__ __align__(16) uint32_t g_low_h[Ll * Mdim * K2_H];
__device__ __align__(16) uint32_t g_low_l[Ll * Mdim * K2_H];
__device__ __align__(16) uint32_t g_hw_h [Vv * K2_M];
__device__ __align__(16) uint32_t g_hw_l [Vv * K2_M];

// ---------------- helpers ----------------
DEV_INLINE float siluf(float v)     { return v / (1.f + expf(-v)); }
DEV_INLINE float softplusf(float v) { return v > 20.f ? v : log1pf(expf(v)); }

DEV_INLINE float warp_sum(float v) {
    #pragma unroll
    for (int o = 16; o; o >>= 1) v += __shfl_xor_sync(0xffffffffu, v, o);
    return v;
}

DEV_INLINE uint32_t packsplit(float f0, float f1, uint32_t& lo) {
    __nv_bfloat16 h0 = __float2bfloat16(f0);
    __nv_bfloat16 h1 = __float2bfloat16(f1);
    __nv_bfloat16 l0 = __float2bfloat16(f0 - __bfloat162float(h0));
    __nv_bfloat16 l1 = __float2bfloat16(f1 - __bfloat162float(h1));
    lo = (uint32_t)__bfloat16_as_ushort(l0) | ((uint32_t)__bfloat16_as_ushort(l1) << 16);
    return (uint32_t)__bfloat16_as_ushort(h0) | ((uint32_t)__bfloat16_as_ushort(h1) << 16);
}

DEV_INLINE void mma_bf16(float* d, const uint32_t* a, const uint32_t* b) {
    asm volatile(
        "mma.sync.aligned.m16n8k16.row.col.f32.bf16.bf16.f32 "
        "{%0,%1,%2,%3}, {%4,%5,%6,%7}, {%8,%9}, {%0,%1,%2,%3};"
        : "+f"(d[0]), "+f"(d[1]), "+f"(d[2]), "+f"(d[3])
        : "r"(a[0]), "r"(a[1]), "r"(a[2]), "r"(a[3]),
          "r"(b[0]), "r"(b[1]));
}

DEV_INLINE void cp_async16(uint32_t dst, const void* src) {
    asm volatile("cp.async.cg.shared.global [%0], [%1], 16;" :: "r"(dst), "l"(src));
}
DEV_INLINE void cp_commit() { asm volatile("cp.async.commit_group;"); }
template<int N> DEV_INLINE void cp_wait() {
    asm volatile("cp.async.wait_group %0;" :: "n"(N));
}

// ---------------- split float -> (hi,lo) bf16-pair planes ----------------
__global__ void split_kernel(const float* __restrict__ in, int in_ld, int K,
                             int K2p, int total,
                             uint32_t* __restrict__ hi, uint32_t* __restrict__ lo) {
    int idx = blockIdx.x * blockDim.x + threadIdx.x;
    if (idx >= total) return;
    int r = idx / K2p, j = idx - r * K2p;
    int k = 2 * j;
    float f0 = (k     < K) ? in[(size_t)r * in_ld + k]     : 0.f;
    float f1 = (k + 1 < K) ? in[(size_t)r * in_ld + k + 1] : 0.f;
    uint32_t l;
    uint32_t h = packsplit(f0, f1, l);
    hi[idx] = h;
    lo[idx] = l;
}

// ---------------- embedding gather + planes ----------------
__global__ void embed_kernel(const int* __restrict__ ids,
                             const float* __restrict__ emb,
                             float* __restrict__ x,
                             uint32_t* __restrict__ xph,
                             uint32_t* __restrict__ xpl) {
    int idx = blockIdx.x * blockDim.x + threadIdx.x;
    if (idx >= BS * K2_M) return;
    int row = idx / K2_M;
    int m2  = idx - row * K2_M;
    const float* e = emb + (size_t)ids[row] * Mdim + 2 * m2;
    float f0 = e[0], f1 = e[1];
    x[(size_t)row * Mdim + 2 * m2]     = f0;
    x[(size_t)row * Mdim + 2 * m2 + 1] = f1;
    uint32_t l;
    uint32_t h = packsplit(f0, f1, l);
    xph[idx] = h;
    xpl[idx] = l;
}

// ---------------- bf16x3 tensor-core GEMM, 3-stage cp.async --------------
// C[i,j] = sum_k A[i,k]*W[j,k] + bias[j]; planes [rows][K2], K2 % 8 == 0.
// BM=128 x BN, k16 per stage. 256 threads, warps 2(m) x 4(n).
template<int BN, int ACT>
__global__ __launch_bounds__(256)
void gemm_bf16x3(const uint32_t* __restrict__ Ah, const uint32_t* __restrict__ Al,
                 const uint32_t* __restrict__ Wh, const uint32_t* __restrict__ Wl,
                 int K2,
                 const float* __restrict__ bias,
                 float* __restrict__ C, int ldc) {
    constexpr int NTt = BN / 32;              // n8 tiles per warp
    constexpr int AP  = 128 * 12;             // u32 per A plane (8 data + 4 pad)
    constexpr int WP  = BN * 12;
    constexpr int STG = 2 * AP + 2 * WP;      // u32 per stage
    constexpr int RT  = 256 + 2 * BN;         // rows per stage
    constexpr int NCH = RT * 2 / 256;         // 16B chunks per thread

    extern __shared__ __align__(16) uint32_t smu[];   // 3 stages

    const int tid  = threadIdx.x;
    const int lane = tid & 31;
    const int wid  = tid >> 5;
    const int wm   = wid >> 2;
    const int wn   = wid & 3;
    const int i0   = blockIdx.y * 128;
    const int j0   = blockIdx.x * BN;
    const int lq   = lane & 3;
    const int lg   = lane >> 2;

    // per-thread cp.async slots
    const uint32_t* src[NCH];
    uint32_t dst[NCH];
    #pragma unroll
    for (int uu = 0; uu < NCH; uu++) {
        int c = uu * 256 + tid;
        int r2   = c >> 1;
        int half = c & 1;
        const uint32_t* gbase;
        int pofs, r;
        if (r2 < 128)            { r = r2;            gbase = Ah + (size_t)i0 * K2; pofs = 0; }
        else if (r2 < 256)       { r = r2 - 128;      gbase = Al + (size_t)i0 * K2; pofs = AP; }
        else if (r2 < 256 + BN)  { r = r2 - 256;      gbase = Wh + (size_t)j0 * K2; pofs = 2 * AP; }
        else                     { r = r2 - 256 - BN; gbase = Wl + (size_t)j0 * K2; pofs = 2 * AP + WP; }
        src[uu] = gbase + (size_t)r * K2 + half * 4;
        dst[uu] = (uint32_t)__cvta_generic_to_shared(
                      &smu[pofs + r * 12 + half * 4]);
    }

    float acc[4][NTt][4];
    #pragma unroll
    for (int m = 0; m < 4; m++)
        #pragma unroll
        for (int n = 0; n < NTt; n++)
            #pragma unroll
            for (int c = 0; c < 4; c++) acc[m][n][c] = 0.f;

    const int nk = K2 >> 3;     // k16 chunks

    // prefetch stages 0, 1
    #pragma unroll
    for (int uu = 0; uu < NCH; uu++) cp_async16(dst[uu], src[uu]);
    cp_commit();
    if (nk > 1) {
        #pragma unroll
        for (int uu = 0; uu < NCH; uu++)
            cp_async16(dst[uu] + STG * 4, src[uu] + 8);
        cp_commit();
    }

    for (int t = 0; t < nk; t++) {
        if (t + 1 < nk) { cp_wait<1>(); } else { cp_wait<0>(); }
        __syncthreads();
        // overwrite stage (t+2)%3 — safe: its consumers finished before this sync
        if (t + 2 < nk) {
            uint32_t so = (uint32_t)((t + 2) % 3) * (STG * 4);
            int ko = (t + 2) * 8;
            #pragma unroll
            for (int uu = 0; uu < NCH; uu++)
                cp_async16(dst[uu] + so, src[uu] + ko);
            cp_commit();
        }

        const uint32_t* base = smu + (t % 3) * STG;
        const uint32_t* pAh = base;
        const uint32_t* pAl = base + AP;
        const uint32_t* pWh = base + 2 * AP;
        const uint32_t* pWl = base + 2 * AP + WP;

        uint32_t ah[4][4], al[4][4], bh[NTt][2], bl[NTt][2];
        #pragma unroll
        for (int m = 0; m < 4; m++) {
            int mb = wm * 64 + m * 16 + lg;
            ah[m][0] = pAh[mb * 12 + lq];           ah[m][1] = pAh[(mb + 8) * 12 + lq];
            ah[m][2] = pAh[mb * 12 + lq + 4];       ah[m][3] = pAh[(mb + 8) * 12 + lq + 4];
            al[m][0] = pAl[mb * 12 + lq];           al[m][1] = pAl[(mb + 8) * 12 + lq];
            al[m][2] = pAl[mb * 12 + lq + 4];       al[m][3] = pAl[(mb + 8) * 12 + lq + 4];
        }
        #pragma unroll
        for (int n = 0; n < NTt; n++) {
            int nb = wn * (NTt * 8) + n * 8 + lg;
            bh[n][0] = pWh[nb * 12 + lq]; bh[n][1] = pWh[nb * 12 + lq + 4];
            bl[n][0] = pWl[nb * 12 + lq]; bl[n][1] = pWl[nb * 12 + lq + 4];
        }

        #pragma unroll
        for (int m = 0; m < 4; m++)
            #pragma unroll
            for (int n = 0; n < NTt; n++)
                mma_bf16(acc[m][n], ah[m], bh[n]);
        #pragma unroll
        for (int m = 0; m < 4; m++)
            #pragma unroll
            for (int n = 0; n < NTt; n++)
                mma_bf16(acc[m][n], ah[m], bl[n]);
        #pragma unroll
        for (int m = 0; m < 4; m++)
            #pragma unroll
            for (int n = 0; n < NTt; n++)
                mma_bf16(acc[m][n], al[m], bh[n]);
    }

    // epilogue
    #pragma unroll
    for (int m = 0; m < 4; m++) {
        int gi = i0 + wm * 64 + m * 16 + lg;
        #pragma unroll
        for (int n = 0; n < NTt; n++) {
            int gj = j0 + wn * (NTt * 8) + n * 8 + 2 * lq;
            float b0 = bias[gj], b1 = bias[gj + 1];
            float v0 = acc[m][n][0] + b0;
            float v1 = acc[m][n][1] + b1;
            float v2 = acc[m][n][2] + b0;
            float v3 = acc[m][n][3] + b1;
            if (ACT == 1) {
                v0 = softplusf(v0); v1 = softplusf(v1);
                v2 = softplusf(v2); v3 = softplusf(v3);
            }
            *(float2*)(C + (size_t)gi * ldc + gj)       = make_float2(v0, v1);
            *(float2*)(C + (size_t)(gi + 8) * ldc + gj) = make_float2(v2, v3);
        }
    }
}

// ---------------- lin_x: [BS,1536] x [80,1536]^T, warp-reduction ----------
__global__ __launch_bounds__(256)
void linx_kernel(const float* __restrict__ u,
                 const float* __restrict__ w,
                 const float* __restrict__ bias,
                 float* __restrict__ xdbl) {
    int ig = blockIdx.x / 20;
    int jc = blockIdx.x % 20;
    int wid  = threadIdx.x >> 5;
    int lane = threadIdx.x & 31;
    int i  = ig * 8 + wid;
    int j0 = jc * 4;

    const float4* u4 = (const float4*)(u + (size_t)i * Hh);
    const float4* w0 = (const float4*)(w + (size_t)(j0 + 0) * Hh);
    const float4* w1 = (const float4*)(w + (size_t)(j0 + 1) * Hh);
    const float4* w2 = (const float4*)(w + (size_t)(j0 + 2) * Hh);
    const float4* w3 = (const float4*)(w + (size_t)(j0 + 3) * Hh);

    float p0 = 0.f, p1 = 0.f, p2 = 0.f, p3 = 0.f;
    #pragma unroll
    for (int t = 0; t < Hh / 128; t++) {
        int k = t * 32 + lane;
        float4 uv = u4[k];
        float4 a  = w0[k];
        p0 += uv.x * a.x + uv.y * a.y + uv.z * a.z + uv.w * a.w;
        a = w1[k];
        p1 += uv.x * a.x + uv.y * a.y + uv.z * a.z + uv.w * a.w;
        a = w2[k];
        p2 += uv.x * a.x + uv.y * a.y + uv.z * a.z + uv.w * a.w;
        a = w3[k];
        p3 += uv.x * a.x + uv.y * a.y + uv.z * a.z + uv.w * a.w;
    }
    p0 = warp_sum(p0); p1 = warp_sum(p1);
    p2 = warp_sum(p2); p3 = warp_sum(p3);
    if (lane == 0) {
        float* o = xdbl + (size_t)i * XD + j0;
        o[0] = p0 + bias[j0];
        o[1] = p1 + bias[j0 + 1];
        o[2] = p2 + bias[j0 + 2];
        o[3] = p3 + bias[j0 + 3];
    }
}

// ---------------- depthwise causal conv (K=4) + silu ----------------
__global__ void conv_silu_kernel(const float* __restrict__ xr,
                                 const float* __restrict__ cw,
                                 const float* __restrict__ cb,
                                 float* __restrict__ u) {
    int idx = blockIdx.x * blockDim.x + threadIdx.x;
    if (idx >= BS * Hh) return;
    int h   = idx % Hh;
    int row = idx / Hh;
    int s   = row % Ss;
    int b   = row / Ss;
    float acc = cb[h];
    #pragma unroll
    for (int k = 0; k < Kk; k++) {
        int sp = s - (Kk - 1) + k;
        if (sp >= 0)
            acc += cw[h * Kk + k] * xr[(size_t)(b * Ss + sp) * H2 + h];
    }
    u[idx] = siluf(acc);
}

// ---------------- selective scan + gate + plane split fused ---------------
__global__ void scan_gate_kernel(const float* __restrict__ delta,
                                 const float* __restrict__ u,
                                 const float* __restrict__ xdbl,
                                 const float* __restrict__ Dp,
                                 const float* __restrict__ xr,
                                 uint32_t* __restrict__ yh,
                                 uint32_t* __restrict__ yl) {
    int gwarp = (blockIdx.x * blockDim.x + threadIdx.x) >> 5;
    if (gwarp >= Bb * (Hh / 2)) return;
    int lane = threadIdx.x & 31;
    int half = lane >> 4;
    int n    = lane & 15;
    int b    = gwarp / (Hh / 2);
    int hp   = gwarp % (Hh / 2);
    int h    = hp * 2 + half;

    const float An = -(float)(n + 1);
    const float Dh = Dp[h];
    float state = 0.f;

    int base = b * Ss;
    for (int s = 0; s < Ss; s++) {
        int row = base + s;
        float dv = __ldg(delta + (size_t)row * Hh + h);
        float uv = __ldg(u + (size_t)row * Hh + h);
        float Bn = __ldg(xdbl + row * XD + Rr + n);
        float Cn = __ldg(xdbl + row * XD + Rr + Nn + n);
        float dA = expf(dv * An);
        state = dA * state + dv * Bn * uv;
        float val = state * Cn;
        val += __shfl_xor_sync(0xffffffffu, val, 8);
        val += __shfl_xor_sync(0xffffffffu, val, 4);
        val += __shfl_xor_sync(0xffffffffu, val, 2);
        val += __shfl_xor_sync(0xffffffffu, val, 1);
        float res = __ldg(xr + (size_t)row * H2 + Hh + h);
        float yv  = (val + uv * Dh) * siluf(res);
        float y1  = __shfl_sync(0xffffffffu, yv, 16);
        if (lane == 0) {
            uint32_t lo;
            uint32_t hi = packsplit(yv, y1, lo);
            yh[(size_t)row * K2_H + hp] = hi;
            yl[(size_t)row * K2_H + hp] = lo;
        }
    }
}

// ---------------- x += rmsnorm(mo) * w ; emit x planes ----------------
__global__ void rmsnorm_add_kernel(float* __restrict__ x,
                                   const float* __restrict__ mo,
                                   const float* __restrict__ w,
                                   uint32_t* __restrict__ xph,
                                   uint32_t* __restrict__ xpl) {
    int row = blockIdx.x;
    const float* r = mo + (size_t)row * Mdim;
    float ss = 0.f;
    for (int m = threadIdx.x; m < Mdim; m += blockDim.x) {
        float v = r[m];
        ss += v * v;
    }
    __shared__ float sh[8];
    ss = warp_sum(ss);
    int wid = threadIdx.x >> 5, lane = threadIdx.x & 31;
    if (lane == 0) sh[wid] = ss;
    __syncthreads();
    if (wid == 0) {
        float v = (lane < (int)(blockDim.x >> 5)) ? sh[lane] : 0.f;
        v = warp_sum(v);
        if (lane == 0) sh[0] = v;
    }
    __syncthreads();
    float scale = rsqrtf(sh[0] / (float)Mdim + 1e-15f);
    float* xp = x + (size_t)row * Mdim;
    for (int m2 = threadIdx.x; m2 < K2_M; m2 += blockDim.x) {
        int m = 2 * m2;
        float v0 = xp[m]     + r[m]     * scale * w[m];
        float v1 = xp[m + 1] + r[m + 1] * scale * w[m + 1];
        xp[m] = v0; xp[m + 1] = v1;
        uint32_t lo;
        uint32_t hi = packsplit(v0, v1, lo);
        xph[(size_t)row * K2_M + m2] = hi;
        xpl[(size_t)row * K2_M + m2] = lo;
    }
}

// ---------------- final rmsnorm -> planes only ----------------
__global__ void rmsnorm_final_kernel(const float* __restrict__ x,
                                     const float* __restrict__ w,
                                     uint32_t* __restrict__ xph,
                                     uint32_t* __restrict__ xpl) {
    int row = blockIdx.x;
    const float* r = x + (size_t)row * Mdim;
    float ss = 0.f;
    for (int m = threadIdx.x; m < Mdim; m += blockDim.x) {
        float v = r[m];
        ss += v * v;
    }
    __shared__ float sh[8];
    ss = warp_sum(ss);
    int wid = threadIdx.x >> 5, lane = threadIdx.x & 31;
    if (lane == 0) sh[wid] = ss;
    __syncthreads();
    if (wid == 0) {
        float v = (lane < (int)(blockDim.x >> 5)) ? sh[lane] : 0.f;
        v = warp_sum(v);
        if (lane == 0) sh[0] = v;
    }
    __syncthreads();
    float scale = rsqrtf(sh[0] / (float)Mdim + 1e-15f);
    for (int m2 = threadIdx.x; m2 < K2_M; m2 += blockDim.x) {
        int m = 2 * m2;
        float v0 = r[m]     * scale * w[m];
        float v1 = r[m + 1] * scale * w[m + 1];
        uint32_t lo;
        uint32_t hi = packsplit(v0, v1, lo);
        xph[(size_t)row * K2_M + m2] = hi;
        xpl[(size_t)row * K2_M + m2] = lo;
    }
}

// ---------------- launch ----------------
static void split_launch(const float* in, int in_ld, int K, int K2p, int rows,
                         uint32_t* hi, uint32_t* lo) {
    int total = rows * K2p;
    split_kernel<<<(total + 255) / 256, 256>>>(in, in_ld, K, K2p, total, hi, lo);
}

extern "C" void kernel_launch(void* const* d_in, const int* in_sizes, int n_in,
                              void* d_out, int out_size) {
    const int*   ids = (const int*)  d_in[0];
    const float* emb = (const float*)d_in[1];
    const float* liw = (const float*)d_in[2];
    const float* lib = (const float*)d_in[3];
    const float* cw  = (const float*)d_in[4];
    const float* cb  = (const float*)d_in[5];
    const float* lxw = (const float*)d_in[6];
    const float* lxb = (const float*)d_in[7];
    const float* ldw = (const float*)d_in[8];
    const float* ldb = (const float*)d_in[9];
    const float* low = (const float*)d_in[10];
    const float* lob = (const float*)d_in[11];
    const float* Dp  = (const float*)d_in[12];
    const float* bnw = (const float*)d_in[13];
    const float* fnw = (const float*)d_in[14];
    const float* hw  = (const float*)d_in[15];
    const float* hb  = (const float*)d_in[16];
    float* out = (float*)d_out;

    float *x, *xr, *u, *xdbl, *delta, *mo;
    cudaGetSymbolAddress((void**)&x,     g_x);
    cudaGetSymbolAddress((void**)&xr,    g_xr);
    cudaGetSymbolAddress((void**)&u,     g_u);
    cudaGetSymbolAddress((void**)&xdbl,  g_xdbl);
    cudaGetSymbolAddress((void**)&delta, g_delta);
    cudaGetSymbolAddress((void**)&mo,    g_mo);

    uint32_t *xp_h, *xp_l, *act_h, *act_l;
    uint32_t *liw_h, *liw_l, *ldw_h, *ldw_l, *low_h, *low_l, *hw_h, *hw_l;
    cudaGetSymbolAddress((void**)&xp_h,  g_xp_h);
    cudaGetSymbolAddress((void**)&xp_l,  g_xp_l);
    cudaGetSymbolAddress((void**)&act_h, g_act_h);
    cudaGetSymbolAddress((void**)&act_l, g_act_l);
    cudaGetSymbolAddress((void**)&liw_h, g_liw_h);
    cudaGetSymbolAddress((void**)&liw_l, g_liw_l);
    cudaGetSymbolAddress((void**)&ldw_h, g_ldw_h);
    cudaGetSymbolAddress((void**)&ldw_l, g_ldw_l);
    cudaGetSymbolAddress((void**)&low_h, g_low_h);
    cudaGetSymbolAddress((void**)&low_l, g_low_l);
    cudaGetSymbolAddress((void**)&hw_h,  g_hw_h);
    cudaGetSymbolAddress((void**)&hw_l,  g_hw_l);

    // dynamic smem: 3 stages
    const int SM128 = 3 * (2 * 128 * 12 + 2 * 128 * 12) * 4;  // 73728
    const int SM64  = 3 * (2 * 128 * 12 + 2 * 64 * 12) * 4;   // 55296
    cudaFuncSetAttribute((const void*)gemm_bf16x3<128, 0>,
                         cudaFuncAttributeMaxDynamicSharedMemorySize, SM128);
    cudaFuncSetAttribute((const void*)gemm_bf16x3<128, 1>,
                         cudaFuncAttributeMaxDynamicSharedMemorySize, SM128);
    cudaFuncSetAttribute((const void*)gemm_bf16x3<64, 0>,
                         cudaFuncAttributeMaxDynamicSharedMemorySize, SM64);

    embed_kernel<<<(BS * K2_M + 255) / 256, 256>>>(ids, emb, x, xp_h, xp_l);

    // weight plane splits
    for (int l = 0; l < Ll; l++) {
        split_launch(liw + (size_t)l * H2 * Mdim, Mdim, Mdim, K2_M, H2,
                     liw_h + (size_t)l * H2 * K2_M, liw_l + (size_t)l * H2 * K2_M);
        split_launch(ldw + (size_t)l * Hh * Rr, Rr, Rr, K2_DT, Hh,
                     ldw_h + (size_t)l * Hh * K2_DT, ldw_l + (size_t)l * Hh * K2_DT);
        split_launch(low + (size_t)l * Mdim * Hh, Hh, Hh, K2_H, Mdim,
                     low_h + (size_t)l * Mdim * K2_H, low_l + (size_t)l * Mdim * K2_H);
    }
    split_launch(hw, Mdim, Mdim, K2_M, Vv, hw_h, hw_l);

    for (int l = 0; l < Ll; l++) {
        // lin_in: [2048,768] x [3072,768]^T -> xr
        gemm_bf16x3<128, 0><<<dim3(H2 / 128, BS / 128), 256, SM128>>>(
            xp_h, xp_l,
            liw_h + (size_t)l * H2 * K2_M, liw_l + (size_t)l * H2 * K2_M,
            K2_M, lib + (size_t)l * H2, xr, H2);

        conv_silu_kernel<<<(BS * Hh + 255) / 256, 256>>>(
            xr, cw + (size_t)l * Hh * Kk, cb + (size_t)l * Hh, u);

        linx_kernel<<<(BS / 8) * (XD / 4), 256>>>(
            u, lxw + (size_t)l * XD * Hh, lxb + (size_t)l * XD, xdbl);

        // delta-part planes (K=48, pad to 64)
        split_launch(xdbl, XD, Rr, K2_DT, BS, act_h, act_l);

        // lin_dt + softplus: [2048,48] x [1536,48]^T -> delta
        gemm_bf16x3<128, 1><<<dim3(Hh / 128, BS / 128), 256, SM128>>>(
            act_h, act_l,
            ldw_h + (size_t)l * Hh * K2_DT, ldw_l + (size_t)l * Hh * K2_DT,
            K2_DT, ldb + (size_t)l * Hh, delta, Hh);

        // scan + gate -> y planes
        scan_gate_kernel<<<(Bb * (Hh / 2) * 32 + 255) / 256, 256>>>(
            delta, u, xdbl, Dp + (size_t)l * Hh, xr, act_h, act_l);

        // lin_out: [2048,1536] x [768,1536]^T -> mo
        gemm_bf16x3<64, 0><<<dim3(Mdim / 64, BS / 128), 256, SM64>>>(
            act_h, act_l,
            low_h + (size_t)l * Mdim * K2_H, low_l + (size_t)l * Mdim * K2_H,
            K2_H, lob + (size_t)l * Mdim, mo, Mdim);

        rmsnorm_add_kernel<<<BS, 256>>>(x, mo, bnw + (size_t)l * Mdim, xp_h, xp_l);
    }

    rmsnorm_final_kernel<<<BS, 256>>>(x, fnw, xp_h, xp_l);

    // head: [2048,768] x [32000,768]^T -> out
    gemm_bf16x3<128, 0><<<dim3(Vv / 128, BS / 128), 256, SM128>>>(
        xp_h, xp_l, hw_h, hw_l, K2_M, hb, out, Vv);
}

// round 7
// speedup vs baseline: 2.1874x; 1.0087x over previous
#include <cuda_runtime.h>
#include <cuda_bf16.h>
#include <math.h>
#include <stdint.h>

#define DEV_INLINE __device__ __forceinline__

// Problem constants
constexpr int Mdim = 768;
constexpr int Vv   = 32000;
constexpr int Rr   = 48;
constexpr int Nn   = 16;
constexpr int Kk   = 4;
constexpr int Ll   = 2;
constexpr int Hh   = 1536;
constexpr int Bb   = 2;
constexpr int Ss   = 1024;
constexpr int BS   = Bb * Ss;     // 2048
constexpr int H2   = 2 * Hh;      // 3072
constexpr int XD   = Rr + 2 * Nn; // 80

// packed bf16-pair (u32) K extents, multiples of 16 (k32 granule)
constexpr int K2_M  = Mdim / 2;   // 384
constexpr int K2_H  = Hh / 2;     // 768
constexpr int K2_DT = 32;         // 48/2=24 -> pad 32

// ---------------- fp32 scratch ----------------
__device__ float g_x    [BS * Mdim];
__device__ float g_xr   [BS * H2];
__device__ float g_u    [BS * Hh];
__device__ float g_xdbl [BS * XD];
__device__ float g_delta[BS * Hh];
__device__ float g_mo   [BS * Mdim];

// ---------------- bf16x2 hi/lo planes ----------------
__device__ __align__(16) uint32_t g_xp_h [BS * K2_M];
__device__ __align__(16) uint32_t g_xp_l [BS * K2_M];
__device__ __align__(16) uint32_t g_act_h[BS * K2_H];
__device__ __align__(16) uint32_t g_act_l[BS * K2_H];
__device__ __align__(16) uint32_t g_liw_h[Ll * H2 * K2_M];
__device__ __align__(16) uint32_t g_liw_l[Ll * H2 * K2_M];
__device__ __align__(16) uint32_t g_ldw_h[Ll * Hh * K2_DT];
__device__ __align__(16) uint32_t g_ldw_l[Ll * Hh * K2_DT];
__device__ __align__(16) uint32_t g_low_h[Ll * Mdim * K2_H];
__device__ __align__(16) uint32_t g_low_l[Ll * Mdim * K2_H];
__device__ __align__(16) uint32_t g_hw_h [Vv * K2_M];
__device__ __align__(16) uint32_t g_hw_l [Vv * K2_M];

// ---------------- helpers ----------------
DEV_INLINE float siluf(float v)     { return v / (1.f + expf(-v)); }
DEV_INLINE float softplusf(float v) { return v > 20.f ? v : log1pf(expf(v)); }

DEV_INLINE float warp_sum(float v) {
    #pragma unroll
    for (int o = 16; o; o >>= 1) v += __shfl_xor_sync(0xffffffffu, v, o);
    return v;
}

DEV_INLINE uint32_t packsplit(float f0, float f1, uint32_t& lo) {
    __nv_bfloat16 h0 = __float2bfloat16(f0);
    __nv_bfloat16 h1 = __float2bfloat16(f1);
    __nv_bfloat16 l0 = __float2bfloat16(f0 - __bfloat162float(h0));
    __nv_bfloat16 l1 = __float2bfloat16(f1 - __bfloat162float(h1));
    lo = (uint32_t)__bfloat16_as_ushort(l0) | ((uint32_t)__bfloat16_as_ushort(l1) << 16);
    return (uint32_t)__bfloat16_as_ushort(h0) | ((uint32_t)__bfloat16_as_ushort(h1) << 16);
}

DEV_INLINE void mma_bf16(float* d, const uint32_t* a, const uint32_t* b) {
    asm volatile(
        "mma.sync.aligned.m16n8k16.row.col.f32.bf16.bf16.f32 "
        "{%0,%1,%2,%3}, {%4,%5,%6,%7}, {%8,%9}, {%0,%1,%2,%3};"
        : "+f"(d[0]), "+f"(d[1]), "+f"(d[2]), "+f"(d[3])
        : "r"(a[0]), "r"(a[1]), "r"(a[2]), "r"(a[3]),
          "r"(b[0]), "r"(b[1]));
}

DEV_INLINE void ldsm_x4(uint32_t& r0, uint32_t& r1, uint32_t& r2, uint32_t& r3,
                        uint32_t addr) {
    asm volatile("ldmatrix.sync.aligned.m8n8.x4.shared.b16 {%0,%1,%2,%3}, [%4];"
                 : "=r"(r0), "=r"(r1), "=r"(r2), "=r"(r3) : "r"(addr));
}

DEV_INLINE void cp_async16(uint32_t dst, const void* src) {
    asm volatile("cp.async.cg.shared.global [%0], [%1], 16;" :: "r"(dst), "l"(src));
}
DEV_INLINE void cp_commit() { asm volatile("cp.async.commit_group;"); }
template<int N> DEV_INLINE void cp_wait() {
    asm volatile("cp.async.wait_group %0;" :: "n"(N));
}

// ---------------- split float -> (hi,lo) bf16-pair planes ----------------
__global__ void split_kernel(const float* __restrict__ in, int in_ld, int K,
                             int K2p, int total,
                             uint32_t* __restrict__ hi, uint32_t* __restrict__ lo) {
    int idx = blockIdx.x * blockDim.x + threadIdx.x;
    if (idx >= total) return;
    int r = idx / K2p, j = idx - r * K2p;
    int k = 2 * j;
    float f0 = (k     < K) ? in[(size_t)r * in_ld + k]     : 0.f;
    float f1 = (k + 1 < K) ? in[(size_t)r * in_ld + k + 1] : 0.f;
    uint32_t l;
    uint32_t h = packsplit(f0, f1, l);
    hi[idx] = h;
    lo[idx] = l;
}

// ---------------- embedding gather + planes ----------------
__global__ void embed_kernel(const int* __restrict__ ids,
                             const float* __restrict__ emb,
                             float* __restrict__ x,
                             uint32_t* __restrict__ xph,
                             uint32_t* __restrict__ xpl) {
    int idx = blockIdx.x * blockDim.x + threadIdx.x;
    if (idx >= BS * K2_M) return;
    int row = idx / K2_M;
    int m2  = idx - row * K2_M;
    const float* e = emb + (size_t)ids[row] * Mdim + 2 * m2;
    float f0 = e[0], f1 = e[1];
    x[(size_t)row * Mdim + 2 * m2]     = f0;
    x[(size_t)row * Mdim + 2 * m2 + 1] = f1;
    uint32_t l;
    uint32_t h = packsplit(f0, f1, l);
    xph[idx] = h;
    xpl[idx] = l;
}

// ---------------- bf16x3 tensor-core GEMM, 3-stage cp.async + ldmatrix -----
// C[i,j] = sum_k A[i,k]*W[j,k] + bias[j]; planes [rows][K2], K2 % 16 == 0.
// BM=128 x BN, k32 floats (16 u32) per stage. 256 threads, warps 2(m) x 4(n).
// Stage layout: A_h[128], A_l[128], W_h[BN], W_l[BN]; row = 16 u32 data + 4 pad.
template<int BN, int ACT>
__global__ __launch_bounds__(256)
void gemm_bf16x3(const uint32_t* __restrict__ Ah, const uint32_t* __restrict__ Al,
                 const uint32_t* __restrict__ Wh, const uint32_t* __restrict__ Wl,
                 int K2,
                 const float* __restrict__ bias,
                 float* __restrict__ C, int ldc) {
    constexpr int NTt  = BN / 32;                 // n8 tiles per warp
    constexpr int ROWB = 80;                      // bytes per smem row
    constexpr int APB  = 128 * ROWB;              // A plane bytes
    constexpr int WPB  = BN * ROWB;               // W plane bytes
    constexpr int STGB = 2 * APB + 2 * WPB;       // stage bytes
    constexpr int NCH  = (256 + 2 * BN) * 4 / 256; // 16B chunks per thread

    extern __shared__ __align__(16) uint32_t smu[];   // 3 stages

    const int tid  = threadIdx.x;
    const int lane = tid & 31;
    const int wid  = tid >> 5;
    const int wm   = wid >> 2;
    const int wn   = wid & 3;
    const int i0   = blockIdx.y * 128;
    const int j0   = blockIdx.x * BN;
    const int lq   = lane & 3;
    const int lg   = lane >> 2;

    const uint32_t sb = (uint32_t)__cvta_generic_to_shared(smu);

    // per-thread cp.async slots (stage-0 dst; add stage*STGB)
    const uint32_t* src[NCH];
    uint32_t dst[NCH];
    #pragma unroll
    for (int uu = 0; uu < NCH; uu++) {
        int c  = uu * 256 + tid;
        int r2 = c >> 2;      // row across planes
        int q  = c & 3;       // 16B quarter within 64B row
        const uint32_t* gbase;
        int pofs, r;
        if (r2 < 128)            { r = r2;            gbase = Ah + (size_t)i0 * K2; pofs = 0; }
        else if (r2 < 256)       { r = r2 - 128;      gbase = Al + (size_t)i0 * K2; pofs = APB; }
        else if (r2 < 256 + BN)  { r = r2 - 256;      gbase = Wh + (size_t)j0 * K2; pofs = 2 * APB; }
        else                     { r = r2 - 256 - BN; gbase = Wl + (size_t)j0 * K2; pofs = 2 * APB + WPB; }
        src[uu] = gbase + (size_t)r * K2 + q * 4;
        dst[uu] = sb + pofs + r * ROWB + q * 16;
    }

    // ldmatrix per-thread row bytes
    const uint32_t aRow = (uint32_t)((wm * 64 + (lane & 15)) * ROWB + ((lane >> 4) << 4));
    const uint32_t bRow = (uint32_t)((wn * (NTt * 8) + ((lane >> 4) << 3) + (lane & 7)) * ROWB
                                     + (((lane >> 3) & 1) << 4));

    float acc[4][NTt][4];
    #pragma unroll
    for (int m = 0; m < 4; m++)
        #pragma unroll
        for (int n = 0; n < NTt; n++)
            #pragma unroll
            for (int c = 0; c < 4; c++) acc[m][n][c] = 0.f;

    const int nk = K2 >> 4;     // k32 chunks

    #pragma unroll
    for (int uu = 0; uu < NCH; uu++) cp_async16(dst[uu], src[uu]);
    cp_commit();
    if (nk > 1) {
        #pragma unroll
        for (int uu = 0; uu < NCH; uu++)
            cp_async16(dst[uu] + STGB, src[uu] + 16);
        cp_commit();
    }

    for (int t = 0; t < nk; t++) {
        if (t + 1 < nk) { cp_wait<1>(); } else { cp_wait<0>(); }
        __syncthreads();
        if (t + 2 < nk) {
            uint32_t so = (uint32_t)((t + 2) % 3) * STGB;
            int ko = (t + 2) * 16;
            #pragma unroll
            for (int uu = 0; uu < NCH; uu++)
                cp_async16(dst[uu] + so, src[uu] + ko);
            cp_commit();
        }

        const uint32_t st = sb + (uint32_t)(t % 3) * STGB;

        #pragma unroll
        for (int h = 0; h < 2; h++) {
            uint32_t ah[4][4], al[4][4], bh[NTt][2], bl[NTt][2];
            #pragma unroll
            for (int m = 0; m < 4; m++) {
                uint32_t a0 = st + aRow + m * (16 * ROWB) + h * 32;
                ldsm_x4(ah[m][0], ah[m][1], ah[m][2], ah[m][3], a0);
                ldsm_x4(al[m][0], al[m][1], al[m][2], al[m][3], a0 + APB);
            }
            #pragma unroll
            for (int j = 0; j < NTt / 2; j++) {
                uint32_t b0 = st + 2 * APB + bRow + j * (16 * ROWB) + h * 32;
                ldsm_x4(bh[2*j][0], bh[2*j][1], bh[2*j+1][0], bh[2*j+1][1], b0);
                ldsm_x4(bl[2*j][0], bl[2*j][1], bl[2*j+1][0], bl[2*j+1][1], b0 + WPB);
            }
            #pragma unroll
            for (int m = 0; m < 4; m++)
                #pragma unroll
                for (int n = 0; n < NTt; n++)
                    mma_bf16(acc[m][n], ah[m], bh[n]);
            #pragma unroll
            for (int m = 0; m < 4; m++)
                #pragma unroll
                for (int n = 0; n < NTt; n++)
                    mma_bf16(acc[m][n], ah[m], bl[n]);
            #pragma unroll
            for (int m = 0; m < 4; m++)
                #pragma unroll
                for (int n = 0; n < NTt; n++)
                    mma_bf16(acc[m][n], al[m], bh[n]);
        }
    }

    // epilogue
    #pragma unroll
    for (int m = 0; m < 4; m++) {
        int gi = i0 + wm * 64 + m * 16 + lg;
        #pragma unroll
        for (int n = 0; n < NTt; n++) {
            int gj = j0 + wn * (NTt * 8) + n * 8 + 2 * lq;
            float b0 = bias[gj], b1 = bias[gj + 1];
            float v0 = acc[m][n][0] + b0;
            float v1 = acc[m][n][1] + b1;
            float v2 = acc[m][n][2] + b0;
            float v3 = acc[m][n][3] + b1;
            if (ACT == 1) {
                v0 = softplusf(v0); v1 = softplusf(v1);
                v2 = softplusf(v2); v3 = softplusf(v3);
            }
            *(float2*)(C + (size_t)gi * ldc + gj)       = make_float2(v0, v1);
            *(float2*)(C + (size_t)(gi + 8) * ldc + gj) = make_float2(v2, v3);
        }
    }
}

// ---------------- lin_x: [BS,1536] x [80,1536]^T, warp-reduction ----------
__global__ __launch_bounds__(256)
void linx_kernel(const float* __restrict__ u,
                 const float* __restrict__ w,
                 const float* __restrict__ bias,
                 float* __restrict__ xdbl) {
    int ig = blockIdx.x / 20;
    int jc = blockIdx.x % 20;
    int wid  = threadIdx.x >> 5;
    int lane = threadIdx.x & 31;
    int i  = ig * 8 + wid;
    int j0 = jc * 4;

    const float4* u4 = (const float4*)(u + (size_t)i * Hh);
    const float4* w0 = (const float4*)(w + (size_t)(j0 + 0) * Hh);
    const float4* w1 = (const float4*)(w + (size_t)(j0 + 1) * Hh);
    const float4* w2 = (const float4*)(w + (size_t)(j0 + 2) * Hh);
    const float4* w3 = (const float4*)(w + (size_t)(j0 + 3) * Hh);

    float p0 = 0.f, p1 = 0.f, p2 = 0.f, p3 = 0.f;
    #pragma unroll
    for (int t = 0; t < Hh / 128; t++) {
        int k = t * 32 + lane;
        float4 uv = u4[k];
        float4 a  = w0[k];
        p0 += uv.x * a.x + uv.y * a.y + uv.z * a.z + uv.w * a.w;
        a = w1[k];
        p1 += uv.x * a.x + uv.y * a.y + uv.z * a.z + uv.w * a.w;
        a = w2[k];
        p2 += uv.x * a.x + uv.y * a.y + uv.z * a.z + uv.w * a.w;
        a = w3[k];
        p3 += uv.x * a.x + uv.y * a.y + uv.z * a.z + uv.w * a.w;
    }
    p0 = warp_sum(p0); p1 = warp_sum(p1);
    p2 = warp_sum(p2); p3 = warp_sum(p3);
    if (lane == 0) {
        float* o = xdbl + (size_t)i * XD + j0;
        o[0] = p0 + bias[j0];
        o[1] = p1 + bias[j0 + 1];
        o[2] = p2 + bias[j0 + 2];
        o[3] = p3 + bias[j0 + 3];
    }
}

// ---------------- depthwise causal conv (K=4) + silu ----------------
__global__ void conv_silu_kernel(const float* __restrict__ xr,
                                 const float* __restrict__ cw,
                                 const float* __restrict__ cb,
                                 float* __restrict__ u) {
    int idx = blockIdx.x * blockDim.x + threadIdx.x;
    if (idx >= BS * Hh) return;
    int h   = idx % Hh;
    int row = idx / Hh;
    int s   = row % Ss;
    int b   = row / Ss;
    float acc = cb[h];
    #pragma unroll
    for (int k = 0; k < Kk; k++) {
        int sp = s - (Kk - 1) + k;
        if (sp >= 0)
            acc += cw[h * Kk + k] * xr[(size_t)(b * Ss + sp) * H2 + h];
    }
    u[idx] = siluf(acc);
}

// ---------------- selective scan + gate + plane split fused ---------------
__global__ void scan_gate_kernel(const float* __restrict__ delta,
                                 const float* __restrict__ u,
                                 const float* __restrict__ xdbl,
                                 const float* __restrict__ Dp,
                                 const float* __restrict__ xr,
                                 uint32_t* __restrict__ yh,
                                 uint32_t* __restrict__ yl) {
    int gwarp = (blockIdx.x * blockDim.x + threadIdx.x) >> 5;
    if (gwarp >= Bb * (Hh / 2)) return;
    int lane = threadIdx.x & 31;
    int half = lane >> 4;
    int n    = lane & 15;
    int b    = gwarp / (Hh / 2);
    int hp   = gwarp % (Hh / 2);
    int h    = hp * 2 + half;

    const float An = -(float)(n + 1);
    const float Dh = Dp[h];
    float state = 0.f;

    int base = b * Ss;
    for (int s = 0; s < Ss; s++) {
        int row = base + s;
        float dv = __ldg(delta + (size_t)row * Hh + h);
        float uv = __ldg(u + (size_t)row * Hh + h);
        float Bn = __ldg(xdbl + row * XD + Rr + n);
        float Cn = __ldg(xdbl + row * XD + Rr + Nn + n);
        float dA = expf(dv * An);
        state = dA * state + dv * Bn * uv;
        float val = state * Cn;
        val += __shfl_xor_sync(0xffffffffu, val, 8);
        val += __shfl_xor_sync(0xffffffffu, val, 4);
        val += __shfl_xor_sync(0xffffffffu, val, 2);
        val += __shfl_xor_sync(0xffffffffu, val, 1);
        float res = __ldg(xr + (size_t)row * H2 + Hh + h);
        float yv  = (val + uv * Dh) * siluf(res);
        float y1  = __shfl_sync(0xffffffffu, yv, 16);
        if (lane == 0) {
            uint32_t lo;
            uint32_t hi = packsplit(yv, y1, lo);
            yh[(size_t)row * K2_H + hp] = hi;
            yl[(size_t)row * K2_H + hp] = lo;
        }
    }
}

// ---------------- x += rmsnorm(mo) * w ; emit x planes ----------------
__global__ void rmsnorm_add_kernel(float* __restrict__ x,
                                   const float* __restrict__ mo,
                                   const float* __restrict__ w,
                                   uint32_t* __restrict__ xph,
                                   uint32_t* __restrict__ xpl) {
    int row = blockIdx.x;
    const float* r = mo + (size_t)row * Mdim;
    float ss = 0.f;
    for (int m = threadIdx.x; m < Mdim; m += blockDim.x) {
        float v = r[m];
        ss += v * v;
    }
    __shared__ float sh[8];
    ss = warp_sum(ss);
    int wid = threadIdx.x >> 5, lane = threadIdx.x & 31;
    if (lane == 0) sh[wid] = ss;
    __syncthreads();
    if (wid == 0) {
        float v = (lane < (int)(blockDim.x >> 5)) ? sh[lane] : 0.f;
        v = warp_sum(v);
        if (lane == 0) sh[0] = v;
    }
    __syncthreads();
    float scale = rsqrtf(sh[0] / (float)Mdim + 1e-15f);
    float* xp = x + (size_t)row * Mdim;
    for (int m2 = threadIdx.x; m2 < K2_M; m2 += blockDim.x) {
        int m = 2 * m2;
        float v0 = xp[m]     + r[m]     * scale * w[m];
        float v1 = xp[m + 1] + r[m + 1] * scale * w[m + 1];
        xp[m] = v0; xp[m + 1] = v1;
        uint32_t lo;
        uint32_t hi = packsplit(v0, v1, lo);
        xph[(size_t)row * K2_M + m2] = hi;
        xpl[(size_t)row * K2_M + m2] = lo;
    }
}

// ---------------- final rmsnorm -> planes only ----------------
__global__ void rmsnorm_final_kernel(const float* __restrict__ x,
                                     const float* __restrict__ w,
                                     uint32_t* __restrict__ xph,
                                     uint32_t* __restrict__ xpl) {
    int row = blockIdx.x;
    const float* r = x + (size_t)row * Mdim;
    float ss = 0.f;
    for (int m = threadIdx.x; m < Mdim; m += blockDim.x) {
        float v = r[m];
        ss += v * v;
    }
    __shared__ float sh[8];
    ss = warp_sum(ss);
    int wid = threadIdx.x >> 5, lane = threadIdx.x & 31;
    if (lane == 0) sh[wid] = ss;
    __syncthreads();
    if (wid == 0) {
        float v = (lane < (int)(blockDim.x >> 5)) ? sh[lane] : 0.f;
        v = warp_sum(v);
        if (lane == 0) sh[0] = v;
    }
    __syncthreads();
    float scale = rsqrtf(sh[0] / (float)Mdim + 1e-15f);
    for (int m2 = threadIdx.x; m2 < K2_M; m2 += blockDim.x) {
        int m = 2 * m2;
        float v0 = r[m]     * scale * w[m];
        float v1 = r[m + 1] * scale * w[m + 1];
        uint32_t lo;
        uint32_t hi = packsplit(v0, v1, lo);
        xph[(size_t)row * K2_M + m2] = hi;
        xpl[(size_t)row * K2_M + m2] = lo;
    }
}

// ---------------- launch ----------------
static void split_launch(const float* in, int in_ld, int K, int K2p, int rows,
                         uint32_t* hi, uint32_t* lo) {
    int total = rows * K2p;
    split_kernel<<<(total + 255) / 256, 256>>>(in, in_ld, K, K2p, total, hi, lo);
}

extern "C" void kernel_launch(void* const* d_in, const int* in_sizes, int n_in,
                              void* d_out, int out_size) {
    const int*   ids = (const int*)  d_in[0];
    const float* emb = (const float*)d_in[1];
    const float* liw = (const float*)d_in[2];
    const float* lib = (const float*)d_in[3];
    const float* cw  = (const float*)d_in[4];
    const float* cb  = (const float*)d_in[5];
    const float* lxw = (const float*)d_in[6];
    const float* lxb = (const float*)d_in[7];
    const float* ldw = (const float*)d_in[8];
    const float* ldb = (const float*)d_in[9];
    const float* low = (const float*)d_in[10];
    const float* lob = (const float*)d_in[11];
    const float* Dp  = (const float*)d_in[12];
    const float* bnw = (const float*)d_in[13];
    const float* fnw = (const float*)d_in[14];
    const float* hw  = (const float*)d_in[15];
    const float* hb  = (const float*)d_in[16];
    float* out = (float*)d_out;

    float *x, *xr, *u, *xdbl, *delta, *mo;
    cudaGetSymbolAddress((void**)&x,     g_x);
    cudaGetSymbolAddress((void**)&xr,    g_xr);
    cudaGetSymbolAddress((void**)&u,     g_u);
    cudaGetSymbolAddress((void**)&xdbl,  g_xdbl);
    cudaGetSymbolAddress((void**)&delta, g_delta);
    cudaGetSymbolAddress((void**)&mo,    g_mo);

    uint32_t *xp_h, *xp_l, *act_h, *act_l;
    uint32_t *liw_h, *liw_l, *ldw_h, *ldw_l, *low_h, *low_l, *hw_h, *hw_l;
    cudaGetSymbolAddress((void**)&xp_h,  g_xp_h);
    cudaGetSymbolAddress((void**)&xp_l,  g_xp_l);
    cudaGetSymbolAddress((void**)&act_h, g_act_h);
    cudaGetSymbolAddress((void**)&act_l, g_act_l);
    cudaGetSymbolAddress((void**)&liw_h, g_liw_h);
    cudaGetSymbolAddress((void**)&liw_l, g_liw_l);
    cudaGetSymbolAddress((void**)&ldw_h, g_ldw_h);
    cudaGetSymbolAddress((void**)&ldw_l, g_ldw_l);
    cudaGetSymbolAddress((void**)&low_h, g_low_h);
    cudaGetSymbolAddress((void**)&low_l, g_low_l);
    cudaGetSymbolAddress((void**)&hw_h,  g_hw_h);
    cudaGetSymbolAddress((void**)&hw_l,  g_hw_l);

    // dynamic smem: 3 stages, 80B rows
    const int SM128 = 3 * (256 + 256) * 80;  // 122880
    const int SM64  = 3 * (256 + 128) * 80;  // 92160
    cudaFuncSetAttribute((const void*)gemm_bf16x3<128, 0>,
                         cudaFuncAttributeMaxDynamicSharedMemorySize, SM128);
    cudaFuncSetAttribute((const void*)gemm_bf16x3<128, 1>,
                         cudaFuncAttributeMaxDynamicSharedMemorySize, SM128);
    cudaFuncSetAttribute((const void*)gemm_bf16x3<64, 0>,
                         cudaFuncAttributeMaxDynamicSharedMemorySize, SM64);

    embed_kernel<<<(BS * K2_M + 255) / 256, 256>>>(ids, emb, x, xp_h, xp_l);

    for (int l = 0; l < Ll; l++) {
        // weight plane splits for this layer (launches 1-3 for l=0)
        split_launch(liw + (size_t)l * H2 * Mdim, Mdim, Mdim, K2_M, H2,
                     liw_h + (size_t)l * H2 * K2_M, liw_l + (size_t)l * H2 * K2_M);
        split_launch(ldw + (size_t)l * Hh * Rr, Rr, Rr, K2_DT, Hh,
                     ldw_h + (size_t)l * Hh * K2_DT, ldw_l + (size_t)l * Hh * K2_DT);
        split_launch(low + (size_t)l * Mdim * Hh, Hh, Hh, K2_H, Mdim,
                     low_h + (size_t)l * Mdim * K2_H, low_l + (size_t)l * Mdim * K2_H);
        if (l == 0)   // launch 4
            split_launch(hw, Mdim, Mdim, K2_M, Vv, hw_h, hw_l);

        // lin_in: [2048,768] x [3072,768]^T -> xr   (launch 5 for l=0: profiled)
        gemm_bf16x3<128, 0><<<dim3(H2 / 128, BS / 128), 256, SM128>>>(
            xp_h, xp_l,
            liw_h + (size_t)l * H2 * K2_M, liw_l + (size_t)l * H2 * K2_M,
            K2_M, lib + (size_t)l * H2, xr, H2);

        conv_silu_kernel<<<(BS * Hh + 255) / 256, 256>>>(
            xr, cw + (size_t)l * Hh * Kk, cb + (size_t)l * Hh, u);

        linx_kernel<<<(BS / 8) * (XD / 4), 256>>>(
            u, lxw + (size_t)l * XD * Hh, lxb + (size_t)l * XD, xdbl);

        // delta-part planes (K=48, pad to 64)
        split_launch(xdbl, XD, Rr, K2_DT, BS, act_h, act_l);

        // lin_dt + softplus: [2048,48] x [1536,48]^T -> delta
        gemm_bf16x3<128, 1><<<dim3(Hh / 128, BS / 128), 256, SM128>>>(
            act_h, act_l,
            ldw_h + (size_t)l * Hh * K2_DT, ldw_l + (size_t)l * Hh * K2_DT,
            K2_DT, ldb + (size_t)l * Hh, delta, Hh);

        // scan + gate -> y planes
        scan_gate_kernel<<<(Bb * (Hh / 2) * 32 + 255) / 256, 256>>>(
            delta, u, xdbl, Dp + (size_t)l * Hh, xr, act_h, act_l);

        // lin_out: [2048,1536] x [768,1536]^T -> mo
        gemm_bf16x3<64, 0><<<dim3(Mdim / 64, BS / 128), 256, SM64>>>(
            act_h, act_l,
            low_h + (size_t)l * Mdim * K2_H, low_l + (size_t)l * Mdim * K2_H,
            K2_H, lob + (size_t)l * Mdim, mo, Mdim);

        rmsnorm_add_kernel<<<BS, 256>>>(x, mo, bnw + (size_t)l * Mdim, xp_h, xp_l);
    }

    rmsnorm_final_kernel<<<BS, 256>>>(x, fnw, xp_h, xp_l);

    // head: [2048,768] x [32000,768]^T -> out
    gemm_bf16x3<128, 0><<<dim3(Vv / 128, BS / 128), 256, SM128>>>(
        xp_h, xp_l, hw_h, hw_l, K2_M, hb, out, Vv);
}

// round 8
// speedup vs baseline: 2.8589x; 1.3070x over previous
#include <cuda_runtime.h>
#include <cuda_bf16.h>
#include <cuda_fp16.h>
#include <math.h>
#include <stdint.h>

#define DEV_INLINE __device__ __forceinline__

// Problem constants
constexpr int Mdim = 768;
constexpr int Vv   = 32000;
constexpr int Rr   = 48;
constexpr int Nn   = 16;
constexpr int Kk   = 4;
constexpr int Ll   = 2;
constexpr int Hh   = 1536;
constexpr int Bb   = 2;
constexpr int Ss   = 1024;
constexpr int BS   = Bb * Ss;     // 2048
constexpr int H2   = 2 * Hh;      // 3072
constexpr int XD   = Rr + 2 * Nn; // 80

constexpr int K2_M  = Mdim / 2;   // 384
constexpr int K2_H  = Hh / 2;     // 768
constexpr int K2_DT = 32;         // 48/2=24 -> pad 32

// ---------------- fp32 scratch ----------------
__device__ float g_x    [BS * Mdim];
__device__ float g_xr   [BS * H2];
__device__ float g_u    [BS * Hh];
__device__ float g_xdbl [BS * XD];
__device__ float g_delta[BS * Hh];
__device__ float g_mo   [BS * Mdim];

// ---------------- packed 16-bit planes ----------------
__device__ __align__(16) uint32_t g_xp_h [BS * K2_M];
__device__ __align__(16) uint32_t g_xp_l [BS * K2_M];
__device__ __align__(16) uint32_t g_act_h[BS * K2_H];   // y planes / fp16 xn
__device__ __align__(16) uint32_t g_act_l[BS * K2_H];
__device__ __align__(16) uint32_t g_liw_h[Ll * H2 * K2_M];
__device__ __align__(16) uint32_t g_liw_l[Ll * H2 * K2_M];
__device__ __align__(16) uint32_t g_ldw_h[Ll * Hh * K2_DT];
__device__ __align__(16) uint32_t g_ldw_l[Ll * Hh * K2_DT];
__device__ __align__(16) uint32_t g_low_h[Ll * Mdim * K2_H];
__device__ __align__(16) uint32_t g_low_l[Ll * Mdim * K2_H];
__device__ __align__(16) uint32_t g_hw_h [Vv * K2_M];   // fp16 pairs
__device__ __align__(16) uint32_t g_xnf  [BS * K2_M];   // (unused spare)

// ---------------- helpers ----------------
DEV_INLINE float siluf(float v)     { return v / (1.f + expf(-v)); }
DEV_INLINE float softplusf(float v) { return v > 20.f ? v : log1pf(expf(v)); }

DEV_INLINE float warp_sum(float v) {
    #pragma unroll
    for (int o = 16; o; o >>= 1) v += __shfl_xor_sync(0xffffffffu, v, o);
    return v;
}

DEV_INLINE uint32_t packsplit(float f0, float f1, uint32_t& lo) {
    __nv_bfloat16 h0 = __float2bfloat16(f0);
    __nv_bfloat16 h1 = __float2bfloat16(f1);
    __nv_bfloat16 l0 = __float2bfloat16(f0 - __bfloat162float(h0));
    __nv_bfloat16 l1 = __float2bfloat16(f1 - __bfloat162float(h1));
    lo = (uint32_t)__bfloat16_as_ushort(l0) | ((uint32_t)__bfloat16_as_ushort(l1) << 16);
    return (uint32_t)__bfloat16_as_ushort(h0) | ((uint32_t)__bfloat16_as_ushort(h1) << 16);
}

DEV_INLINE uint32_t pack_f16(float f0, float f1) {
    __half2 h = __floats2half2_rn(f0, f1);
    return *(uint32_t*)&h;
}

DEV_INLINE void mma_bf16(float* d, const uint32_t* a, const uint32_t* b) {
    asm volatile(
        "mma.sync.aligned.m16n8k16.row.col.f32.bf16.bf16.f32 "
        "{%0,%1,%2,%3}, {%4,%5,%6,%7}, {%8,%9}, {%0,%1,%2,%3};"
        : "+f"(d[0]), "+f"(d[1]), "+f"(d[2]), "+f"(d[3])
        : "r"(a[0]), "r"(a[1]), "r"(a[2]), "r"(a[3]),
          "r"(b[0]), "r"(b[1]));
}

DEV_INLINE void mma_f16(float* d, const uint32_t* a, const uint32_t* b) {
    asm volatile(
        "mma.sync.aligned.m16n8k16.row.col.f32.f16.f16.f32 "
        "{%0,%1,%2,%3}, {%4,%5,%6,%7}, {%8,%9}, {%0,%1,%2,%3};"
        : "+f"(d[0]), "+f"(d[1]), "+f"(d[2]), "+f"(d[3])
        : "r"(a[0]), "r"(a[1]), "r"(a[2]), "r"(a[3]),
          "r"(b[0]), "r"(b[1]));
}

DEV_INLINE void ldsm_x4(uint32_t& r0, uint32_t& r1, uint32_t& r2, uint32_t& r3,
                        uint32_t addr) {
    asm volatile("ldmatrix.sync.aligned.m8n8.x4.shared.b16 {%0,%1,%2,%3}, [%4];"
                 : "=r"(r0), "=r"(r1), "=r"(r2), "=r"(r3) : "r"(addr));
}

DEV_INLINE void cp_async16(uint32_t dst, const void* src) {
    asm volatile("cp.async.cg.shared.global [%0], [%1], 16;" :: "r"(dst), "l"(src));
}
DEV_INLINE void cp_commit() { asm volatile("cp.async.commit_group;"); }
template<int N> DEV_INLINE void cp_wait() {
    asm volatile("cp.async.wait_group %0;" :: "n"(N));
}

// ---------------- fused per-layer weight split (liw + ldw + low) ----------
constexpr int SEG0 = H2 * K2_M;        // 1179648
constexpr int SEG1 = Hh * K2_DT;       // 49152
constexpr int SEG2 = Mdim * K2_H;      // 589824
constexpr int SEGT = SEG0 + SEG1 + SEG2;

__global__ void split_layer_kernel(const float* __restrict__ liw,
                                   const float* __restrict__ ldw,
                                   const float* __restrict__ low,
                                   uint32_t* __restrict__ liw_h, uint32_t* __restrict__ liw_l,
                                   uint32_t* __restrict__ ldw_h, uint32_t* __restrict__ ldw_l,
                                   uint32_t* __restrict__ low_h, uint32_t* __restrict__ low_l) {
    int idx = blockIdx.x * blockDim.x + threadIdx.x;
    if (idx >= SEGT) return;
    float f0, f1;
    uint32_t *ph, *pl;
    if (idx < SEG0) {
        int k = 2 * (idx % K2_M);
        int r = idx / K2_M;
        f0 = liw[(size_t)r * Mdim + k];
        f1 = liw[(size_t)r * Mdim + k + 1];
        ph = liw_h + idx; pl = liw_l + idx;
    } else if (idx < SEG0 + SEG1) {
        int i = idx - SEG0;
        int j = i % K2_DT, r = i / K2_DT;
        int k = 2 * j;
        f0 = (k     < Rr) ? ldw[(size_t)r * Rr + k]     : 0.f;
        f1 = (k + 1 < Rr) ? ldw[(size_t)r * Rr + k + 1] : 0.f;
        ph = ldw_h + i; pl = ldw_l + i;
    } else {
        int i = idx - SEG0 - SEG1;
        int k = 2 * (i % K2_H);
        int r = i / K2_H;
        f0 = low[(size_t)r * Hh + k];
        f1 = low[(size_t)r * Hh + k + 1];
        ph = low_h + i; pl = low_l + i;
    }
    uint32_t l;
    uint32_t h = packsplit(f0, f1, l);
    *ph = h; *pl = l;
}

// ---------------- fp16 split for head weights ----------------
__global__ void split_hw_f16_kernel(const float* __restrict__ in,
                                    uint32_t* __restrict__ out) {
    int idx = blockIdx.x * blockDim.x + threadIdx.x;
    if (idx >= Vv * K2_M) return;
    int r = idx / K2_M;
    int k = 2 * (idx - r * K2_M);
    out[idx] = pack_f16(in[(size_t)r * Mdim + k], in[(size_t)r * Mdim + k + 1]);
}

// ---------------- xdbl delta-part split (bf16 planes) ----------------
__global__ void split_dt_kernel(const float* __restrict__ xdbl,
                                uint32_t* __restrict__ hi, uint32_t* __restrict__ lo) {
    int idx = blockIdx.x * blockDim.x + threadIdx.x;
    if (idx >= BS * K2_DT) return;
    int r = idx / K2_DT, j = idx - r * K2_DT;
    int k = 2 * j;
    float f0 = (k     < Rr) ? xdbl[(size_t)r * XD + k]     : 0.f;
    float f1 = (k + 1 < Rr) ? xdbl[(size_t)r * XD + k + 1] : 0.f;
    uint32_t l;
    uint32_t h = packsplit(f0, f1, l);
    hi[idx] = h; lo[idx] = l;
}

// ---------------- embedding gather + planes ----------------
__global__ void embed_kernel(const int* __restrict__ ids,
                             const float* __restrict__ emb,
                             float* __restrict__ x,
                             uint32_t* __restrict__ xph,
                             uint32_t* __restrict__ xpl) {
    int idx = blockIdx.x * blockDim.x + threadIdx.x;
    if (idx >= BS * K2_M) return;
    int row = idx / K2_M;
    int m2  = idx - row * K2_M;
    const float* e = emb + (size_t)ids[row] * Mdim + 2 * m2;
    float f0 = e[0], f1 = e[1];
    x[(size_t)row * Mdim + 2 * m2]     = f0;
    x[(size_t)row * Mdim + 2 * m2 + 1] = f1;
    uint32_t l;
    uint32_t h = packsplit(f0, f1, l);
    xph[idx] = h;
    xpl[idx] = l;
}

// ---------------- bf16x3 tensor-core GEMM, 3-stage cp.async + ldmatrix -----
template<int BN, int ACT>
__global__ __launch_bounds__(256)
void gemm_bf16x3(const uint32_t* __restrict__ Ah, const uint32_t* __restrict__ Al,
                 const uint32_t* __restrict__ Wh, const uint32_t* __restrict__ Wl,
                 int K2,
                 const float* __restrict__ bias,
                 float* __restrict__ C, int ldc) {
    constexpr int NTt  = BN / 32;
    constexpr int ROWB = 80;
    constexpr int APB  = 128 * ROWB;
    constexpr int WPB  = BN * ROWB;
    constexpr int STGB = 2 * APB + 2 * WPB;
    constexpr int NCH  = (256 + 2 * BN) * 4 / 256;

    extern __shared__ __align__(16) uint32_t smu[];

    const int tid  = threadIdx.x;
    const int lane = tid & 31;
    const int wid  = tid >> 5;
    const int wm   = wid >> 2;
    const int wn   = wid & 3;
    const int i0   = blockIdx.y * 128;
    const int j0   = blockIdx.x * BN;
    const int lq   = lane & 3;
    const int lg   = lane >> 2;

    const uint32_t sb = (uint32_t)__cvta_generic_to_shared(smu);

    const uint32_t* src[NCH];
    uint32_t dst[NCH];
    #pragma unroll
    for (int uu = 0; uu < NCH; uu++) {
        int c  = uu * 256 + tid;
        int r2 = c >> 2;
        int q  = c & 3;
        const uint32_t* gbase;
        int pofs, r;
        if (r2 < 128)            { r = r2;            gbase = Ah + (size_t)i0 * K2; pofs = 0; }
        else if (r2 < 256)       { r = r2 - 128;      gbase = Al + (size_t)i0 * K2; pofs = APB; }
        else if (r2 < 256 + BN)  { r = r2 - 256;      gbase = Wh + (size_t)j0 * K2; pofs = 2 * APB; }
        else                     { r = r2 - 256 - BN; gbase = Wl + (size_t)j0 * K2; pofs = 2 * APB + WPB; }
        src[uu] = gbase + (size_t)r * K2 + q * 4;
        dst[uu] = sb + pofs + r * ROWB + q * 16;
    }

    const uint32_t aRow = (uint32_t)((wm * 64 + (lane & 15)) * ROWB + ((lane >> 4) << 4));
    const uint32_t bRow = (uint32_t)((wn * (NTt * 8) + ((lane >> 4) << 3) + (lane & 7)) * ROWB
                                     + (((lane >> 3) & 1) << 4));

    float acc[4][NTt][4];
    #pragma unroll
    for (int m = 0; m < 4; m++)
        #pragma unroll
        for (int n = 0; n < NTt; n++)
            #pragma unroll
            for (int c = 0; c < 4; c++) acc[m][n][c] = 0.f;

    const int nk = K2 >> 4;

    #pragma unroll
    for (int uu = 0; uu < NCH; uu++) cp_async16(dst[uu], src[uu]);
    cp_commit();
    if (nk > 1) {
        #pragma unroll
        for (int uu = 0; uu < NCH; uu++)
            cp_async16(dst[uu] + STGB, src[uu] + 16);
        cp_commit();
    }

    for (int t = 0; t < nk; t++) {
        if (t + 1 < nk) { cp_wait<1>(); } else { cp_wait<0>(); }
        __syncthreads();
        if (t + 2 < nk) {
            uint32_t so = (uint32_t)((t + 2) % 3) * STGB;
            int ko = (t + 2) * 16;
            #pragma unroll
            for (int uu = 0; uu < NCH; uu++)
                cp_async16(dst[uu] + so, src[uu] + ko);
            cp_commit();
        }

        const uint32_t st = sb + (uint32_t)(t % 3) * STGB;

        #pragma unroll
        for (int h = 0; h < 2; h++) {
            uint32_t ah[4][4], al[4][4], bh[NTt][2], bl[NTt][2];
            #pragma unroll
            for (int m = 0; m < 4; m++) {
                uint32_t a0 = st + aRow + m * (16 * ROWB) + h * 32;
                ldsm_x4(ah[m][0], ah[m][1], ah[m][2], ah[m][3], a0);
                ldsm_x4(al[m][0], al[m][1], al[m][2], al[m][3], a0 + APB);
            }
            #pragma unroll
            for (int j = 0; j < NTt / 2; j++) {
                uint32_t b0 = st + 2 * APB + bRow + j * (16 * ROWB) + h * 32;
                ldsm_x4(bh[2*j][0], bh[2*j][1], bh[2*j+1][0], bh[2*j+1][1], b0);
                ldsm_x4(bl[2*j][0], bl[2*j][1], bl[2*j+1][0], bl[2*j+1][1], b0 + WPB);
            }
            #pragma unroll
            for (int m = 0; m < 4; m++)
                #pragma unroll
                for (int n = 0; n < NTt; n++)
                    mma_bf16(acc[m][n], ah[m], bh[n]);
            #pragma unroll
            for (int m = 0; m < 4; m++)
                #pragma unroll
                for (int n = 0; n < NTt; n++)
                    mma_bf16(acc[m][n], ah[m], bl[n]);
            #pragma unroll
            for (int m = 0; m < 4; m++)
                #pragma unroll
                for (int n = 0; n < NTt; n++)
                    mma_bf16(acc[m][n], al[m], bh[n]);
        }
    }

    #pragma unroll
    for (int m = 0; m < 4; m++) {
        int gi = i0 + wm * 64 + m * 16 + lg;
        #pragma unroll
        for (int n = 0; n < NTt; n++) {
            int gj = j0 + wn * (NTt * 8) + n * 8 + 2 * lq;
            float b0 = bias[gj], b1 = bias[gj + 1];
            float v0 = acc[m][n][0] + b0;
            float v1 = acc[m][n][1] + b1;
            float v2 = acc[m][n][2] + b0;
            float v3 = acc[m][n][3] + b1;
            if (ACT == 1) {
                v0 = softplusf(v0); v1 = softplusf(v1);
                v2 = softplusf(v2); v3 = softplusf(v3);
            }
            *(float2*)(C + (size_t)gi * ldc + gj)       = make_float2(v0, v1);
            *(float2*)(C + (size_t)(gi + 8) * ldc + gj) = make_float2(v2, v3);
        }
    }
}

// ---------------- fp16 single-pass GEMM (head) ----------------
__global__ __launch_bounds__(256, 2)
void gemm_fp16(const uint32_t* __restrict__ Ah, const uint32_t* __restrict__ Wh,
               int K2,
               const float* __restrict__ bias,
               float* __restrict__ C, int ldc) {
    constexpr int BN   = 128;
    constexpr int ROWB = 80;
    constexpr int APB  = 128 * ROWB;
    constexpr int STGB = 2 * APB;
    constexpr int NCH  = 4;

    extern __shared__ __align__(16) uint32_t smu[];

    const int tid  = threadIdx.x;
    const int lane = tid & 31;
    const int wid  = tid >> 5;
    const int wm   = wid >> 2;
    const int wn   = wid & 3;
    const int i0   = blockIdx.y * 128;
    const int j0   = blockIdx.x * BN;
    const int lq   = lane & 3;
    const int lg   = lane >> 2;

    const uint32_t sb = (uint32_t)__cvta_generic_to_shared(smu);

    const uint32_t* src[NCH];
    uint32_t dst[NCH];
    #pragma unroll
    for (int uu = 0; uu < NCH; uu++) {
        int c  = uu * 256 + tid;
        int r2 = c >> 2;
        int q  = c & 3;
        const uint32_t* gbase;
        int pofs, r;
        if (r2 < 128) { r = r2;       gbase = Ah + (size_t)i0 * K2; pofs = 0; }
        else          { r = r2 - 128; gbase = Wh + (size_t)j0 * K2; pofs = APB; }
        src[uu] = gbase + (size_t)r * K2 + q * 4;
        dst[uu] = sb + pofs + r * ROWB + q * 16;
    }

    const uint32_t aRow = (uint32_t)((wm * 64 + (lane & 15)) * ROWB + ((lane >> 4) << 4));
    const uint32_t bRow = (uint32_t)((wn * 32 + ((lane >> 4) << 3) + (lane & 7)) * ROWB
                                     + (((lane >> 3) & 1) << 4));

    float acc[4][4][4];
    #pragma unroll
    for (int m = 0; m < 4; m++)
        #pragma unroll
        for (int n = 0; n < 4; n++)
            #pragma unroll
            for (int c = 0; c < 4; c++) acc[m][n][c] = 0.f;

    const int nk = K2 >> 4;

    #pragma unroll
    for (int uu = 0; uu < NCH; uu++) cp_async16(dst[uu], src[uu]);
    cp_commit();
    #pragma unroll
    for (int uu = 0; uu < NCH; uu++) cp_async16(dst[uu] + STGB, src[uu] + 16);
    cp_commit();

    for (int t = 0; t < nk; t++) {
        if (t + 1 < nk) { cp_wait<1>(); } else { cp_wait<0>(); }
        __syncthreads();
        if (t + 2 < nk) {
            uint32_t so = (uint32_t)((t + 2) % 3) * STGB;
            int ko = (t + 2) * 16;
            #pragma unroll
            for (int uu = 0; uu < NCH; uu++)
                cp_async16(dst[uu] + so, src[uu] + ko);
            cp_commit();
        }

        const uint32_t st = sb + (uint32_t)(t % 3) * STGB;

        #pragma unroll
        for (int h = 0; h < 2; h++) {
            uint32_t ah[4][4], bh[4][2];
            #pragma unroll
            for (int m = 0; m < 4; m++) {
                uint32_t a0 = st + aRow + m * (16 * ROWB) + h * 32;
                ldsm_x4(ah[m][0], ah[m][1], ah[m][2], ah[m][3], a0);
            }
            #pragma unroll
            for (int j = 0; j < 2; j++) {
                uint32_t b0 = st + APB + bRow + j * (16 * ROWB) + h * 32;
                ldsm_x4(bh[2*j][0], bh[2*j][1], bh[2*j+1][0], bh[2*j+1][1], b0);
            }
            #pragma unroll
            for (int m = 0; m < 4; m++)
                #pragma unroll
                for (int n = 0; n < 4; n++)
                    mma_f16(acc[m][n], ah[m], bh[n]);
        }
    }

    #pragma unroll
    for (int m = 0; m < 4; m++) {
        int gi = i0 + wm * 64 + m * 16 + lg;
        #pragma unroll
        for (int n = 0; n < 4; n++) {
            int gj = j0 + wn * 32 + n * 8 + 2 * lq;
            float b0 = bias[gj], b1 = bias[gj + 1];
            *(float2*)(C + (size_t)gi * ldc + gj) =
                make_float2(acc[m][n][0] + b0, acc[m][n][1] + b1);
            *(float2*)(C + (size_t)(gi + 8) * ldc + gj) =
                make_float2(acc[m][n][2] + b0, acc[m][n][3] + b1);
        }
    }
}

// ---------------- lin_x: [BS,1536] x [80,1536]^T, warp-reduction ----------
__global__ __launch_bounds__(256)
void linx_kernel(const float* __restrict__ u,
                 const float* __restrict__ w,
                 const float* __restrict__ bias,
                 float* __restrict__ xdbl) {
    int ig = blockIdx.x / 20;
    int jc = blockIdx.x % 20;
    int wid  = threadIdx.x >> 5;
    int lane = threadIdx.x & 31;
    int i  = ig * 8 + wid;
    int j0 = jc * 4;

    const float4* u4 = (const float4*)(u + (size_t)i * Hh);
    const float4* w0 = (const float4*)(w + (size_t)(j0 + 0) * Hh);
    const float4* w1 = (const float4*)(w + (size_t)(j0 + 1) * Hh);
    const float4* w2 = (const float4*)(w + (size_t)(j0 + 2) * Hh);
    const float4* w3 = (const float4*)(w + (size_t)(j0 + 3) * Hh);

    float p0 = 0.f, p1 = 0.f, p2 = 0.f, p3 = 0.f;
    #pragma unroll
    for (int t = 0; t < Hh / 128; t++) {
        int k = t * 32 + lane;
        float4 uv = u4[k];
        float4 a  = w0[k];
        p0 += uv.x * a.x + uv.y * a.y + uv.z * a.z + uv.w * a.w;
        a = w1[k];
        p1 += uv.x * a.x + uv.y * a.y + uv.z * a.z + uv.w * a.w;
        a = w2[k];
        p2 += uv.x * a.x + uv.y * a.y + uv.z * a.z + uv.w * a.w;
        a = w3[k];
        p3 += uv.x * a.x + uv.y * a.y + uv.z * a.z + uv.w * a.w;
    }
    p0 = warp_sum(p0); p1 = warp_sum(p1);
    p2 = warp_sum(p2); p3 = warp_sum(p3);
    if (lane == 0) {
        float* o = xdbl + (size_t)i * XD + j0;
        o[0] = p0 + bias[j0];
        o[1] = p1 + bias[j0 + 1];
        o[2] = p2 + bias[j0 + 2];
        o[3] = p3 + bias[j0 + 3];
    }
}

// ---------------- depthwise causal conv (K=4) + silu ----------------
__global__ void conv_silu_kernel(const float* __restrict__ xr,
                                 const float* __restrict__ cw,
                                 const float* __restrict__ cb,
                                 float* __restrict__ u) {
    int idx = blockIdx.x * blockDim.x + threadIdx.x;
    if (idx >= BS * Hh) return;
    int h   = idx % Hh;
    int row = idx / Hh;
    int s   = row % Ss;
    int b   = row / Ss;
    float acc = cb[h];
    #pragma unroll
    for (int k = 0; k < Kk; k++) {
        int sp = s - (Kk - 1) + k;
        if (sp >= 0)
            acc += cw[h * Kk + k] * xr[(size_t)(b * Ss + sp) * H2 + h];
    }
    u[idx] = siluf(acc);
}

// ---------------- selective scan + gate + plane split fused ---------------
__global__ void scan_gate_kernel(const float* __restrict__ delta,
                                 const float* __restrict__ u,
                                 const float* __restrict__ xdbl,
                                 const float* __restrict__ Dp,
                                 const float* __restrict__ xr,
                                 uint32_t* __restrict__ yh,
                                 uint32_t* __restrict__ yl) {
    int gwarp = (blockIdx.x * blockDim.x + threadIdx.x) >> 5;
    if (gwarp >= Bb * (Hh / 2)) return;
    int lane = threadIdx.x & 31;
    int half = lane >> 4;
    int n    = lane & 15;
    int b    = gwarp / (Hh / 2);
    int hp   = gwarp % (Hh / 2);
    int h    = hp * 2 + half;

    const float An = -(float)(n + 1);
    const float Dh = Dp[h];
    float state = 0.f;

    int base = b * Ss;
    for (int s = 0; s < Ss; s++) {
        int row = base + s;
        float dv = __ldg(delta + (size_t)row * Hh + h);
        float uv = __ldg(u + (size_t)row * Hh + h);
        float Bn = __ldg(xdbl + row * XD + Rr + n);
        float Cn = __ldg(xdbl + row * XD + Rr + Nn + n);
        float dA = expf(dv * An);
        state = dA * state + dv * Bn * uv;
        float val = state * Cn;
        val += __shfl_xor_sync(0xffffffffu, val, 8);
        val += __shfl_xor_sync(0xffffffffu, val, 4);
        val += __shfl_xor_sync(0xffffffffu, val, 2);
        val += __shfl_xor_sync(0xffffffffu, val, 1);
        float res = __ldg(xr + (size_t)row * H2 + Hh + h);
        float yv  = (val + uv * Dh) * siluf(res);
        float y1  = __shfl_sync(0xffffffffu, yv, 16);
        if (lane == 0) {
            uint32_t lo;
            uint32_t hi = packsplit(yv, y1, lo);
            yh[(size_t)row * K2_H + hp] = hi;
            yl[(size_t)row * K2_H + hp] = lo;
        }
    }
}

// ---------------- x += rmsnorm(mo) * w ; emit x planes ----------------
__global__ void rmsnorm_add_kernel(float* __restrict__ x,
                                   const float* __restrict__ mo,
                                   const float* __restrict__ w,
                                   uint32_t* __restrict__ xph,
                                   uint32_t* __restrict__ xpl) {
    int row = blockIdx.x;
    const float* r = mo + (size_t)row * Mdim;
    float ss = 0.f;
    for (int m = threadIdx.x; m < Mdim; m += blockDim.x) {
        float v = r[m];
        ss += v * v;
    }
    __shared__ float sh[8];
    ss = warp_sum(ss);
    int wid = threadIdx.x >> 5, lane = threadIdx.x & 31;
    if (lane == 0) sh[wid] = ss;
    __syncthreads();
    if (wid == 0) {
        float v = (lane < (int)(blockDim.x >> 5)) ? sh[lane] : 0.f;
        v = warp_sum(v);
        if (lane == 0) sh[0] = v;
    }
    __syncthreads();
    float scale = rsqrtf(sh[0] / (float)Mdim + 1e-15f);
    float* xp = x + (size_t)row * Mdim;
    for (int m2 = threadIdx.x; m2 < K2_M; m2 += blockDim.x) {
        int m = 2 * m2;
        float v0 = xp[m]     + r[m]     * scale * w[m];
        float v1 = xp[m + 1] + r[m + 1] * scale * w[m + 1];
        xp[m] = v0; xp[m + 1] = v1;
        uint32_t lo;
        uint32_t hi = packsplit(v0, v1, lo);
        xph[(size_t)row * K2_M + m2] = hi;
        xpl[(size_t)row * K2_M + m2] = lo;
    }
}

// ---------------- final rmsnorm -> fp16 planes ----------------
__global__ void rmsnorm_final_kernel(const float* __restrict__ x,
                                     const float* __restrict__ w,
                                     uint32_t* __restrict__ xnf) {
    int row = blockIdx.x;
    const float* r = x + (size_t)row * Mdim;
    float ss = 0.f;
    for (int m = threadIdx.x; m < Mdim; m += blockDim.x) {
        float v = r[m];
        ss += v * v;
    }
    __shared__ float sh[8];
    ss = warp_sum(ss);
    int wid = threadIdx.x >> 5, lane = threadIdx.x & 31;
    if (lane == 0) sh[wid] = ss;
    __syncthreads();
    if (wid == 0) {
        float v = (lane < (int)(blockDim.x >> 5)) ? sh[lane] : 0.f;
        v = warp_sum(v);
        if (lane == 0) sh[0] = v;
    }
    __syncthreads();
    float scale = rsqrtf(sh[0] / (float)Mdim + 1e-15f);
    for (int m2 = threadIdx.x; m2 < K2_M; m2 += blockDim.x) {
        int m = 2 * m2;
        xnf[(size_t)row * K2_M + m2] =
            pack_f16(r[m] * scale * w[m], r[m + 1] * scale * w[m + 1]);
    }
}

// ---------------- launch ----------------
extern "C" void kernel_launch(void* const* d_in, const int* in_sizes, int n_in,
                              void* d_out, int out_size) {
    const int*   ids = (const int*)  d_in[0];
    const float* emb = (const float*)d_in[1];
    const float* liw = (const float*)d_in[2];
    const float* lib = (const float*)d_in[3];
    const float* cw  = (const float*)d_in[4];
    const float* cb  = (const float*)d_in[5];
    const float* lxw = (const float*)d_in[6];
    const float* lxb = (const float*)d_in[7];
    const float* ldw = (const float*)d_in[8];
    const float* ldb = (const float*)d_in[9];
    const float* low = (const float*)d_in[10];
    const float* lob = (const float*)d_in[11];
    const float* Dp  = (const float*)d_in[12];
    const float* bnw = (const float*)d_in[13];
    const float* fnw = (const float*)d_in[14];
    const float* hw  = (const float*)d_in[15];
    const float* hb  = (const float*)d_in[16];
    float* out = (float*)d_out;

    float *x, *xr, *u, *xdbl, *delta, *mo;
    cudaGetSymbolAddress((void**)&x,     g_x);
    cudaGetSymbolAddress((void**)&xr,    g_xr);
    cudaGetSymbolAddress((void**)&u,     g_u);
    cudaGetSymbolAddress((void**)&xdbl,  g_xdbl);
    cudaGetSymbolAddress((void**)&delta, g_delta);
    cudaGetSymbolAddress((void**)&mo,    g_mo);

    uint32_t *xp_h, *xp_l, *act_h, *act_l;
    uint32_t *liw_h, *liw_l, *ldw_h, *ldw_l, *low_h, *low_l, *hw_h;
    cudaGetSymbolAddress((void**)&xp_h,  g_xp_h);
    cudaGetSymbolAddress((void**)&xp_l,  g_xp_l);
    cudaGetSymbolAddress((void**)&act_h, g_act_h);
    cudaGetSymbolAddress((void**)&act_l, g_act_l);
    cudaGetSymbolAddress((void**)&liw_h, g_liw_h);
    cudaGetSymbolAddress((void**)&liw_l, g_liw_l);
    cudaGetSymbolAddress((void**)&ldw_h, g_ldw_h);
    cudaGetSymbolAddress((void**)&ldw_l, g_ldw_l);
    cudaGetSymbolAddress((void**)&low_h, g_low_h);
    cudaGetSymbolAddress((void**)&low_l, g_low_l);
    cudaGetSymbolAddress((void**)&hw_h,  g_hw_h);

    const int SM128 = 3 * (256 + 256) * 80;  // 122880
    const int SM64  = 3 * (256 + 128) * 80;  // 92160
    const int SMF   = 3 * (128 + 128) * 80;  // 61440
    cudaFuncSetAttribute((const void*)gemm_bf16x3<128, 0>,
                         cudaFuncAttributeMaxDynamicSharedMemorySize, SM128);
    cudaFuncSetAttribute((const void*)gemm_bf16x3<128, 1>,
                         cudaFuncAttributeMaxDynamicSharedMemorySize, SM128);
    cudaFuncSetAttribute((const void*)gemm_bf16x3<64, 0>,
                         cudaFuncAttributeMaxDynamicSharedMemorySize, SM64);
    cudaFuncSetAttribute((const void*)gemm_fp16,
                         cudaFuncAttributeMaxDynamicSharedMemorySize, SMF);

    // #0: embed
    embed_kernel<<<(BS * K2_M + 255) / 256, 256>>>(ids, emb, x, xp_h, xp_l);

    for (int l = 0; l < Ll; l++) {
        // #1 (l=0): fused per-layer weight split
        split_layer_kernel<<<(SEGT + 255) / 256, 256>>>(
            liw + (size_t)l * H2 * Mdim, ldw + (size_t)l * Hh * Rr,
            low + (size_t)l * Mdim * Hh,
            liw_h + (size_t)l * H2 * K2_M, liw_l + (size_t)l * H2 * K2_M,
            ldw_h + (size_t)l * Hh * K2_DT, ldw_l + (size_t)l * Hh * K2_DT,
            low_h + (size_t)l * Mdim * K2_H, low_l + (size_t)l * Mdim * K2_H);

        // #2 (l=0): head weights -> fp16 planes
        if (l == 0)
            split_hw_f16_kernel<<<(Vv * K2_M + 255) / 256, 256>>>(hw, hw_h);

        // #3 (l=0): lin_in GEMM  <-- absolute launch #5: profiled
        gemm_bf16x3<128, 0><<<dim3(H2 / 128, BS / 128), 256, SM128>>>(
            xp_h, xp_l,
            liw_h + (size_t)l * H2 * K2_M, liw_l + (size_t)l * H2 * K2_M,
            K2_M, lib + (size_t)l * H2, xr, H2);

        conv_silu_kernel<<<(BS * Hh + 255) / 256, 256>>>(
            xr, cw + (size_t)l * Hh * Kk, cb + (size_t)l * Hh, u);

        linx_kernel<<<(BS / 8) * (XD / 4), 256>>>(
            u, lxw + (size_t)l * XD * Hh, lxb + (size_t)l * XD, xdbl);

        split_dt_kernel<<<(BS * K2_DT + 255) / 256, 256>>>(xdbl, act_h, act_l);

        gemm_bf16x3<128, 1><<<dim3(Hh / 128, BS / 128), 256, SM128>>>(
            act_h, act_l,
            ldw_h + (size_t)l * Hh * K2_DT, ldw_l + (size_t)l * Hh * K2_DT,
            K2_DT, ldb + (size_t)l * Hh, delta, Hh);

        scan_gate_kernel<<<(Bb * (Hh / 2) * 32 + 255) / 256, 256>>>(
            delta, u, xdbl, Dp + (size_t)l * Hh, xr, act_h, act_l);

        gemm_bf16x3<64, 0><<<dim3(Mdim / 64, BS / 128), 256, SM64>>>(
            act_h, act_l,
            low_h + (size_t)l * Mdim * K2_H, low_l + (size_t)l * Mdim * K2_H,
            K2_H, lob + (size_t)l * Mdim, mo, Mdim);

        rmsnorm_add_kernel<<<BS, 256>>>(x, mo, bnw + (size_t)l * Mdim, xp_h, xp_l);
    }

    // final rmsnorm -> fp16 planes (reuse act_h)
    rmsnorm_final_kernel<<<BS, 256>>>(x, fnw, act_h);

    // head: fp16 single-pass
    gemm_fp16<<<dim3(Vv / 128, BS / 128), 256, SMF>>>(
        act_h, hw_h, K2_M, hb, out, Vv);
}

// round 9
// speedup vs baseline: 2.9438x; 1.0297x over previous
#include <cuda_runtime.h>
#include <cuda_bf16.h>
#include <cuda_fp16.h>
#include <math.h>
#include <stdint.h>

#define DEV_INLINE __device__ __forceinline__

// Problem constants
constexpr int Mdim = 768;
constexpr int Vv   = 32000;
constexpr int Rr   = 48;
constexpr int Nn   = 16;
constexpr int Kk   = 4;
constexpr int Ll   = 2;
constexpr int Hh   = 1536;
constexpr int Bb   = 2;
constexpr int Ss   = 1024;
constexpr int BS   = Bb * Ss;     // 2048
constexpr int H2   = 2 * Hh;      // 3072
constexpr int XD   = Rr + 2 * Nn; // 80

constexpr int K2_M  = Mdim / 2;   // 384
constexpr int K2_H  = Hh / 2;     // 768
constexpr int K2_DT = 32;         // 48/2=24 -> pad 32

// ---------------- fp32 scratch ----------------
__device__ float g_x    [BS * Mdim];
__device__ float g_xr   [BS * H2];
__device__ float g_u    [BS * Hh];
__device__ float g_xdbl [BS * XD];
__device__ float g_delta[BS * Hh];
__device__ float g_mo   [BS * Mdim];

// ---------------- packed 16-bit planes ----------------
__device__ __align__(16) uint32_t g_xp_h [BS * K2_M];
__device__ __align__(16) uint32_t g_xp_l [BS * K2_M];
__device__ __align__(16) uint32_t g_act_h[BS * K2_H];
__device__ __align__(16) uint32_t g_act_l[BS * K2_H];
__device__ __align__(16) uint32_t g_liw_h[Ll * H2 * K2_M];
__device__ __align__(16) uint32_t g_liw_l[Ll * H2 * K2_M];
__device__ __align__(16) uint32_t g_ldw_h[Ll * Hh * K2_DT];
__device__ __align__(16) uint32_t g_ldw_l[Ll * Hh * K2_DT];
__device__ __align__(16) uint32_t g_low_h[Ll * Mdim * K2_H];
__device__ __align__(16) uint32_t g_low_l[Ll * Mdim * K2_H];
__device__ __align__(16) uint32_t g_hw_h [Vv * K2_M];

// ---------------- helpers ----------------
DEV_INLINE float siluf(float v)     { return v / (1.f + expf(-v)); }
DEV_INLINE float softplusf(float v) { return v > 20.f ? v : log1pf(expf(v)); }

DEV_INLINE float warp_sum(float v) {
    #pragma unroll
    for (int o = 16; o; o >>= 1) v += __shfl_xor_sync(0xffffffffu, v, o);
    return v;
}

DEV_INLINE uint32_t packsplit(float f0, float f1, uint32_t& lo) {
    __nv_bfloat16 h0 = __float2bfloat16(f0);
    __nv_bfloat16 h1 = __float2bfloat16(f1);
    __nv_bfloat16 l0 = __float2bfloat16(f0 - __bfloat162float(h0));
    __nv_bfloat16 l1 = __float2bfloat16(f1 - __bfloat162float(h1));
    lo = (uint32_t)__bfloat16_as_ushort(l0) | ((uint32_t)__bfloat16_as_ushort(l1) << 16);
    return (uint32_t)__bfloat16_as_ushort(h0) | ((uint32_t)__bfloat16_as_ushort(h1) << 16);
}

DEV_INLINE uint32_t pack_f16(float f0, float f1) {
    __half2 h = __floats2half2_rn(f0, f1);
    return *(uint32_t*)&h;
}

DEV_INLINE void mma_bf16(float* d, const uint32_t* a, const uint32_t* b) {
    asm volatile(
        "mma.sync.aligned.m16n8k16.row.col.f32.bf16.bf16.f32 "
        "{%0,%1,%2,%3}, {%4,%5,%6,%7}, {%8,%9}, {%0,%1,%2,%3};"
        : "+f"(d[0]), "+f"(d[1]), "+f"(d[2]), "+f"(d[3])
        : "r"(a[0]), "r"(a[1]), "r"(a[2]), "r"(a[3]),
          "r"(b[0]), "r"(b[1]));
}

DEV_INLINE void mma_f16(float* d, const uint32_t* a, const uint32_t* b) {
    asm volatile(
        "mma.sync.aligned.m16n8k16.row.col.f32.f16.f16.f32 "
        "{%0,%1,%2,%3}, {%4,%5,%6,%7}, {%8,%9}, {%0,%1,%2,%3};"
        : "+f"(d[0]), "+f"(d[1]), "+f"(d[2]), "+f"(d[3])
        : "r"(a[0]), "r"(a[1]), "r"(a[2]), "r"(a[3]),
          "r"(b[0]), "r"(b[1]));
}

DEV_INLINE void ldsm_x4(uint32_t& r0, uint32_t& r1, uint32_t& r2, uint32_t& r3,
                        uint32_t addr) {
    asm volatile("ldmatrix.sync.aligned.m8n8.x4.shared.b16 {%0,%1,%2,%3}, [%4];"
                 : "=r"(r0), "=r"(r1), "=r"(r2), "=r"(r3) : "r"(addr));
}

DEV_INLINE void cp_async16(uint32_t dst, const void* src) {
    asm volatile("cp.async.cg.shared.global [%0], [%1], 16;" :: "r"(dst), "l"(src));
}
DEV_INLINE void cp_commit() { asm volatile("cp.async.commit_group;"); }
template<int N> DEV_INLINE void cp_wait() {
    asm volatile("cp.async.wait_group %0;" :: "n"(N));
}

// ---------------- fused per-layer weight split (liw + ldw + low) ----------
constexpr int SEG0 = H2 * K2_M;
constexpr int SEG1 = Hh * K2_DT;
constexpr int SEG2 = Mdim * K2_H;
constexpr int SEGT = SEG0 + SEG1 + SEG2;

__global__ void split_layer_kernel(const float* __restrict__ liw,
                                   const float* __restrict__ ldw,
                                   const float* __restrict__ low,
                                   uint32_t* __restrict__ liw_h, uint32_t* __restrict__ liw_l,
                                   uint32_t* __restrict__ ldw_h, uint32_t* __restrict__ ldw_l,
                                   uint32_t* __restrict__ low_h, uint32_t* __restrict__ low_l) {
    int idx = blockIdx.x * blockDim.x + threadIdx.x;
    if (idx >= SEGT) return;
    float f0, f1;
    uint32_t *ph, *pl;
    if (idx < SEG0) {
        int k = 2 * (idx % K2_M);
        int r = idx / K2_M;
        f0 = liw[(size_t)r * Mdim + k];
        f1 = liw[(size_t)r * Mdim + k + 1];
        ph = liw_h + idx; pl = liw_l + idx;
    } else if (idx < SEG0 + SEG1) {
        int i = idx - SEG0;
        int j = i % K2_DT, r = i / K2_DT;
        int k = 2 * j;
        f0 = (k     < Rr) ? ldw[(size_t)r * Rr + k]     : 0.f;
        f1 = (k + 1 < Rr) ? ldw[(size_t)r * Rr + k + 1] : 0.f;
        ph = ldw_h + i; pl = ldw_l + i;
    } else {
        int i = idx - SEG0 - SEG1;
        int k = 2 * (i % K2_H);
        int r = i / K2_H;
        f0 = low[(size_t)r * Hh + k];
        f1 = low[(size_t)r * Hh + k + 1];
        ph = low_h + i; pl = low_l + i;
    }
    uint32_t l;
    uint32_t h = packsplit(f0, f1, l);
    *ph = h; *pl = l;
}

// ---------------- fp16 split for head weights ----------------
__global__ void split_hw_f16_kernel(const float* __restrict__ in,
                                    uint32_t* __restrict__ out) {
    int idx = blockIdx.x * blockDim.x + threadIdx.x;
    if (idx >= Vv * K2_M) return;
    int r = idx / K2_M;
    int k = 2 * (idx - r * K2_M);
    out[idx] = pack_f16(in[(size_t)r * Mdim + k], in[(size_t)r * Mdim + k + 1]);
}

// ---------------- xdbl delta-part split (bf16 planes) ----------------
__global__ void split_dt_kernel(const float* __restrict__ xdbl,
                                uint32_t* __restrict__ hi, uint32_t* __restrict__ lo) {
    int idx = blockIdx.x * blockDim.x + threadIdx.x;
    if (idx >= BS * K2_DT) return;
    int r = idx / K2_DT, j = idx - r * K2_DT;
    int k = 2 * j;
    float f0 = (k     < Rr) ? xdbl[(size_t)r * XD + k]     : 0.f;
    float f1 = (k + 1 < Rr) ? xdbl[(size_t)r * XD + k + 1] : 0.f;
    uint32_t l;
    uint32_t h = packsplit(f0, f1, l);
    hi[idx] = h; lo[idx] = l;
}

// ---------------- embedding gather + planes ----------------
__global__ void embed_kernel(const int* __restrict__ ids,
                             const float* __restrict__ emb,
                             float* __restrict__ x,
                             uint32_t* __restrict__ xph,
                             uint32_t* __restrict__ xpl) {
    int idx = blockIdx.x * blockDim.x + threadIdx.x;
    if (idx >= BS * K2_M) return;
    int row = idx / K2_M;
    int m2  = idx - row * K2_M;
    const float* e = emb + (size_t)ids[row] * Mdim + 2 * m2;
    float f0 = e[0], f1 = e[1];
    x[(size_t)row * Mdim + 2 * m2]     = f0;
    x[(size_t)row * Mdim + 2 * m2 + 1] = f1;
    uint32_t l;
    uint32_t h = packsplit(f0, f1, l);
    xph[idx] = h;
    xpl[idx] = l;
}

// ---------------- bf16x3 GEMM, 2-stage double buffer, 2 CTAs/SM ----------
template<int BN, int ACT>
__global__ __launch_bounds__(256, 2)
void gemm_bf16x3(const uint32_t* __restrict__ Ah, const uint32_t* __restrict__ Al,
                 const uint32_t* __restrict__ Wh, const uint32_t* __restrict__ Wl,
                 int K2,
                 const float* __restrict__ bias,
                 float* __restrict__ C, int ldc) {
    constexpr int NTt  = BN / 32;
    constexpr int ROWB = 80;
    constexpr int APB  = 128 * ROWB;
    constexpr int WPB  = BN * ROWB;
    constexpr int STGB = 2 * APB + 2 * WPB;
    constexpr int NCH  = (256 + 2 * BN) * 4 / 256;

    extern __shared__ __align__(16) uint32_t smu[];   // 2 stages

    const int tid  = threadIdx.x;
    const int lane = tid & 31;
    const int wid  = tid >> 5;
    const int wm   = wid >> 2;
    const int wn   = wid & 3;
    const int i0   = blockIdx.y * 128;
    const int j0   = blockIdx.x * BN;
    const int lq   = lane & 3;
    const int lg   = lane >> 2;

    const uint32_t sb = (uint32_t)__cvta_generic_to_shared(smu);

    const uint32_t* src[NCH];
    uint32_t dst[NCH];
    #pragma unroll
    for (int uu = 0; uu < NCH; uu++) {
        int c  = uu * 256 + tid;
        int r2 = c >> 2;
        int q  = c & 3;
        const uint32_t* gbase;
        int pofs, r;
        if (r2 < 128)            { r = r2;            gbase = Ah + (size_t)i0 * K2; pofs = 0; }
        else if (r2 < 256)       { r = r2 - 128;      gbase = Al + (size_t)i0 * K2; pofs = APB; }
        else if (r2 < 256 + BN)  { r = r2 - 256;      gbase = Wh + (size_t)j0 * K2; pofs = 2 * APB; }
        else                     { r = r2 - 256 - BN; gbase = Wl + (size_t)j0 * K2; pofs = 2 * APB + WPB; }
        src[uu] = gbase + (size_t)r * K2 + q * 4;
        dst[uu] = sb + pofs + r * ROWB + q * 16;
    }

    const uint32_t aRow = (uint32_t)((wm * 64 + (lane & 15)) * ROWB + ((lane >> 4) << 4));
    const uint32_t bRow = (uint32_t)((wn * (NTt * 8) + ((lane >> 4) << 3) + (lane & 7)) * ROWB
                                     + (((lane >> 3) & 1) << 4));

    float acc[4][NTt][4];
    #pragma unroll
    for (int m = 0; m < 4; m++)
        #pragma unroll
        for (int n = 0; n < NTt; n++)
            #pragma unroll
            for (int c = 0; c < 4; c++) acc[m][n][c] = 0.f;

    const int nk = K2 >> 4;

    // prefetch stage 0
    #pragma unroll
    for (int uu = 0; uu < NCH; uu++) cp_async16(dst[uu], src[uu]);
    cp_commit();

    for (int t = 0; t < nk; t++) {
        cp_wait<0>();
        __syncthreads();
        // prefetch t+1 into the other buffer (all warps past compute of t-1)
        if (t + 1 < nk) {
            uint32_t so = (uint32_t)((t + 1) & 1) * STGB;
            int ko = (t + 1) * 16;
            #pragma unroll
            for (int uu = 0; uu < NCH; uu++)
                cp_async16(dst[uu] + so, src[uu] + ko);
            cp_commit();
        }

        const uint32_t st = sb + (uint32_t)(t & 1) * STGB;

        #pragma unroll
        for (int h = 0; h < 2; h++) {
            uint32_t ah[4][4], al[4][4], bh[NTt][2], bl[NTt][2];
            #pragma unroll
            for (int m = 0; m < 4; m++) {
                uint32_t a0 = st + aRow + m * (16 * ROWB) + h * 32;
                ldsm_x4(ah[m][0], ah[m][1], ah[m][2], ah[m][3], a0);
                ldsm_x4(al[m][0], al[m][1], al[m][2], al[m][3], a0 + APB);
            }
            #pragma unroll
            for (int j = 0; j < NTt / 2; j++) {
                uint32_t b0 = st + 2 * APB + bRow + j * (16 * ROWB) + h * 32;
                ldsm_x4(bh[2*j][0], bh[2*j][1], bh[2*j+1][0], bh[2*j+1][1], b0);
                ldsm_x4(bl[2*j][0], bl[2*j][1], bl[2*j+1][0], bl[2*j+1][1], b0 + WPB);
            }
            #pragma unroll
            for (int m = 0; m < 4; m++)
                #pragma unroll
                for (int n = 0; n < NTt; n++)
                    mma_bf16(acc[m][n], ah[m], bh[n]);
            #pragma unroll
            for (int m = 0; m < 4; m++)
                #pragma unroll
                for (int n = 0; n < NTt; n++)
                    mma_bf16(acc[m][n], ah[m], bl[n]);
            #pragma unroll
            for (int m = 0; m < 4; m++)
                #pragma unroll
                for (int n = 0; n < NTt; n++)
                    mma_bf16(acc[m][n], al[m], bh[n]);
        }
        __syncthreads();
    }

    #pragma unroll
    for (int m = 0; m < 4; m++) {
        int gi = i0 + wm * 64 + m * 16 + lg;
        #pragma unroll
        for (int n = 0; n < NTt; n++) {
            int gj = j0 + wn * (NTt * 8) + n * 8 + 2 * lq;
            float b0 = bias[gj], b1 = bias[gj + 1];
            float v0 = acc[m][n][0] + b0;
            float v1 = acc[m][n][1] + b1;
            float v2 = acc[m][n][2] + b0;
            float v3 = acc[m][n][3] + b1;
            if (ACT == 1) {
                v0 = softplusf(v0); v1 = softplusf(v1);
                v2 = softplusf(v2); v3 = softplusf(v3);
            }
            *(float2*)(C + (size_t)gi * ldc + gj)       = make_float2(v0, v1);
            *(float2*)(C + (size_t)(gi + 8) * ldc + gj) = make_float2(v2, v3);
        }
    }
}

// ---------------- fp16 single-pass GEMM (head), 3-stage, 2 CTAs/SM --------
__global__ __launch_bounds__(256, 2)
void gemm_fp16(const uint32_t* __restrict__ Ah, const uint32_t* __restrict__ Wh,
               int K2,
               const float* __restrict__ bias,
               float* __restrict__ C, int ldc) {
    constexpr int BN   = 128;
    constexpr int ROWB = 80;
    constexpr int APB  = 128 * ROWB;
    constexpr int STGB = 2 * APB;
    constexpr int NCH  = 4;

    extern __shared__ __align__(16) uint32_t smu[];

    const int tid  = threadIdx.x;
    const int lane = tid & 31;
    const int wid  = tid >> 5;
    const int wm   = wid >> 2;
    const int wn   = wid & 3;
    const int i0   = blockIdx.y * 128;
    const int j0   = blockIdx.x * BN;
    const int lq   = lane & 3;
    const int lg   = lane >> 2;

    const uint32_t sb = (uint32_t)__cvta_generic_to_shared(smu);

    const uint32_t* src[NCH];
    uint32_t dst[NCH];
    #pragma unroll
    for (int uu = 0; uu < NCH; uu++) {
        int c  = uu * 256 + tid;
        int r2 = c >> 2;
        int q  = c & 3;
        const uint32_t* gbase;
        int pofs, r;
        if (r2 < 128) { r = r2;       gbase = Ah + (size_t)i0 * K2; pofs = 0; }
        else          { r = r2 - 128; gbase = Wh + (size_t)j0 * K2; pofs = APB; }
        src[uu] = gbase + (size_t)r * K2 + q * 4;
        dst[uu] = sb + pofs + r * ROWB + q * 16;
    }

    const uint32_t aRow = (uint32_t)((wm * 64 + (lane & 15)) * ROWB + ((lane >> 4) << 4));
    const uint32_t bRow = (uint32_t)((wn * 32 + ((lane >> 4) << 3) + (lane & 7)) * ROWB
                                     + (((lane >> 3) & 1) << 4));

    float acc[4][4][4];
    #pragma unroll
    for (int m = 0; m < 4; m++)
        #pragma unroll
        for (int n = 0; n < 4; n++)
            #pragma unroll
            for (int c = 0; c < 4; c++) acc[m][n][c] = 0.f;

    const int nk = K2 >> 4;

    #pragma unroll
    for (int uu = 0; uu < NCH; uu++) cp_async16(dst[uu], src[uu]);
    cp_commit();
    #pragma unroll
    for (int uu = 0; uu < NCH; uu++) cp_async16(dst[uu] + STGB, src[uu] + 16);
    cp_commit();

    for (int t = 0; t < nk; t++) {
        if (t + 1 < nk) { cp_wait<1>(); } else { cp_wait<0>(); }
        __syncthreads();
        if (t + 2 < nk) {
            uint32_t so = (uint32_t)((t + 2) % 3) * STGB;
            int ko = (t + 2) * 16;
            #pragma unroll
            for (int uu = 0; uu < NCH; uu++)
                cp_async16(dst[uu] + so, src[uu] + ko);
            cp_commit();
        }

        const uint32_t st = sb + (uint32_t)(t % 3) * STGB;

        #pragma unroll
        for (int h = 0; h < 2; h++) {
            uint32_t ah[4][4], bh[4][2];
            #pragma unroll
            for (int m = 0; m < 4; m++) {
                uint32_t a0 = st + aRow + m * (16 * ROWB) + h * 32;
                ldsm_x4(ah[m][0], ah[m][1], ah[m][2], ah[m][3], a0);
            }
            #pragma unroll
            for (int j = 0; j < 2; j++) {
                uint32_t b0 = st + APB + bRow + j * (16 * ROWB) + h * 32;
                ldsm_x4(bh[2*j][0], bh[2*j][1], bh[2*j+1][0], bh[2*j+1][1], b0);
            }
            #pragma unroll
            for (int m = 0; m < 4; m++)
                #pragma unroll
                for (int n = 0; n < 4; n++)
                    mma_f16(acc[m][n], ah[m], bh[n]);
        }
    }

    #pragma unroll
    for (int m = 0; m < 4; m++) {
        int gi = i0 + wm * 64 + m * 16 + lg;
        #pragma unroll
        for (int n = 0; n < 4; n++) {
            int gj = j0 + wn * 32 + n * 8 + 2 * lq;
            float b0 = bias[gj], b1 = bias[gj + 1];
            *(float2*)(C + (size_t)gi * ldc + gj) =
                make_float2(acc[m][n][0] + b0, acc[m][n][1] + b1);
            *(float2*)(C + (size_t)(gi + 8) * ldc + gj) =
                make_float2(acc[m][n][2] + b0, acc[m][n][3] + b1);
        }
    }
}

// ---------------- lin_x: [BS,1536] x [80,1536]^T, warp-reduction ----------
__global__ __launch_bounds__(256)
void linx_kernel(const float* __restrict__ u,
                 const float* __restrict__ w,
                 const float* __restrict__ bias,
                 float* __restrict__ xdbl) {
    int ig = blockIdx.x / 20;
    int jc = blockIdx.x % 20;
    int wid  = threadIdx.x >> 5;
    int lane = threadIdx.x & 31;
    int i  = ig * 8 + wid;
    int j0 = jc * 4;

    const float4* u4 = (const float4*)(u + (size_t)i * Hh);
    const float4* w0 = (const float4*)(w + (size_t)(j0 + 0) * Hh);
    const float4* w1 = (const float4*)(w + (size_t)(j0 + 1) * Hh);
    const float4* w2 = (const float4*)(w + (size_t)(j0 + 2) * Hh);
    const float4* w3 = (const float4*)(w + (size_t)(j0 + 3) * Hh);

    float p0 = 0.f, p1 = 0.f, p2 = 0.f, p3 = 0.f;
    #pragma unroll
    for (int t = 0; t < Hh / 128; t++) {
        int k = t * 32 + lane;
        float4 uv = u4[k];
        float4 a  = w0[k];
        p0 += uv.x * a.x + uv.y * a.y + uv.z * a.z + uv.w * a.w;
        a = w1[k];
        p1 += uv.x * a.x + uv.y * a.y + uv.z * a.z + uv.w * a.w;
        a = w2[k];
        p2 += uv.x * a.x + uv.y * a.y + uv.z * a.z + uv.w * a.w;
        a = w3[k];
        p3 += uv.x * a.x + uv.y * a.y + uv.z * a.z + uv.w * a.w;
    }
    p0 = warp_sum(p0); p1 = warp_sum(p1);
    p2 = warp_sum(p2); p3 = warp_sum(p3);
    if (lane == 0) {
        float* o = xdbl + (size_t)i * XD + j0;
        o[0] = p0 + bias[j0];
        o[1] = p1 + bias[j0 + 1];
        o[2] = p2 + bias[j0 + 2];
        o[3] = p3 + bias[j0 + 3];
    }
}

// ---------------- depthwise causal conv (K=4) + silu ----------------
__global__ void conv_silu_kernel(const float* __restrict__ xr,
                                 const float* __restrict__ cw,
                                 const float* __restrict__ cb,
                                 float* __restrict__ u) {
    int idx = blockIdx.x * blockDim.x + threadIdx.x;
    if (idx >= BS * Hh) return;
    int h   = idx % Hh;
    int row = idx / Hh;
    int s   = row % Ss;
    int b   = row / Ss;
    float acc = cb[h];
    #pragma unroll
    for (int k = 0; k < Kk; k++) {
        int sp = s - (Kk - 1) + k;
        if (sp >= 0)
            acc += cw[h * Kk + k] * xr[(size_t)(b * Ss + sp) * H2 + h];
    }
    u[idx] = siluf(acc);
}

// ---------------- selective scan + gate + plane split fused ---------------
__global__ void scan_gate_kernel(const float* __restrict__ delta,
                                 const float* __restrict__ u,
                                 const float* __restrict__ xdbl,
                                 const float* __restrict__ Dp,
                                 const float* __restrict__ xr,
                                 uint32_t* __restrict__ yh,
                                 uint32_t* __restrict__ yl) {
    int gwarp = (blockIdx.x * blockDim.x + threadIdx.x) >> 5;
    if (gwarp >= Bb * (Hh / 2)) return;
    int lane = threadIdx.x & 31;
    int half = lane >> 4;
    int n    = lane & 15;
    int b    = gwarp / (Hh / 2);
    int hp   = gwarp % (Hh / 2);
    int h    = hp * 2 + half;

    const float An = -(float)(n + 1);
    const float Dh = Dp[h];
    float state = 0.f;

    int base = b * Ss;
    for (int s = 0; s < Ss; s++) {
        int row = base + s;
        float dv = __ldg(delta + (size_t)row * Hh + h);
        float uv = __ldg(u + (size_t)row * Hh + h);
        float Bn = __ldg(xdbl + row * XD + Rr + n);
        float Cn = __ldg(xdbl + row * XD + Rr + Nn + n);
        float dA = expf(dv * An);
        state = dA * state + dv * Bn * uv;
        float val = state * Cn;
        val += __shfl_xor_sync(0xffffffffu, val, 8);
        val += __shfl_xor_sync(0xffffffffu, val, 4);
        val += __shfl_xor_sync(0xffffffffu, val, 2);
        val += __shfl_xor_sync(0xffffffffu, val, 1);
        float res = __ldg(xr + (size_t)row * H2 + Hh + h);
        float yv  = (val + uv * Dh) * siluf(res);
        float y1  = __shfl_sync(0xffffffffu, yv, 16);
        if (lane == 0) {
            uint32_t lo;
            uint32_t hi = packsplit(yv, y1, lo);
            yh[(size_t)row * K2_H + hp] = hi;
            yl[(size_t)row * K2_H + hp] = lo;
        }
    }
}

// ---------------- x += rmsnorm(mo) * w ; emit x planes ----------------
__global__ void rmsnorm_add_kernel(float* __restrict__ x,
                                   const float* __restrict__ mo,
                                   const float* __restrict__ w,
                                   uint32_t* __restrict__ xph,
                                   uint32_t* __restrict__ xpl) {
    int row = blockIdx.x;
    const float* r = mo + (size_t)row * Mdim;
    float ss = 0.f;
    for (int m = threadIdx.x; m < Mdim; m += blockDim.x) {
        float v = r[m];
        ss += v * v;
    }
    __shared__ float sh[8];
    ss = warp_sum(ss);
    int wid = threadIdx.x >> 5, lane = threadIdx.x & 31;
    if (lane == 0) sh[wid] = ss;
    __syncthreads();
    if (wid == 0) {
        float v = (lane < (int)(blockDim.x >> 5)) ? sh[lane] : 0.f;
        v = warp_sum(v);
        if (lane == 0) sh[0] = v;
    }
    __syncthreads();
    float scale = rsqrtf(sh[0] / (float)Mdim + 1e-15f);
    float* xp = x + (size_t)row * Mdim;
    for (int m2 = threadIdx.x; m2 < K2_M; m2 += blockDim.x) {
        int m = 2 * m2;
        float v0 = xp[m]     + r[m]     * scale * w[m];
        float v1 = xp[m + 1] + r[m + 1] * scale * w[m + 1];
        xp[m] = v0; xp[m + 1] = v1;
        uint32_t lo;
        uint32_t hi = packsplit(v0, v1, lo);
        xph[(size_t)row * K2_M + m2] = hi;
        xpl[(size_t)row * K2_M + m2] = lo;
    }
}

// ---------------- final rmsnorm -> fp16 planes ----------------
__global__ void rmsnorm_final_kernel(const float* __restrict__ x,
                                     const float* __restrict__ w,
                                     uint32_t* __restrict__ xnf) {
    int row = blockIdx.x;
    const float* r = x + (size_t)row * Mdim;
    float ss = 0.f;
    for (int m = threadIdx.x; m < Mdim; m += blockDim.x) {
        float v = r[m];
        ss += v * v;
    }
    __shared__ float sh[8];
    ss = warp_sum(ss);
    int wid = threadIdx.x >> 5, lane = threadIdx.x & 31;
    if (lane == 0) sh[wid] = ss;
    __syncthreads();
    if (wid == 0) {
        float v = (lane < (int)(blockDim.x >> 5)) ? sh[lane] : 0.f;
        v = warp_sum(v);
        if (lane == 0) sh[0] = v;
    }
    __syncthreads();
    float scale = rsqrtf(sh[0] / (float)Mdim + 1e-15f);
    for (int m2 = threadIdx.x; m2 < K2_M; m2 += blockDim.x) {
        int m = 2 * m2;
        xnf[(size_t)row * K2_M + m2] =
            pack_f16(r[m] * scale * w[m], r[m + 1] * scale * w[m + 1]);
    }
}

// ---------------- launch ----------------
extern "C" void kernel_launch(void* const* d_in, const int* in_sizes, int n_in,
                              void* d_out, int out_size) {
    const int*   ids = (const int*)  d_in[0];
    const float* emb = (const float*)d_in[1];
    const float* liw = (const float*)d_in[2];
    const float* lib = (const float*)d_in[3];
    const float* cw  = (const float*)d_in[4];
    const float* cb  = (const float*)d_in[5];
    const float* lxw = (const float*)d_in[6];
    const float* lxb = (const float*)d_in[7];
    const float* ldw = (const float*)d_in[8];
    const float* ldb = (const float*)d_in[9];
    const float* low = (const float*)d_in[10];
    const float* lob = (const float*)d_in[11];
    const float* Dp  = (const float*)d_in[12];
    const float* bnw = (const float*)d_in[13];
    const float* fnw = (const float*)d_in[14];
    const float* hw  = (const float*)d_in[15];
    const float* hb  = (const float*)d_in[16];
    float* out = (float*)d_out;

    float *x, *xr, *u, *xdbl, *delta, *mo;
    cudaGetSymbolAddress((void**)&x,     g_x);
    cudaGetSymbolAddress((void**)&xr,    g_xr);
    cudaGetSymbolAddress((void**)&u,     g_u);
    cudaGetSymbolAddress((void**)&xdbl,  g_xdbl);
    cudaGetSymbolAddress((void**)&delta, g_delta);
    cudaGetSymbolAddress((void**)&mo,    g_mo);

    uint32_t *xp_h, *xp_l, *act_h, *act_l;
    uint32_t *liw_h, *liw_l, *ldw_h, *ldw_l, *low_h, *low_l, *hw_h;
    cudaGetSymbolAddress((void**)&xp_h,  g_xp_h);
    cudaGetSymbolAddress((void**)&xp_l,  g_xp_l);
    cudaGetSymbolAddress((void**)&act_h, g_act_h);
    cudaGetSymbolAddress((void**)&act_l, g_act_l);
    cudaGetSymbolAddress((void**)&liw_h, g_liw_h);
    cudaGetSymbolAddress((void**)&liw_l, g_liw_l);
    cudaGetSymbolAddress((void**)&ldw_h, g_ldw_h);
    cudaGetSymbolAddress((void**)&ldw_l, g_ldw_l);
    cudaGetSymbolAddress((void**)&low_h, g_low_h);
    cudaGetSymbolAddress((void**)&low_l, g_low_l);
    cudaGetSymbolAddress((void**)&hw_h,  g_hw_h);

    // 2-stage smem for bf16x3, 3-stage for fp16 head
    const int SM128 = 2 * (2 * 128 * 80 + 2 * 128 * 80);  // 81920
    const int SM64  = 2 * (2 * 128 * 80 + 2 * 64 * 80);   // 61440
    const int SMF   = 3 * (2 * 128 * 80);                 // 61440
    cudaFuncSetAttribute((const void*)gemm_bf16x3<128, 0>,
                         cudaFuncAttributeMaxDynamicSharedMemorySize, SM128);
    cudaFuncSetAttribute((const void*)gemm_bf16x3<128, 1>,
                         cudaFuncAttributeMaxDynamicSharedMemorySize, SM128);
    cudaFuncSetAttribute((const void*)gemm_bf16x3<64, 0>,
                         cudaFuncAttributeMaxDynamicSharedMemorySize, SM64);
    cudaFuncSetAttribute((const void*)gemm_fp16,
                         cudaFuncAttributeMaxDynamicSharedMemorySize, SMF);

    // #0: embed
    embed_kernel<<<(BS * K2_M + 255) / 256, 256>>>(ids, emb, x, xp_h, xp_l);

    for (int l = 0; l < Ll; l++) {
        // #1 (l=0): fused per-layer weight split
        split_layer_kernel<<<(SEGT + 255) / 256, 256>>>(
            liw + (size_t)l * H2 * Mdim, ldw + (size_t)l * Hh * Rr,
            low + (size_t)l * Mdim * Hh,
            liw_h + (size_t)l * H2 * K2_M, liw_l + (size_t)l * H2 * K2_M,
            ldw_h + (size_t)l * Hh * K2_DT, ldw_l + (size_t)l * Hh * K2_DT,
            low_h + (size_t)l * Mdim * K2_H, low_l + (size_t)l * Mdim * K2_H);

        // #2 (l=0): head weights -> fp16 planes
        if (l == 0)
            split_hw_f16_kernel<<<(Vv * K2_M + 255) / 256, 256>>>(hw, hw_h);

        // #3 (l=0): lin_in GEMM (absolute launch #5: profiled)
        gemm_bf16x3<128, 0><<<dim3(H2 / 128, BS / 128), 256, SM128>>>(
            xp_h, xp_l,
            liw_h + (size_t)l * H2 * K2_M, liw_l + (size_t)l * H2 * K2_M,
            K2_M, lib + (size_t)l * H2, xr, H2);

        conv_silu_kernel<<<(BS * Hh + 255) / 256, 256>>>(
            xr, cw + (size_t)l * Hh * Kk, cb + (size_t)l * Hh, u);

        linx_kernel<<<(BS / 8) * (XD / 4), 256>>>(
            u, lxw + (size_t)l * XD * Hh, lxb + (size_t)l * XD, xdbl);

        split_dt_kernel<<<(BS * K2_DT + 255) / 256, 256>>>(xdbl, act_h, act_l);

        gemm_bf16x3<128, 1><<<dim3(Hh / 128, BS / 128), 256, SM128>>>(
            act_h, act_l,
            ldw_h + (size_t)l * Hh * K2_DT, ldw_l + (size_t)l * Hh * K2_DT,
            K2_DT, ldb + (size_t)l * Hh, delta, Hh);

        scan_gate_kernel<<<(Bb * (Hh / 2) * 32 + 255) / 256, 256>>>(
            delta, u, xdbl, Dp + (size_t)l * Hh, xr, act_h, act_l);

        gemm_bf16x3<64, 0><<<dim3(Mdim / 64, BS / 128), 256, SM64>>>(
            act_h, act_l,
            low_h + (size_t)l * Mdim * K2_H, low_l + (size_t)l * Mdim * K2_H,
            K2_H, lob + (size_t)l * Mdim, mo, Mdim);

        rmsnorm_add_kernel<<<BS, 256>>>(x, mo, bnw + (size_t)l * Mdim, xp_h, xp_l);
    }

    // final rmsnorm -> fp16 planes (reuse act_h)
    rmsnorm_final_kernel<<<BS, 256>>>(x, fnw, act_h);

    // head: fp16 single-pass
    gemm_fp16<<<dim3(Vv / 128, BS / 128), 256, SMF>>>(
        act_h, hw_h, K2_M, hb, out, Vv);
}

// round 11
// speedup vs baseline: 2.9618x; 1.0061x over previous
#include <cuda_runtime.h>
#include <cuda_bf16.h>
#include <cuda_fp16.h>
#include <math.h>
#include <stdint.h>

#define DEV_INLINE __device__ __forceinline__

// Problem constants
constexpr int Mdim = 768;
constexpr int Vv   = 32000;
constexpr int Rr   = 48;
constexpr int Nn   = 16;
constexpr int Kk   = 4;
constexpr int Ll   = 2;
constexpr int Hh   = 1536;
constexpr int Bb   = 2;
constexpr int Ss   = 1024;
constexpr int BS   = Bb * Ss;     // 2048
constexpr int H2   = 2 * Hh;      // 3072
constexpr int XD   = Rr + 2 * Nn; // 80

constexpr int K2_M  = Mdim / 2;   // 384
constexpr int K2_H  = Hh / 2;     // 768
constexpr int K2_DT = 32;         // 48/2=24 -> pad 32

// ---------------- fp32 scratch ----------------
__device__ float g_x    [BS * Mdim];
__device__ float g_xr   [BS * H2];
__device__ float g_u    [BS * Hh];
__device__ float g_xdbl [BS * XD];
__device__ float g_delta[BS * Hh];
__device__ float g_mo   [BS * Mdim];

// ---------------- packed 16-bit planes ----------------
__device__ __align__(16) uint32_t g_xp_h [BS * K2_M];
__device__ __align__(16) uint32_t g_xp_l [BS * K2_M];
__device__ __align__(16) uint32_t g_act_h[BS * K2_H];   // dt/y planes hi, fp16 xn
__device__ __align__(16) uint32_t g_act_l[BS * K2_H];   // dt/y planes lo
__device__ __align__(16) uint32_t g_liw_h[Ll * H2 * K2_M];
__device__ __align__(16) uint32_t g_liw_l[Ll * H2 * K2_M];
__device__ __align__(16) uint32_t g_ldw_h[Ll * Hh * K2_DT];
__device__ __align__(16) uint32_t g_ldw_l[Ll * Hh * K2_DT];
__device__ __align__(16) uint32_t g_low_h[Ll * Mdim * K2_H];   // bf16 hi
__device__ __align__(16) uint32_t g_low_l[Ll * Mdim * K2_H];   // bf16 lo
__device__ __align__(16) uint32_t g_hw_h [Vv * K2_M];          // fp16 single (head only)

// ---------------- helpers ----------------
DEV_INLINE float siluf(float v)     { return v / (1.f + expf(-v)); }
DEV_INLINE float softplusf(float v) { return v > 20.f ? v : log1pf(expf(v)); }

DEV_INLINE float warp_sum(float v) {
    #pragma unroll
    for (int o = 16; o; o >>= 1) v += __shfl_xor_sync(0xffffffffu, v, o);
    return v;
}

DEV_INLINE uint32_t packsplit(float f0, float f1, uint32_t& lo) {
    __nv_bfloat16 h0 = __float2bfloat16(f0);
    __nv_bfloat16 h1 = __float2bfloat16(f1);
    __nv_bfloat16 l0 = __float2bfloat16(f0 - __bfloat162float(h0));
    __nv_bfloat16 l1 = __float2bfloat16(f1 - __bfloat162float(h1));
    lo = (uint32_t)__bfloat16_as_ushort(l0) | ((uint32_t)__bfloat16_as_ushort(l1) << 16);
    return (uint32_t)__bfloat16_as_ushort(h0) | ((uint32_t)__bfloat16_as_ushort(h1) << 16);
}

DEV_INLINE uint32_t pack_f16(float f0, float f1) {
    __half2 h = __floats2half2_rn(f0, f1);
    return *(uint32_t*)&h;
}

DEV_INLINE void mma_bf16(float* d, const uint32_t* a, const uint32_t* b) {
    asm volatile(
        "mma.sync.aligned.m16n8k16.row.col.f32.bf16.bf16.f32 "
        "{%0,%1,%2,%3}, {%4,%5,%6,%7}, {%8,%9}, {%0,%1,%2,%3};"
        : "+f"(d[0]), "+f"(d[1]), "+f"(d[2]), "+f"(d[3])
        : "r"(a[0]), "r"(a[1]), "r"(a[2]), "r"(a[3]),
          "r"(b[0]), "r"(b[1]));
}

DEV_INLINE void mma_f16(float* d, const uint32_t* a, const uint32_t* b) {
    asm volatile(
        "mma.sync.aligned.m16n8k16.row.col.f32.f16.f16.f32 "
        "{%0,%1,%2,%3}, {%4,%5,%6,%7}, {%8,%9}, {%0,%1,%2,%3};"
        : "+f"(d[0]), "+f"(d[1]), "+f"(d[2]), "+f"(d[3])
        : "r"(a[0]), "r"(a[1]), "r"(a[2]), "r"(a[3]),
          "r"(b[0]), "r"(b[1]));
}

DEV_INLINE void ldsm_x4(uint32_t& r0, uint32_t& r1, uint32_t& r2, uint32_t& r3,
                        uint32_t addr) {
    asm volatile("ldmatrix.sync.aligned.m8n8.x4.shared.b16 {%0,%1,%2,%3}, [%4];"
                 : "=r"(r0), "=r"(r1), "=r"(r2), "=r"(r3) : "r"(addr));
}

DEV_INLINE void cp_async16(uint32_t dst, const void* src) {
    asm volatile("cp.async.cg.shared.global [%0], [%1], 16;" :: "r"(dst), "l"(src));
}
DEV_INLINE void cp_commit() { asm volatile("cp.async.commit_group;"); }
template<int N> DEV_INLINE void cp_wait() {
    asm volatile("cp.async.wait_group %0;" :: "n"(N));
}

// ---------------- fused per-layer weight split (all bf16 hi/lo) ----------
constexpr int SEG0 = H2 * K2_M;
constexpr int SEG1 = Hh * K2_DT;
constexpr int SEG2 = Mdim * K2_H;
constexpr int SEGT = SEG0 + SEG1 + SEG2;

__global__ void split_layer_kernel(const float* __restrict__ liw,
                                   const float* __restrict__ ldw,
                                   const float* __restrict__ low,
                                   uint32_t* __restrict__ liw_h, uint32_t* __restrict__ liw_l,
                                   uint32_t* __restrict__ ldw_h, uint32_t* __restrict__ ldw_l,
                                   uint32_t* __restrict__ low_h, uint32_t* __restrict__ low_l) {
    int idx = blockIdx.x * blockDim.x + threadIdx.x;
    if (idx >= SEGT) return;
    float f0, f1;
    uint32_t *ph, *pl;
    if (idx < SEG0) {
        int k = 2 * (idx % K2_M);
        int r = idx / K2_M;
        f0 = liw[(size_t)r * Mdim + k];
        f1 = liw[(size_t)r * Mdim + k + 1];
        ph = liw_h + idx; pl = liw_l + idx;
    } else if (idx < SEG0 + SEG1) {
        int i = idx - SEG0;
        int j = i % K2_DT, r = i / K2_DT;
        int k = 2 * j;
        f0 = (k     < Rr) ? ldw[(size_t)r * Rr + k]     : 0.f;
        f1 = (k + 1 < Rr) ? ldw[(size_t)r * Rr + k + 1] : 0.f;
        ph = ldw_h + i; pl = ldw_l + i;
    } else {
        int i = idx - SEG0 - SEG1;
        int k = 2 * (i % K2_H);
        int r = i / K2_H;
        f0 = low[(size_t)r * Hh + k];
        f1 = low[(size_t)r * Hh + k + 1];
        ph = low_h + i; pl = low_l + i;
    }
    uint32_t l;
    uint32_t h = packsplit(f0, f1, l);
    *ph = h; *pl = l;
}

// ---------------- fp16 split for head weights ----------------
__global__ void split_hw_f16_kernel(const float* __restrict__ in,
                                    uint32_t* __restrict__ out) {
    int idx = blockIdx.x * blockDim.x + threadIdx.x;
    if (idx >= Vv * K2_M) return;
    int r = idx / K2_M;
    int k = 2 * (idx - r * K2_M);
    out[idx] = pack_f16(in[(size_t)r * Mdim + k], in[(size_t)r * Mdim + k + 1]);
}

// ---------------- embedding gather + planes ----------------
__global__ void embed_kernel(const int* __restrict__ ids,
                             const float* __restrict__ emb,
                             float* __restrict__ x,
                             uint32_t* __restrict__ xph,
                             uint32_t* __restrict__ xpl) {
    int idx = blockIdx.x * blockDim.x + threadIdx.x;
    if (idx >= BS * K2_M) return;
    int row = idx / K2_M;
    int m2  = idx - row * K2_M;
    const float* e = emb + (size_t)ids[row] * Mdim + 2 * m2;
    float f0 = e[0], f1 = e[1];
    x[(size_t)row * Mdim + 2 * m2]     = f0;
    x[(size_t)row * Mdim + 2 * m2 + 1] = f1;
    uint32_t l;
    uint32_t h = packsplit(f0, f1, l);
    xph[idx] = h;
    xpl[idx] = l;
}

// ---------------- bf16x3 GEMM, 2-stage double buffer, 2 CTAs/SM ----------
template<int BN, int ACT>
__global__ __launch_bounds__(256, 2)
void gemm_bf16x3(const uint32_t* __restrict__ Ah, const uint32_t* __restrict__ Al,
                 const uint32_t* __restrict__ Wh, const uint32_t* __restrict__ Wl,
                 int K2,
                 const float* __restrict__ bias,
                 float* __restrict__ C, int ldc) {
    constexpr int NTt  = BN / 32;
    constexpr int ROWB = 80;
    constexpr int APB  = 128 * ROWB;
    constexpr int WPB  = BN * ROWB;
    constexpr int STGB = 2 * APB + 2 * WPB;
    constexpr int NCH  = (256 + 2 * BN) * 4 / 256;

    extern __shared__ __align__(16) uint32_t smu[];

    const int tid  = threadIdx.x;
    const int lane = tid & 31;
    const int wid  = tid >> 5;
    const int wm   = wid >> 2;
    const int wn   = wid & 3;
    const int i0   = blockIdx.y * 128;
    const int j0   = blockIdx.x * BN;
    const int lq   = lane & 3;
    const int lg   = lane >> 2;

    const uint32_t sb = (uint32_t)__cvta_generic_to_shared(smu);

    const uint32_t* src[NCH];
    uint32_t dst[NCH];
    #pragma unroll
    for (int uu = 0; uu < NCH; uu++) {
        int c  = uu * 256 + tid;
        int r2 = c >> 2;
        int q  = c & 3;
        const uint32_t* gbase;
        int pofs, r;
        if (r2 < 128)            { r = r2;            gbase = Ah + (size_t)i0 * K2; pofs = 0; }
        else if (r2 < 256)       { r = r2 - 128;      gbase = Al + (size_t)i0 * K2; pofs = APB; }
        else if (r2 < 256 + BN)  { r = r2 - 256;      gbase = Wh + (size_t)j0 * K2; pofs = 2 * APB; }
        else                     { r = r2 - 256 - BN; gbase = Wl + (size_t)j0 * K2; pofs = 2 * APB + WPB; }
        src[uu] = gbase + (size_t)r * K2 + q * 4;
        dst[uu] = sb + pofs + r * ROWB + q * 16;
    }

    const uint32_t aRow = (uint32_t)((wm * 64 + (lane & 15)) * ROWB + ((lane >> 4) << 4));
    const uint32_t bRow = (uint32_t)((wn * (NTt * 8) + ((lane >> 4) << 3) + (lane & 7)) * ROWB
                                     + (((lane >> 3) & 1) << 4));

    float acc[4][NTt][4];
    #pragma unroll
    for (int m = 0; m < 4; m++)
        #pragma unroll
        for (int n = 0; n < NTt; n++)
            #pragma unroll
            for (int c = 0; c < 4; c++) acc[m][n][c] = 0.f;

    const int nk = K2 >> 4;

    #pragma unroll
    for (int uu = 0; uu < NCH; uu++) cp_async16(dst[uu], src[uu]);
    cp_commit();

    for (int t = 0; t < nk; t++) {
        cp_wait<0>();
        __syncthreads();
        if (t + 1 < nk) {
            uint32_t so = (uint32_t)((t + 1) & 1) * STGB;
            int ko = (t + 1) * 16;
            #pragma unroll
            for (int uu = 0; uu < NCH; uu++)
                cp_async16(dst[uu] + so, src[uu] + ko);
            cp_commit();
        }

        const uint32_t st = sb + (uint32_t)(t & 1) * STGB;

        #pragma unroll
        for (int h = 0; h < 2; h++) {
            uint32_t ah[4][4], al[4][4], bh[NTt][2], bl[NTt][2];
            #pragma unroll
            for (int m = 0; m < 4; m++) {
                uint32_t a0 = st + aRow + m * (16 * ROWB) + h * 32;
                ldsm_x4(ah[m][0], ah[m][1], ah[m][2], ah[m][3], a0);
                ldsm_x4(al[m][0], al[m][1], al[m][2], al[m][3], a0 + APB);
            }
            #pragma unroll
            for (int j = 0; j < NTt / 2; j++) {
                uint32_t b0 = st + 2 * APB + bRow + j * (16 * ROWB) + h * 32;
                ldsm_x4(bh[2*j][0], bh[2*j][1], bh[2*j+1][0], bh[2*j+1][1], b0);
                ldsm_x4(bl[2*j][0], bl[2*j][1], bl[2*j+1][0], bl[2*j+1][1], b0 + WPB);
            }
            #pragma unroll
            for (int m = 0; m < 4; m++)
                #pragma unroll
                for (int n = 0; n < NTt; n++)
                    mma_bf16(acc[m][n], ah[m], bh[n]);
            #pragma unroll
            for (int m = 0; m < 4; m++)
                #pragma unroll
                for (int n = 0; n < NTt; n++)
                    mma_bf16(acc[m][n], ah[m], bl[n]);
            #pragma unroll
            for (int m = 0; m < 4; m++)
                #pragma unroll
                for (int n = 0; n < NTt; n++)
                    mma_bf16(acc[m][n], al[m], bh[n]);
        }
        __syncthreads();
    }

    #pragma unroll
    for (int m = 0; m < 4; m++) {
        int gi = i0 + wm * 64 + m * 16 + lg;
        #pragma unroll
        for (int n = 0; n < NTt; n++) {
            int gj = j0 + wn * (NTt * 8) + n * 8 + 2 * lq;
            float b0 = bias[gj], b1 = bias[gj + 1];
            float v0 = acc[m][n][0] + b0;
            float v1 = acc[m][n][1] + b1;
            float v2 = acc[m][n][2] + b0;
            float v3 = acc[m][n][3] + b1;
            if (ACT == 1) {
                v0 = softplusf(v0); v1 = softplusf(v1);
                v2 = softplusf(v2); v3 = softplusf(v3);
            }
            *(float2*)(C + (size_t)gi * ldc + gj)       = make_float2(v0, v1);
            *(float2*)(C + (size_t)(gi + 8) * ldc + gj) = make_float2(v2, v3);
        }
    }
}

// ---------------- fp16 single-pass GEMM (head only), 3-stage, 2 CTAs/SM ---
template<int BN>
__global__ __launch_bounds__(256, 2)
void gemm_fp16(const uint32_t* __restrict__ Ah, const uint32_t* __restrict__ Wh,
               int K2,
               const float* __restrict__ bias,
               float* __restrict__ C, int ldc) {
    constexpr int NTt  = BN / 32;
    constexpr int ROWB = 80;
    constexpr int APB  = 128 * ROWB;
    constexpr int WPB  = BN * ROWB;
    constexpr int STGB = APB + WPB;
    constexpr int NCH  = (128 + BN) * 4 / 256;

    extern __shared__ __align__(16) uint32_t smu[];

    const int tid  = threadIdx.x;
    const int lane = tid & 31;
    const int wid  = tid >> 5;
    const int wm   = wid >> 2;
    const int wn   = wid & 3;
    const int i0   = blockIdx.y * 128;
    const int j0   = blockIdx.x * BN;
    const int lq   = lane & 3;
    const int lg   = lane >> 2;

    const uint32_t sb = (uint32_t)__cvta_generic_to_shared(smu);

    const uint32_t* src[NCH];
    uint32_t dst[NCH];
    #pragma unroll
    for (int uu = 0; uu < NCH; uu++) {
        int c  = uu * 256 + tid;
        int r2 = c >> 2;
        int q  = c & 3;
        const uint32_t* gbase;
        int pofs, r;
        if (r2 < 128) { r = r2;       gbase = Ah + (size_t)i0 * K2; pofs = 0; }
        else          { r = r2 - 128; gbase = Wh + (size_t)j0 * K2; pofs = APB; }
        src[uu] = gbase + (size_t)r * K2 + q * 4;
        dst[uu] = sb + pofs + r * ROWB + q * 16;
    }

    const uint32_t aRow = (uint32_t)((wm * 64 + (lane & 15)) * ROWB + ((lane >> 4) << 4));
    const uint32_t bRow = (uint32_t)((wn * (NTt * 8) + ((lane >> 4) << 3) + (lane & 7)) * ROWB
                                     + (((lane >> 3) & 1) << 4));

    float acc[4][NTt][4];
    #pragma unroll
    for (int m = 0; m < 4; m++)
        #pragma unroll
        for (int n = 0; n < NTt; n++)
            #pragma unroll
            for (int c = 0; c < 4; c++) acc[m][n][c] = 0.f;

    const int nk = K2 >> 4;

    #pragma unroll
    for (int uu = 0; uu < NCH; uu++) cp_async16(dst[uu], src[uu]);
    cp_commit();
    #pragma unroll
    for (int uu = 0; uu < NCH; uu++) cp_async16(dst[uu] + STGB, src[uu] + 16);
    cp_commit();

    for (int t = 0; t < nk; t++) {
        if (t + 1 < nk) { cp_wait<1>(); } else { cp_wait<0>(); }
        __syncthreads();
        if (t + 2 < nk) {
            uint32_t so = (uint32_t)((t + 2) % 3) * STGB;
            int ko = (t + 2) * 16;
            #pragma unroll
            for (int uu = 0; uu < NCH; uu++)
                cp_async16(dst[uu] + so, src[uu] + ko);
            cp_commit();
        }

        const uint32_t st = sb + (uint32_t)(t % 3) * STGB;

        #pragma unroll
        for (int h = 0; h < 2; h++) {
            uint32_t ah[4][4], bh[NTt][2];
            #pragma unroll
            for (int m = 0; m < 4; m++) {
                uint32_t a0 = st + aRow + m * (16 * ROWB) + h * 32;
                ldsm_x4(ah[m][0], ah[m][1], ah[m][2], ah[m][3], a0);
            }
            #pragma unroll
            for (int j = 0; j < NTt / 2; j++) {
                uint32_t b0 = st + APB + bRow + j * (16 * ROWB) + h * 32;
                ldsm_x4(bh[2*j][0], bh[2*j][1], bh[2*j+1][0], bh[2*j+1][1], b0);
            }
            #pragma unroll
            for (int m = 0; m < 4; m++)
                #pragma unroll
                for (int n = 0; n < NTt; n++)
                    mma_f16(acc[m][n], ah[m], bh[n]);
        }
    }

    #pragma unroll
    for (int m = 0; m < 4; m++) {
        int gi = i0 + wm * 64 + m * 16 + lg;
        #pragma unroll
        for (int n = 0; n < NTt; n++) {
            int gj = j0 + wn * (NTt * 8) + n * 8 + 2 * lq;
            float b0 = bias[gj], b1 = bias[gj + 1];
            *(float2*)(C + (size_t)gi * ldc + gj) =
                make_float2(acc[m][n][0] + b0, acc[m][n][1] + b1);
            *(float2*)(C + (size_t)(gi + 8) * ldc + gj) =
                make_float2(acc[m][n][2] + b0, acc[m][n][3] + b1);
        }
    }
}

// ---------------- lin_x + fused dt-plane emit ----------------
__global__ __launch_bounds__(256)
void linx_kernel(const float* __restrict__ u,
                 const float* __restrict__ w,
                 const float* __restrict__ bias,
                 float* __restrict__ xdbl,
                 uint32_t* __restrict__ dth,
                 uint32_t* __restrict__ dtl) {
    int ig = blockIdx.x / 20;
    int jc = blockIdx.x % 20;
    int wid  = threadIdx.x >> 5;
    int lane = threadIdx.x & 31;
    int i  = ig * 8 + wid;
    int j0 = jc * 4;

    const float4* u4 = (const float4*)(u + (size_t)i * Hh);
    const float4* w0 = (const float4*)(w + (size_t)(j0 + 0) * Hh);
    const float4* w1 = (const float4*)(w + (size_t)(j0 + 1) * Hh);
    const float4* w2 = (const float4*)(w + (size_t)(j0 + 2) * Hh);
    const float4* w3 = (const float4*)(w + (size_t)(j0 + 3) * Hh);

    float p0 = 0.f, p1 = 0.f, p2 = 0.f, p3 = 0.f;
    #pragma unroll
    for (int t = 0; t < Hh / 128; t++) {
        int k = t * 32 + lane;
        float4 uv = u4[k];
        float4 a  = w0[k];
        p0 += uv.x * a.x + uv.y * a.y + uv.z * a.z + uv.w * a.w;
        a = w1[k];
        p1 += uv.x * a.x + uv.y * a.y + uv.z * a.z + uv.w * a.w;
        a = w2[k];
        p2 += uv.x * a.x + uv.y * a.y + uv.z * a.z + uv.w * a.w;
        a = w3[k];
        p3 += uv.x * a.x + uv.y * a.y + uv.z * a.z + uv.w * a.w;
    }
    p0 = warp_sum(p0); p1 = warp_sum(p1);
    p2 = warp_sum(p2); p3 = warp_sum(p3);
    if (lane == 0) {
        float v0 = p0 + bias[j0];
        float v1 = p1 + bias[j0 + 1];
        float v2 = p2 + bias[j0 + 2];
        float v3 = p3 + bias[j0 + 3];
        float* o = xdbl + (size_t)i * XD + j0;
        o[0] = v0; o[1] = v1; o[2] = v2; o[3] = v3;
        if (j0 < Rr) {
            int j2 = j0 >> 1;
            uint32_t l0, l1;
            uint32_t h0 = packsplit(v0, v1, l0);
            uint32_t h1 = packsplit(v2, v3, l1);
            dth[(size_t)i * K2_DT + j2]     = h0;
            dtl[(size_t)i * K2_DT + j2]     = l0;
            dth[(size_t)i * K2_DT + j2 + 1] = h1;
            dtl[(size_t)i * K2_DT + j2 + 1] = l1;
        }
    }
    if (jc == 0 && lane < 8) {
        dth[(size_t)i * K2_DT + 24 + lane] = 0;
        dtl[(size_t)i * K2_DT + 24 + lane] = 0;
    }
}

// ---------------- depthwise causal conv (K=4) + silu, float4 --------------
__global__ void conv_silu_kernel(const float* __restrict__ xr,
                                 const float* __restrict__ cw,
                                 const float* __restrict__ cb,
                                 float* __restrict__ u) {
    int idx = blockIdx.x * blockDim.x + threadIdx.x;
    if (idx >= BS * (Hh / 4)) return;
    int h4  = idx % (Hh / 4);
    int row = idx / (Hh / 4);
    int h   = h4 * 4;
    int s   = row % Ss;
    int b   = row / Ss;

    const float4* cw4 = (const float4*)cw;
    float4 t0 = cw4[h], t1 = cw4[h + 1], t2 = cw4[h + 2], t3 = cw4[h + 3];
    float4 acc = ((const float4*)cb)[h4];

    #pragma unroll
    for (int k = 0; k < Kk; k++) {
        int sp = s - (Kk - 1) + k;
        if (sp >= 0) {
            float4 xv = *(const float4*)(xr + (size_t)(b * Ss + sp) * H2 + h);
            float ta = (k == 0) ? t0.x : (k == 1) ? t0.y : (k == 2) ? t0.z : t0.w;
            float tb = (k == 0) ? t1.x : (k == 1) ? t1.y : (k == 2) ? t1.z : t1.w;
            float tc = (k == 0) ? t2.x : (k == 1) ? t2.y : (k == 2) ? t2.z : t2.w;
            float td = (k == 0) ? t3.x : (k == 1) ? t3.y : (k == 2) ? t3.z : t3.w;
            acc.x += ta * xv.x;
            acc.y += tb * xv.y;
            acc.z += tc * xv.z;
            acc.w += td * xv.w;
        }
    }
    float4 o;
    o.x = siluf(acc.x); o.y = siluf(acc.y);
    o.z = siluf(acc.z); o.w = siluf(acc.w);
    *(float4*)(u + (size_t)row * Hh + h) = o;
}

// ---------------- scan + gate, software-pipelined, bf16 hi/lo y out -------
__global__ void scan_gate_kernel(const float* __restrict__ delta,
                                 const float* __restrict__ u,
                                 const float* __restrict__ xdbl,
                                 const float* __restrict__ Dp,
                                 const float* __restrict__ xr,
                                 uint32_t* __restrict__ yh,
                                 uint32_t* __restrict__ yl) {
    int gwarp = (blockIdx.x * blockDim.x + threadIdx.x) >> 5;
    if (gwarp >= Bb * (Hh / 2)) return;
    int lane = threadIdx.x & 31;
    int half = lane >> 4;
    int n    = lane & 15;
    int b    = gwarp / (Hh / 2);
    int hp   = gwarp % (Hh / 2);
    int h    = hp * 2 + half;

    const float An = -(float)(n + 1);
    const float Dh = Dp[h];
    float state = 0.f;

    const int base = b * Ss;

    float dv  = __ldg(delta + (size_t)base * Hh + h);
    float uv  = __ldg(u + (size_t)base * Hh + h);
    float Bn  = __ldg(xdbl + base * XD + Rr + n);
    float Cn  = __ldg(xdbl + base * XD + Rr + Nn + n);
    float res = __ldg(xr + (size_t)base * H2 + Hh + h);
    float dA  = expf(dv * An);
    float dBu = dv * Bn * uv;

    for (int s = 0; s < Ss; s++) {
        int row = base + s;
        float dv1 = 0.f, uv1 = 0.f, Bn1 = 0.f, Cn1 = 0.f, res1 = 0.f;
        if (s + 1 < Ss) {
            int r1 = row + 1;
            dv1  = __ldg(delta + (size_t)r1 * Hh + h);
            uv1  = __ldg(u + (size_t)r1 * Hh + h);
            Bn1  = __ldg(xdbl + r1 * XD + Rr + n);
            Cn1  = __ldg(xdbl + r1 * XD + Rr + Nn + n);
            res1 = __ldg(xr + (size_t)r1 * H2 + Hh + h);
        }
        state = dA * state + dBu;
        float dA1  = expf(dv1 * An);
        float dBu1 = dv1 * Bn1 * uv1;
        float val = state * Cn;
        val += __shfl_xor_sync(0xffffffffu, val, 8);
        val += __shfl_xor_sync(0xffffffffu, val, 4);
        val += __shfl_xor_sync(0xffffffffu, val, 2);
        val += __shfl_xor_sync(0xffffffffu, val, 1);
        float yv = (val + uv * Dh) * siluf(res);
        float y1 = __shfl_sync(0xffffffffu, yv, 16);
        if (lane == 0) {
            uint32_t lo;
            uint32_t hi = packsplit(yv, y1, lo);
            yh[(size_t)row * K2_H + hp] = hi;
            yl[(size_t)row * K2_H + hp] = lo;
        }
        dA = dA1; dBu = dBu1;
        uv = uv1; Cn = Cn1; res = res1;
    }
}

// ---------------- x += rmsnorm(mo) * w ; emit x planes ----------------
__global__ void rmsnorm_add_kernel(float* __restrict__ x,
                                   const float* __restrict__ mo,
                                   const float* __restrict__ w,
                                   uint32_t* __restrict__ xph,
                                   uint32_t* __restrict__ xpl) {
    int row = blockIdx.x;
    const float* r = mo + (size_t)row * Mdim;
    float ss = 0.f;
    for (int m = threadIdx.x; m < Mdim; m += blockDim.x) {
        float v = r[m];
        ss += v * v;
    }
    __shared__ float sh[8];
    ss = warp_sum(ss);
    int wid = threadIdx.x >> 5, lane = threadIdx.x & 31;
    if (lane == 0) sh[wid] = ss;
    __syncthreads();
    if (wid == 0) {
        float v = (lane < (int)(blockDim.x >> 5)) ? sh[lane] : 0.f;
        v = warp_sum(v);
        if (lane == 0) sh[0] = v;
    }
    __syncthreads();
    float scale = rsqrtf(sh[0] / (float)Mdim + 1e-15f);
    float* xp = x + (size_t)row * Mdim;
    for (int m2 = threadIdx.x; m2 < K2_M; m2 += blockDim.x) {
        int m = 2 * m2;
        float v0 = xp[m]     + r[m]     * scale * w[m];
        float v1 = xp[m + 1] + r[m + 1] * scale * w[m + 1];
        xp[m] = v0; xp[m + 1] = v1;
        uint32_t lo;
        uint32_t hi = packsplit(v0, v1, lo);
        xph[(size_t)row * K2_M + m2] = hi;
        xpl[(size_t)row * K2_M + m2] = lo;
    }
}

// ---------------- final rmsnorm -> fp16 planes (head input) ----------------
__global__ void rmsnorm_final_kernel(const float* __restrict__ x,
                                     const float* __restrict__ w,
                                     uint32_t* __restrict__ xnf) {
    int row = blockIdx.x;
    const float* r = x + (size_t)row * Mdim;
    float ss = 0.f;
    for (int m = threadIdx.x; m < Mdim; m += blockDim.x) {
        float v = r[m];
        ss += v * v;
    }
    __shared__ float sh[8];
    ss = warp_sum(ss);
    int wid = threadIdx.x >> 5, lane = threadIdx.x & 31;
    if (lane == 0) sh[wid] = ss;
    __syncthreads();
    if (wid == 0) {
        float v = (lane < (int)(blockDim.x >> 5)) ? sh[lane] : 0.f;
        v = warp_sum(v);
        if (lane == 0) sh[0] = v;
    }
    __syncthreads();
    float scale = rsqrtf(sh[0] / (float)Mdim + 1e-15f);
    for (int m2 = threadIdx.x; m2 < K2_M; m2 += blockDim.x) {
        int m = 2 * m2;
        xnf[(size_t)row * K2_M + m2] =
            pack_f16(r[m] * scale * w[m], r[m + 1] * scale * w[m + 1]);
    }
}

// ---------------- launch ----------------
extern "C" void kernel_launch(void* const* d_in, const int* in_sizes, int n_in,
                              void* d_out, int out_size) {
    const int*   ids = (const int*)  d_in[0];
    const float* emb = (const float*)d_in[1];
    const float* liw = (const float*)d_in[2];
    const float* lib = (const float*)d_in[3];
    const float* cw  = (const float*)d_in[4];
    const float* cb  = (const float*)d_in[5];
    const float* lxw = (const float*)d_in[6];
    const float* lxb = (const float*)d_in[7];
    const float* ldw = (const float*)d_in[8];
    const float* ldb = (const float*)d_in[9];
    const float* low = (const float*)d_in[10];
    const float* lob = (const float*)d_in[11];
    const float* Dp  = (const float*)d_in[12];
    const float* bnw = (const float*)d_in[13];
    const float* fnw = (const float*)d_in[14];
    const float* hw  = (const float*)d_in[15];
    const float* hb  = (const float*)d_in[16];
    float* out = (float*)d_out;

    float *x, *xr, *u, *xdbl, *delta, *mo;
    cudaGetSymbolAddress((void**)&x,     g_x);
    cudaGetSymbolAddress((void**)&xr,    g_xr);
    cudaGetSymbolAddress((void**)&u,     g_u);
    cudaGetSymbolAddress((void**)&xdbl,  g_xdbl);
    cudaGetSymbolAddress((void**)&delta, g_delta);
    cudaGetSymbolAddress((void**)&mo,    g_mo);

    uint32_t *xp_h, *xp_l, *act_h, *act_l;
    uint32_t *liw_h, *liw_l, *ldw_h, *ldw_l, *low_h, *low_l, *hw_h;
    cudaGetSymbolAddress((void**)&xp_h,  g_xp_h);
    cudaGetSymbolAddress((void**)&xp_l,  g_xp_l);
    cudaGetSymbolAddress((void**)&act_h, g_act_h);
    cudaGetSymbolAddress((void**)&act_l, g_act_l);
    cudaGetSymbolAddress((void**)&liw_h, g_liw_h);
    cudaGetSymbolAddress((void**)&liw_l, g_liw_l);
    cudaGetSymbolAddress((void**)&ldw_h, g_ldw_h);
    cudaGetSymbolAddress((void**)&ldw_l, g_ldw_l);
    cudaGetSymbolAddress((void**)&low_h, g_low_h);
    cudaGetSymbolAddress((void**)&low_l, g_low_l);
    cudaGetSymbolAddress((void**)&hw_h,  g_hw_h);

    const int SM128  = 2 * (2 * 128 * 80 + 2 * 128 * 80);  // 81920 (bf16x3 BN=128)
    const int SM64   = 2 * (2 * 128 * 80 + 2 * 64 * 80);   // 61440 (bf16x3 BN=64)
    const int SMF128 = 3 * (128 + 128) * 80;               // 61440 (fp16 BN=128)
    cudaFuncSetAttribute((const void*)gemm_bf16x3<128, 0>,
                         cudaFuncAttributeMaxDynamicSharedMemorySize, SM128);
    cudaFuncSetAttribute((const void*)gemm_bf16x3<128, 1>,
                         cudaFuncAttributeMaxDynamicSharedMemorySize, SM128);
    cudaFuncSetAttribute((const void*)gemm_bf16x3<64, 0>,
                         cudaFuncAttributeMaxDynamicSharedMemorySize, SM64);
    cudaFuncSetAttribute((const void*)gemm_fp16<128>,
                         cudaFuncAttributeMaxDynamicSharedMemorySize, SMF128);

    embed_kernel<<<(BS * K2_M + 255) / 256, 256>>>(ids, emb, x, xp_h, xp_l);

    for (int l = 0; l < Ll; l++) {
        split_layer_kernel<<<(SEGT + 255) / 256, 256>>>(
            liw + (size_t)l * H2 * Mdim, ldw + (size_t)l * Hh * Rr,
            low + (size_t)l * Mdim * Hh,
            liw_h + (size_t)l * H2 * K2_M, liw_l + (size_t)l * H2 * K2_M,
            ldw_h + (size_t)l * Hh * K2_DT, ldw_l + (size_t)l * Hh * K2_DT,
            low_h + (size_t)l * Mdim * K2_H, low_l + (size_t)l * Mdim * K2_H);

        if (l == 0)
            split_hw_f16_kernel<<<(Vv * K2_M + 255) / 256, 256>>>(hw, hw_h);

        // lin_in (absolute launch #5 when l=0 — profiled)
        gemm_bf16x3<128, 0><<<dim3(H2 / 128, BS / 128), 256, SM128>>>(
            xp_h, xp_l,
            liw_h + (size_t)l * H2 * K2_M, liw_l + (size_t)l * H2 * K2_M,
            K2_M, lib + (size_t)l * H2, xr, H2);

        conv_silu_kernel<<<(BS * (Hh / 4) + 255) / 256, 256>>>(
            xr, cw + (size_t)l * Hh * Kk, cb + (size_t)l * Hh, u);

        linx_kernel<<<(BS / 8) * (XD / 4), 256>>>(
            u, lxw + (size_t)l * XD * Hh, lxb + (size_t)l * XD, xdbl,
            act_h, act_l);

        gemm_bf16x3<128, 1><<<dim3(Hh / 128, BS / 128), 256, SM128>>>(
            act_h, act_l,
            ldw_h + (size_t)l * Hh * K2_DT, ldw_l + (size_t)l * Hh * K2_DT,
            K2_DT, ldb + (size_t)l * Hh, delta, Hh);

        scan_gate_kernel<<<(Bb * (Hh / 2) * 32 + 255) / 256, 256>>>(
            delta, u, xdbl, Dp + (size_t)l * Hh, xr, act_h, act_l);

        // lin_out: bf16x3 (precision-critical — feeds residual stream)
        gemm_bf16x3<64, 0><<<dim3(Mdim / 64, BS / 128), 256, SM64>>>(
            act_h, act_l,
            low_h + (size_t)l * Mdim * K2_H, low_l + (size_t)l * Mdim * K2_H,
            K2_H, lob + (size_t)l * Mdim, mo, Mdim);

        rmsnorm_add_kernel<<<BS, 256>>>(x, mo, bnw + (size_t)l * Mdim, xp_h, xp_l);
    }

    rmsnorm_final_kernel<<<BS, 256>>>(x, fnw, act_h);

    gemm_fp16<128><<<dim3(Vv / 128, BS / 128), 256, SMF128>>>(
        act_h, hw_h, K2_M, hb, out, Vv);
}

// round 12
// speedup vs baseline: 2.9833x; 1.0073x over previous
#include <cuda_runtime.h>
#include <cuda_bf16.h>
#include <cuda_fp16.h>
#include <math.h>
#include <stdint.h>

#define DEV_INLINE __device__ __forceinline__

// Problem constants
constexpr int Mdim = 768;
constexpr int Vv   = 32000;
constexpr int Rr   = 48;
constexpr int Nn   = 16;
constexpr int Kk   = 4;
constexpr int Ll   = 2;
constexpr int Hh   = 1536;
constexpr int Bb   = 2;
constexpr int Ss   = 1024;
constexpr int BS   = Bb * Ss;     // 2048
constexpr int H2   = 2 * Hh;      // 3072
constexpr int XD   = Rr + 2 * Nn; // 80

constexpr int K2_M  = Mdim / 2;   // 384
constexpr int K2_H  = Hh / 2;     // 768
constexpr int K2_DT = 32;         // 48/2=24 -> pad 32

// ---------------- fp32 scratch ----------------
__device__ float g_x    [BS * Mdim];
__device__ float g_xr   [BS * H2];
__device__ float g_u    [BS * Hh];
__device__ float g_xdbl [BS * XD];
__device__ float g_delta[BS * Hh];
__device__ float g_mo   [BS * Mdim];

// ---------------- packed 16-bit planes ----------------
__device__ __align__(16) uint32_t g_xp_h [BS * K2_M];
__device__ __align__(16) uint32_t g_xp_l [BS * K2_M];
__device__ __align__(16) uint32_t g_act_h[BS * K2_H];
__device__ __align__(16) uint32_t g_act_l[BS * K2_H];
__device__ __align__(16) uint32_t g_liw_h[Ll * H2 * K2_M];
__device__ __align__(16) uint32_t g_liw_l[Ll * H2 * K2_M];
__device__ __align__(16) uint32_t g_ldw_h[Ll * Hh * K2_DT];
__device__ __align__(16) uint32_t g_ldw_l[Ll * Hh * K2_DT];
__device__ __align__(16) uint32_t g_low_h[Ll * Mdim * K2_H];
__device__ __align__(16) uint32_t g_low_l[Ll * Mdim * K2_H];
__device__ __align__(16) uint32_t g_hw_h [Vv * K2_M];          // fp16 single

// ---------------- helpers ----------------
DEV_INLINE float siluf(float v)     { return v / (1.f + expf(-v)); }
DEV_INLINE float softplusf(float v) { return v > 20.f ? v : log1pf(expf(v)); }

DEV_INLINE float warp_sum(float v) {
    #pragma unroll
    for (int o = 16; o; o >>= 1) v += __shfl_xor_sync(0xffffffffu, v, o);
    return v;
}

DEV_INLINE uint32_t packsplit(float f0, float f1, uint32_t& lo) {
    __nv_bfloat16 h0 = __float2bfloat16(f0);
    __nv_bfloat16 h1 = __float2bfloat16(f1);
    __nv_bfloat16 l0 = __float2bfloat16(f0 - __bfloat162float(h0));
    __nv_bfloat16 l1 = __float2bfloat16(f1 - __bfloat162float(h1));
    lo = (uint32_t)__bfloat16_as_ushort(l0) | ((uint32_t)__bfloat16_as_ushort(l1) << 16);
    return (uint32_t)__bfloat16_as_ushort(h0) | ((uint32_t)__bfloat16_as_ushort(h1) << 16);
}

DEV_INLINE uint32_t pack_f16(float f0, float f1) {
    __half2 h = __floats2half2_rn(f0, f1);
    return *(uint32_t*)&h;
}

// pack 8 floats -> uint4 hi + uint4 lo (bf16 planes)
DEV_INLINE void packsplit8(float4 a, float4 b, uint4& hi, uint4& lo) {
    hi.x = packsplit(a.x, a.y, lo.x);
    hi.y = packsplit(a.z, a.w, lo.y);
    hi.z = packsplit(b.x, b.y, lo.z);
    hi.w = packsplit(b.z, b.w, lo.w);
}

DEV_INLINE void mma_bf16(float* d, const uint32_t* a, const uint32_t* b) {
    asm volatile(
        "mma.sync.aligned.m16n8k16.row.col.f32.bf16.bf16.f32 "
        "{%0,%1,%2,%3}, {%4,%5,%6,%7}, {%8,%9}, {%0,%1,%2,%3};"
        : "+f"(d[0]), "+f"(d[1]), "+f"(d[2]), "+f"(d[3])
        : "r"(a[0]), "r"(a[1]), "r"(a[2]), "r"(a[3]),
          "r"(b[0]), "r"(b[1]));
}

DEV_INLINE void mma_f16(float* d, const uint32_t* a, const uint32_t* b) {
    asm volatile(
        "mma.sync.aligned.m16n8k16.row.col.f32.f16.f16.f32 "
        "{%0,%1,%2,%3}, {%4,%5,%6,%7}, {%8,%9}, {%0,%1,%2,%3};"
        : "+f"(d[0]), "+f"(d[1]), "+f"(d[2]), "+f"(d[3])
        : "r"(a[0]), "r"(a[1]), "r"(a[2]), "r"(a[3]),
          "r"(b[0]), "r"(b[1]));
}

DEV_INLINE void ldsm_x4(uint32_t& r0, uint32_t& r1, uint32_t& r2, uint32_t& r3,
                        uint32_t addr) {
    asm volatile("ldmatrix.sync.aligned.m8n8.x4.shared.b16 {%0,%1,%2,%3}, [%4];"
                 : "=r"(r0), "=r"(r1), "=r"(r2), "=r"(r3) : "r"(addr));
}

DEV_INLINE void cp_async16(uint32_t dst, const void* src) {
    asm volatile("cp.async.cg.shared.global [%0], [%1], 16;" :: "r"(dst), "l"(src));
}
DEV_INLINE void cp_commit() { asm volatile("cp.async.commit_group;"); }
template<int N> DEV_INLINE void cp_wait() {
    asm volatile("cp.async.wait_group %0;" :: "n"(N));
}

// ---------------- fused per-layer weight split (vectorized, uint4/thread) --
constexpr int SEG0 = H2 * K2_M;
constexpr int SEG1 = Hh * K2_DT;
constexpr int SEG2 = Mdim * K2_H;
constexpr int Q0 = SEG0 / 4;
constexpr int Q1 = SEG1 / 4;
constexpr int Q2 = SEG2 / 4;
constexpr int QT = Q0 + Q1 + Q2;

__global__ void split_layer_kernel(const float* __restrict__ liw,
                                   const float* __restrict__ ldw,
                                   const float* __restrict__ low,
                                   uint32_t* __restrict__ liw_h, uint32_t* __restrict__ liw_l,
                                   uint32_t* __restrict__ ldw_h, uint32_t* __restrict__ ldw_l,
                                   uint32_t* __restrict__ low_h, uint32_t* __restrict__ low_l) {
    int idx = blockIdx.x * blockDim.x + threadIdx.x;
    if (idx >= QT) return;
    if (idx < Q0) {
        int u = idx * 4;
        int r = u / K2_M, j = u - r * K2_M;
        const float4* p = (const float4*)(liw + (size_t)r * Mdim + 2 * j);
        uint4 hi, lo;
        packsplit8(p[0], p[1], hi, lo);
        *(uint4*)(liw_h + u) = hi;
        *(uint4*)(liw_l + u) = lo;
    } else if (idx < Q0 + Q1) {
        int u = (idx - Q0) * 4;
        int r = u / K2_DT, j = u - r * K2_DT;   // j in {0,4,...,28}
        uint4 hi, lo;
        if (2 * j >= Rr) {
            hi = make_uint4(0, 0, 0, 0);
            lo = make_uint4(0, 0, 0, 0);
        } else {
            const float4* p = (const float4*)(ldw + (size_t)r * Rr + 2 * j);
            packsplit8(p[0], p[1], hi, lo);
        }
        *(uint4*)(ldw_h + u) = hi;
        *(uint4*)(ldw_l + u) = lo;
    } else {
        int u = (idx - Q0 - Q1) * 4;
        int r = u / K2_H, j = u - r * K2_H;
        const float4* p = (const float4*)(low + (size_t)r * Hh + 2 * j);
        uint4 hi, lo;
        packsplit8(p[0], p[1], hi, lo);
        *(uint4*)(low_h + u) = hi;
        *(uint4*)(low_l + u) = lo;
    }
}

// ---------------- fp16 split for head weights (vectorized) ----------------
__global__ void split_hw_f16_kernel(const float* __restrict__ in,
                                    uint32_t* __restrict__ out) {
    int idx = blockIdx.x * blockDim.x + threadIdx.x;
    if (idx >= (Vv * K2_M) / 4) return;
    int u = idx * 4;
    int r = u / K2_M, j = u - r * K2_M;
    const float4* p = (const float4*)(in + (size_t)r * Mdim + 2 * j);
    float4 a = p[0], b = p[1];
    uint4 o;
    o.x = pack_f16(a.x, a.y);
    o.y = pack_f16(a.z, a.w);
    o.z = pack_f16(b.x, b.y);
    o.w = pack_f16(b.z, b.w);
    *(uint4*)(out + u) = o;
}

// ---------------- embedding gather + planes ----------------
__global__ void embed_kernel(const int* __restrict__ ids,
                             const float* __restrict__ emb,
                             float* __restrict__ x,
                             uint32_t* __restrict__ xph,
                             uint32_t* __restrict__ xpl) {
    int idx = blockIdx.x * blockDim.x + threadIdx.x;
    if (idx >= BS * K2_M) return;
    int row = idx / K2_M;
    int m2  = idx - row * K2_M;
    const float* e = emb + (size_t)ids[row] * Mdim + 2 * m2;
    float f0 = e[0], f1 = e[1];
    x[(size_t)row * Mdim + 2 * m2]     = f0;
    x[(size_t)row * Mdim + 2 * m2 + 1] = f1;
    uint32_t l;
    uint32_t h = packsplit(f0, f1, l);
    xph[idx] = h;
    xpl[idx] = l;
}

// ---------------- bf16x3 GEMM, 2-stage double buffer, 2 CTAs/SM ----------
template<int BN, int ACT>
__global__ __launch_bounds__(256, 2)
void gemm_bf16x3(const uint32_t* __restrict__ Ah, const uint32_t* __restrict__ Al,
                 const uint32_t* __restrict__ Wh, const uint32_t* __restrict__ Wl,
                 int K2,
                 const float* __restrict__ bias,
                 float* __restrict__ C, int ldc) {
    constexpr int NTt  = BN / 32;
    constexpr int ROWB = 80;
    constexpr int APB  = 128 * ROWB;
    constexpr int WPB  = BN * ROWB;
    constexpr int STGB = 2 * APB + 2 * WPB;
    constexpr int NCH  = (256 + 2 * BN) * 4 / 256;

    extern __shared__ __align__(16) uint32_t smu[];

    const int tid  = threadIdx.x;
    const int lane = tid & 31;
    const int wid  = tid >> 5;
    const int wm   = wid >> 2;
    const int wn   = wid & 3;
    const int i0   = blockIdx.y * 128;
    const int j0   = blockIdx.x * BN;
    const int lq   = lane & 3;
    const int lg   = lane >> 2;

    const uint32_t sb = (uint32_t)__cvta_generic_to_shared(smu);

    const uint32_t* src[NCH];
    uint32_t dst[NCH];
    #pragma unroll
    for (int uu = 0; uu < NCH; uu++) {
        int c  = uu * 256 + tid;
        int r2 = c >> 2;
        int q  = c & 3;
        const uint32_t* gbase;
        int pofs, r;
        if (r2 < 128)            { r = r2;            gbase = Ah + (size_t)i0 * K2; pofs = 0; }
        else if (r2 < 256)       { r = r2 - 128;      gbase = Al + (size_t)i0 * K2; pofs = APB; }
        else if (r2 < 256 + BN)  { r = r2 - 256;      gbase = Wh + (size_t)j0 * K2; pofs = 2 * APB; }
        else                     { r = r2 - 256 - BN; gbase = Wl + (size_t)j0 * K2; pofs = 2 * APB + WPB; }
        src[uu] = gbase + (size_t)r * K2 + q * 4;
        dst[uu] = sb + pofs + r * ROWB + q * 16;
    }

    const uint32_t aRow = (uint32_t)((wm * 64 + (lane & 15)) * ROWB + ((lane >> 4) << 4));
    const uint32_t bRow = (uint32_t)((wn * (NTt * 8) + ((lane >> 4) << 3) + (lane & 7)) * ROWB
                                     + (((lane >> 3) & 1) << 4));

    float acc[4][NTt][4];
    #pragma unroll
    for (int m = 0; m < 4; m++)
        #pragma unroll
        for (int n = 0; n < NTt; n++)
            #pragma unroll
            for (int c = 0; c < 4; c++) acc[m][n][c] = 0.f;

    const int nk = K2 >> 4;

    #pragma unroll
    for (int uu = 0; uu < NCH; uu++) cp_async16(dst[uu], src[uu]);
    cp_commit();

    for (int t = 0; t < nk; t++) {
        cp_wait<0>();
        __syncthreads();
        if (t + 1 < nk) {
            uint32_t so = (uint32_t)((t + 1) & 1) * STGB;
            int ko = (t + 1) * 16;
            #pragma unroll
            for (int uu = 0; uu < NCH; uu++)
                cp_async16(dst[uu] + so, src[uu] + ko);
            cp_commit();
        }

        const uint32_t st = sb + (uint32_t)(t & 1) * STGB;

        #pragma unroll
        for (int h = 0; h < 2; h++) {
            uint32_t ah[4][4], al[4][4], bh[NTt][2], bl[NTt][2];
            #pragma unroll
            for (int m = 0; m < 4; m++) {
                uint32_t a0 = st + aRow + m * (16 * ROWB) + h * 32;
                ldsm_x4(ah[m][0], ah[m][1], ah[m][2], ah[m][3], a0);
                ldsm_x4(al[m][0], al[m][1], al[m][2], al[m][3], a0 + APB);
            }
            #pragma unroll
            for (int j = 0; j < NTt / 2; j++) {
                uint32_t b0 = st + 2 * APB + bRow + j * (16 * ROWB) + h * 32;
                ldsm_x4(bh[2*j][0], bh[2*j][1], bh[2*j+1][0], bh[2*j+1][1], b0);
                ldsm_x4(bl[2*j][0], bl[2*j][1], bl[2*j+1][0], bl[2*j+1][1], b0 + WPB);
            }
            #pragma unroll
            for (int m = 0; m < 4; m++)
                #pragma unroll
                for (int n = 0; n < NTt; n++)
                    mma_bf16(acc[m][n], ah[m], bh[n]);
            #pragma unroll
            for (int m = 0; m < 4; m++)
                #pragma unroll
                for (int n = 0; n < NTt; n++)
                    mma_bf16(acc[m][n], ah[m], bl[n]);
            #pragma unroll
            for (int m = 0; m < 4; m++)
                #pragma unroll
                for (int n = 0; n < NTt; n++)
                    mma_bf16(acc[m][n], al[m], bh[n]);
        }
        // no trailing sync: next-iter cp_wait + top sync orders buffer reuse
    }

    #pragma unroll
    for (int m = 0; m < 4; m++) {
        int gi = i0 + wm * 64 + m * 16 + lg;
        #pragma unroll
        for (int n = 0; n < NTt; n++) {
            int gj = j0 + wn * (NTt * 8) + n * 8 + 2 * lq;
            float b0 = bias[gj], b1 = bias[gj + 1];
            float v0 = acc[m][n][0] + b0;
            float v1 = acc[m][n][1] + b1;
            float v2 = acc[m][n][2] + b0;
            float v3 = acc[m][n][3] + b1;
            if (ACT == 1) {
                v0 = softplusf(v0); v1 = softplusf(v1);
                v2 = softplusf(v2); v3 = softplusf(v3);
            }
            *(float2*)(C + (size_t)gi * ldc + gj)       = make_float2(v0, v1);
            *(float2*)(C + (size_t)(gi + 8) * ldc + gj) = make_float2(v2, v3);
        }
    }
}

// ---------------- fp16 single-pass GEMM (head), 3-stage, half-pipelined ----
template<int BN>
__global__ __launch_bounds__(256, 2)
void gemm_fp16(const uint32_t* __restrict__ Ah, const uint32_t* __restrict__ Wh,
               int K2,
               const float* __restrict__ bias,
               float* __restrict__ C, int ldc) {
    constexpr int NTt  = BN / 32;
    constexpr int ROWB = 80;
    constexpr int APB  = 128 * ROWB;
    constexpr int WPB  = BN * ROWB;
    constexpr int STGB = APB + WPB;
    constexpr int NCH  = (128 + BN) * 4 / 256;

    extern __shared__ __align__(16) uint32_t smu[];

    const int tid  = threadIdx.x;
    const int lane = tid & 31;
    const int wid  = tid >> 5;
    const int wm   = wid >> 2;
    const int wn   = wid & 3;
    const int i0   = blockIdx.y * 128;
    const int j0   = blockIdx.x * BN;
    const int lq   = lane & 3;
    const int lg   = lane >> 2;

    const uint32_t sb = (uint32_t)__cvta_generic_to_shared(smu);

    const uint32_t* src[NCH];
    uint32_t dst[NCH];
    #pragma unroll
    for (int uu = 0; uu < NCH; uu++) {
        int c  = uu * 256 + tid;
        int r2 = c >> 2;
        int q  = c & 3;
        const uint32_t* gbase;
        int pofs, r;
        if (r2 < 128) { r = r2;       gbase = Ah + (size_t)i0 * K2; pofs = 0; }
        else          { r = r2 - 128; gbase = Wh + (size_t)j0 * K2; pofs = APB; }
        src[uu] = gbase + (size_t)r * K2 + q * 4;
        dst[uu] = sb + pofs + r * ROWB + q * 16;
    }

    const uint32_t aRow = (uint32_t)((wm * 64 + (lane & 15)) * ROWB + ((lane >> 4) << 4));
    const uint32_t bRow = (uint32_t)((wn * (NTt * 8) + ((lane >> 4) << 3) + (lane & 7)) * ROWB
                                     + (((lane >> 3) & 1) << 4));

    float acc[4][NTt][4];
    #pragma unroll
    for (int m = 0; m < 4; m++)
        #pragma unroll
        for (int n = 0; n < NTt; n++)
            #pragma unroll
            for (int c = 0; c < 4; c++) acc[m][n][c] = 0.f;

    const int nk = K2 >> 4;

    #pragma unroll
    for (int uu = 0; uu < NCH; uu++) cp_async16(dst[uu], src[uu]);
    cp_commit();
    #pragma unroll
    for (int uu = 0; uu < NCH; uu++) cp_async16(dst[uu] + STGB, src[uu] + 16);
    cp_commit();

    for (int t = 0; t < nk; t++) {
        if (t + 1 < nk) { cp_wait<1>(); } else { cp_wait<0>(); }
        __syncthreads();
        if (t + 2 < nk) {
            uint32_t so = (uint32_t)((t + 2) % 3) * STGB;
            int ko = (t + 2) * 16;
            #pragma unroll
            for (int uu = 0; uu < NCH; uu++)
                cp_async16(dst[uu] + so, src[uu] + ko);
            cp_commit();
        }

        const uint32_t st = sb + (uint32_t)(t % 3) * STGB;

        // hoist BOTH halves' fragment loads before all mma (long LDSM->HMMA distance)
        uint32_t ah2[2][4][4], bh2[2][NTt][2];
        #pragma unroll
        for (int h = 0; h < 2; h++) {
            #pragma unroll
            for (int m = 0; m < 4; m++) {
                uint32_t a0 = st + aRow + m * (16 * ROWB) + h * 32;
                ldsm_x4(ah2[h][m][0], ah2[h][m][1], ah2[h][m][2], ah2[h][m][3], a0);
            }
            #pragma unroll
            for (int j = 0; j < NTt / 2; j++) {
                uint32_t b0 = st + APB + bRow + j * (16 * ROWB) + h * 32;
                ldsm_x4(bh2[h][2*j][0], bh2[h][2*j][1],
                        bh2[h][2*j+1][0], bh2[h][2*j+1][1], b0);
            }
        }
        #pragma unroll
        for (int h = 0; h < 2; h++)
            #pragma unroll
            for (int m = 0; m < 4; m++)
                #pragma unroll
                for (int n = 0; n < NTt; n++)
                    mma_f16(acc[m][n], ah2[h][m], bh2[h][n]);
    }

    #pragma unroll
    for (int m = 0; m < 4; m++) {
        int gi = i0 + wm * 64 + m * 16 + lg;
        #pragma unroll
        for (int n = 0; n < NTt; n++) {
            int gj = j0 + wn * (NTt * 8) + n * 8 + 2 * lq;
            float b0 = bias[gj], b1 = bias[gj + 1];
            *(float2*)(C + (size_t)gi * ldc + gj) =
                make_float2(acc[m][n][0] + b0, acc[m][n][1] + b1);
            *(float2*)(C + (size_t)(gi + 8) * ldc + gj) =
                make_float2(acc[m][n][2] + b0, acc[m][n][3] + b1);
        }
    }
}

// ---------------- lin_x + fused dt-plane emit ----------------
__global__ __launch_bounds__(256)
void linx_kernel(const float* __restrict__ u,
                 const float* __restrict__ w,
                 const float* __restrict__ bias,
                 float* __restrict__ xdbl,
                 uint32_t* __restrict__ dth,
                 uint32_t* __restrict__ dtl) {
    int ig = blockIdx.x / 20;
    int jc = blockIdx.x % 20;
    int wid  = threadIdx.x >> 5;
    int lane = threadIdx.x & 31;
    int i  = ig * 8 + wid;
    int j0 = jc * 4;

    const float4* u4 = (const float4*)(u + (size_t)i * Hh);
    const float4* w0 = (const float4*)(w + (size_t)(j0 + 0) * Hh);
    const float4* w1 = (const float4*)(w + (size_t)(j0 + 1) * Hh);
    const float4* w2 = (const float4*)(w + (size_t)(j0 + 2) * Hh);
    const float4* w3 = (const float4*)(w + (size_t)(j0 + 3) * Hh);

    float p0 = 0.f, p1 = 0.f, p2 = 0.f, p3 = 0.f;
    #pragma unroll
    for (int t = 0; t < Hh / 128; t++) {
        int k = t * 32 + lane;
        float4 uv = u4[k];
        float4 a  = w0[k];
        p0 += uv.x * a.x + uv.y * a.y + uv.z * a.z + uv.w * a.w;
        a = w1[k];
        p1 += uv.x * a.x + uv.y * a.y + uv.z * a.z + uv.w * a.w;
        a = w2[k];
        p2 += uv.x * a.x + uv.y * a.y + uv.z * a.z + uv.w * a.w;
        a = w3[k];
        p3 += uv.x * a.x + uv.y * a.y + uv.z * a.z + uv.w * a.w;
    }
    p0 = warp_sum(p0); p1 = warp_sum(p1);
    p2 = warp_sum(p2); p3 = warp_sum(p3);
    if (lane == 0) {
        float v0 = p0 + bias[j0];
        float v1 = p1 + bias[j0 + 1];
        float v2 = p2 + bias[j0 + 2];
        float v3 = p3 + bias[j0 + 3];
        float* o = xdbl + (size_t)i * XD + j0;
        o[0] = v0; o[1] = v1; o[2] = v2; o[3] = v3;
        if (j0 < Rr) {
            int j2 = j0 >> 1;
            uint32_t l0, l1;
            uint32_t h0 = packsplit(v0, v1, l0);
            uint32_t h1 = packsplit(v2, v3, l1);
            dth[(size_t)i * K2_DT + j2]     = h0;
            dtl[(size_t)i * K2_DT + j2]     = l0;
            dth[(size_t)i * K2_DT + j2 + 1] = h1;
            dtl[(size_t)i * K2_DT + j2 + 1] = l1;
        }
    }
    if (jc == 0 && lane < 8) {
        dth[(size_t)i * K2_DT + 24 + lane] = 0;
        dtl[(size_t)i * K2_DT + 24 + lane] = 0;
    }
}

// ---------------- depthwise causal conv (K=4) + silu, float4 --------------
__global__ void conv_silu_kernel(const float* __restrict__ xr,
                                 const float* __restrict__ cw,
                                 const float* __restrict__ cb,
                                 float* __restrict__ u) {
    int idx = blockIdx.x * blockDim.x + threadIdx.x;
    if (idx >= BS * (Hh / 4)) return;
    int h4  = idx % (Hh / 4);
    int row = idx / (Hh / 4);
    int h   = h4 * 4;
    int s   = row % Ss;
    int b   = row / Ss;

    const float4* cw4 = (const float4*)cw;
    float4 t0 = cw4[h], t1 = cw4[h + 1], t2 = cw4[h + 2], t3 = cw4[h + 3];
    float4 acc = ((const float4*)cb)[h4];

    #pragma unroll
    for (int k = 0; k < Kk; k++) {
        int sp = s - (Kk - 1) + k;
        if (sp >= 0) {
            float4 xv = *(const float4*)(xr + (size_t)(b * Ss + sp) * H2 + h);
            float ta = (k == 0) ? t0.x : (k == 1) ? t0.y : (k == 2) ? t0.z : t0.w;
            float tb = (k == 0) ? t1.x : (k == 1) ? t1.y : (k == 2) ? t1.z : t1.w;
            float tc = (k == 0) ? t2.x : (k == 1) ? t2.y : (k == 2) ? t2.z : t2.w;
            float td = (k == 0) ? t3.x : (k == 1) ? t3.y : (k == 2) ? t3.z : t3.w;
            acc.x += ta * xv.x;
            acc.y += tb * xv.y;
            acc.z += tc * xv.z;
            acc.w += td * xv.w;
        }
    }
    float4 o;
    o.x = siluf(acc.x); o.y = siluf(acc.y);
    o.z = siluf(acc.z); o.w = siluf(acc.w);
    *(float4*)(u + (size_t)row * Hh + h) = o;
}

// ---------------- scan + gate, software-pipelined, bf16 hi/lo y out -------
__global__ void scan_gate_kernel(const float* __restrict__ delta,
                                 const float* __restrict__ u,
                                 const float* __restrict__ xdbl,
                                 const float* __restrict__ Dp,
                                 const float* __restrict__ xr,
                                 uint32_t* __restrict__ yh,
                                 uint32_t* __restrict__ yl) {
    int gwarp = (blockIdx.x * blockDim.x + threadIdx.x) >> 5;
    if (gwarp >= Bb * (Hh / 2)) return;
    int lane = threadIdx.x & 31;
    int half = lane >> 4;
    int n    = lane & 15;
    int b    = gwarp / (Hh / 2);
    int hp   = gwarp % (Hh / 2);
    int h    = hp * 2 + half;

    const float An = -(float)(n + 1);
    const float Dh = Dp[h];
    float state = 0.f;

    const int base = b * Ss;

    float dv  = __ldg(delta + (size_t)base * Hh + h);
    float uv  = __ldg(u + (size_t)base * Hh + h);
    float Bn  = __ldg(xdbl + base * XD + Rr + n);
    float Cn  = __ldg(xdbl + base * XD + Rr + Nn + n);
    float res = __ldg(xr + (size_t)base * H2 + Hh + h);
    float dA  = expf(dv * An);
    float dBu = dv * Bn * uv;

    for (int s = 0; s < Ss; s++) {
        int row = base + s;
        float dv1 = 0.f, uv1 = 0.f, Bn1 = 0.f, Cn1 = 0.f, res1 = 0.f;
        if (s + 1 < Ss) {
            int r1 = row + 1;
            dv1  = __ldg(delta + (size_t)r1 * Hh + h);
            uv1  = __ldg(u + (size_t)r1 * Hh + h);
            Bn1  = __ldg(xdbl + r1 * XD + Rr + n);
            Cn1  = __ldg(xdbl + r1 * XD + Rr + Nn + n);
            res1 = __ldg(xr + (size_t)r1 * H2 + Hh + h);
        }
        state = dA * state + dBu;
        float dA1  = expf(dv1 * An);
        float dBu1 = dv1 * Bn1 * uv1;
        float val = state * Cn;
        val += __shfl_xor_sync(0xffffffffu, val, 8);
        val += __shfl_xor_sync(0xffffffffu, val, 4);
        val += __shfl_xor_sync(0xffffffffu, val, 2);
        val += __shfl_xor_sync(0xffffffffu, val, 1);
        float yv = (val + uv * Dh) * siluf(res);
        float y1 = __shfl_sync(0xffffffffu, yv, 16);
        if (lane == 0) {
            uint32_t lo;
            uint32_t hi = packsplit(yv, y1, lo);
            yh[(size_t)row * K2_H + hp] = hi;
            yl[(size_t)row * K2_H + hp] = lo;
        }
        dA = dA1; dBu = dBu1;
        uv = uv1; Cn = Cn1; res = res1;
    }
}

// ---------------- x += rmsnorm(mo) * w ; emit x planes ----------------
__global__ void rmsnorm_add_kernel(float* __restrict__ x,
                                   const float* __restrict__ mo,
                                   const float* __restrict__ w,
                                   uint32_t* __restrict__ xph,
                                   uint32_t* __restrict__ xpl) {
    int row = blockIdx.x;
    const float* r = mo + (size_t)row * Mdim;
    float ss = 0.f;
    for (int m = threadIdx.x; m < Mdim; m += blockDim.x) {
        float v = r[m];
        ss += v * v;
    }
    __shared__ float sh[8];
    ss = warp_sum(ss);
    int wid = threadIdx.x >> 5, lane = threadIdx.x & 31;
    if (lane == 0) sh[wid] = ss;
    __syncthreads();
    if (wid == 0) {
        float v = (lane < (int)(blockDim.x >> 5)) ? sh[lane] : 0.f;
        v = warp_sum(v);
        if (lane == 0) sh[0] = v;
    }
    __syncthreads();
    float scale = rsqrtf(sh[0] / (float)Mdim + 1e-15f);
    float* xp = x + (size_t)row * Mdim;
    for (int m2 = threadIdx.x; m2 < K2_M; m2 += blockDim.x) {
        int m = 2 * m2;
        float v0 = xp[m]     + r[m]     * scale * w[m];
        float v1 = xp[m + 1] + r[m + 1] * scale * w[m + 1];
        xp[m] = v0; xp[m + 1] = v1;
        uint32_t lo;
        uint32_t hi = packsplit(v0, v1, lo);
        xph[(size_t)row * K2_M + m2] = hi;
        xpl[(size_t)row * K2_M + m2] = lo;
    }
}

// ---------------- final rmsnorm -> fp16 planes (head input) ----------------
__global__ void rmsnorm_final_kernel(const float* __restrict__ x,
                                     const float* __restrict__ w,
                                     uint32_t* __restrict__ xnf) {
    int row = blockIdx.x;
    const float* r = x + (size_t)row * Mdim;
    float ss = 0.f;
    for (int m = threadIdx.x; m < Mdim; m += blockDim.x) {
        float v = r[m];
        ss += v * v;
    }
    __shared__ float sh[8];
    ss = warp_sum(ss);
    int wid = threadIdx.x >> 5, lane = threadIdx.x & 31;
    if (lane == 0) sh[wid] = ss;
    __syncthreads();
    if (wid == 0) {
        float v = (lane < (int)(blockDim.x >> 5)) ? sh[lane] : 0.f;
        v = warp_sum(v);
        if (lane == 0) sh[0] = v;
    }
    __syncthreads();
    float scale = rsqrtf(sh[0] / (float)Mdim + 1e-15f);
    for (int m2 = threadIdx.x; m2 < K2_M; m2 += blockDim.x) {
        int m = 2 * m2;
        xnf[(size_t)row * K2_M + m2] =
            pack_f16(r[m] * scale * w[m], r[m + 1] * scale * w[m + 1]);
    }
}

// ---------------- launch ----------------
extern "C" void kernel_launch(void* const* d_in, const int* in_sizes, int n_in,
                              void* d_out, int out_size) {
    const int*   ids = (const int*)  d_in[0];
    const float* emb = (const float*)d_in[1];
    const float* liw = (const float*)d_in[2];
    const float* lib = (const float*)d_in[3];
    const float* cw  = (const float*)d_in[4];
    const float* cb  = (const float*)d_in[5];
    const float* lxw = (const float*)d_in[6];
    const float* lxb = (const float*)d_in[7];
    const float* ldw = (const float*)d_in[8];
    const float* ldb = (const float*)d_in[9];
    const float* low = (const float*)d_in[10];
    const float* lob = (const float*)d_in[11];
    const float* Dp  = (const float*)d_in[12];
    const float* bnw = (const float*)d_in[13];
    const float* fnw = (const float*)d_in[14];
    const float* hw  = (const float*)d_in[15];
    const float* hb  = (const float*)d_in[16];
    float* out = (float*)d_out;

    float *x, *xr, *u, *xdbl, *delta, *mo;
    cudaGetSymbolAddress((void**)&x,     g_x);
    cudaGetSymbolAddress((void**)&xr,    g_xr);
    cudaGetSymbolAddress((void**)&u,     g_u);
    cudaGetSymbolAddress((void**)&xdbl,  g_xdbl);
    cudaGetSymbolAddress((void**)&delta, g_delta);
    cudaGetSymbolAddress((void**)&mo,    g_mo);

    uint32_t *xp_h, *xp_l, *act_h, *act_l;
    uint32_t *liw_h, *liw_l, *ldw_h, *ldw_l, *low_h, *low_l, *hw_h;
    cudaGetSymbolAddress((void**)&xp_h,  g_xp_h);
    cudaGetSymbolAddress((void**)&xp_l,  g_xp_l);
    cudaGetSymbolAddress((void**)&act_h, g_act_h);
    cudaGetSymbolAddress((void**)&act_l, g_act_l);
    cudaGetSymbolAddress((void**)&liw_h, g_liw_h);
    cudaGetSymbolAddress((void**)&liw_l, g_liw_l);
    cudaGetSymbolAddress((void**)&ldw_h, g_ldw_h);
    cudaGetSymbolAddress((void**)&ldw_l, g_ldw_l);
    cudaGetSymbolAddress((void**)&low_h, g_low_h);
    cudaGetSymbolAddress((void**)&low_l, g_low_l);
    cudaGetSymbolAddress((void**)&hw_h,  g_hw_h);

    const int SM128  = 2 * (2 * 128 * 80 + 2 * 128 * 80);  // 81920 (bf16x3 BN=128)
    const int SM64   = 2 * (2 * 128 * 80 + 2 * 64 * 80);   // 61440 (bf16x3 BN=64)
    const int SMF128 = 3 * (128 + 128) * 80;               // 61440 (fp16 BN=128)
    cudaFuncSetAttribute((const void*)gemm_bf16x3<128, 0>,
                         cudaFuncAttributeMaxDynamicSharedMemorySize, SM128);
    cudaFuncSetAttribute((const void*)gemm_bf16x3<128, 1>,
                         cudaFuncAttributeMaxDynamicSharedMemorySize, SM128);
    cudaFuncSetAttribute((const void*)gemm_bf16x3<64, 0>,
                         cudaFuncAttributeMaxDynamicSharedMemorySize, SM64);
    cudaFuncSetAttribute((const void*)gemm_fp16<128>,
                         cudaFuncAttributeMaxDynamicSharedMemorySize, SMF128);

    embed_kernel<<<(BS * K2_M + 255) / 256, 256>>>(ids, emb, x, xp_h, xp_l);

    for (int l = 0; l < Ll; l++) {
        split_layer_kernel<<<(QT + 255) / 256, 256>>>(
            liw + (size_t)l * H2 * Mdim, ldw + (size_t)l * Hh * Rr,
            low + (size_t)l * Mdim * Hh,
            liw_h + (size_t)l * H2 * K2_M, liw_l + (size_t)l * H2 * K2_M,
            ldw_h + (size_t)l * Hh * K2_DT, ldw_l + (size_t)l * Hh * K2_DT,
            low_h + (size_t)l * Mdim * K2_H, low_l + (size_t)l * Mdim * K2_H);

        if (l == 0)
            split_hw_f16_kernel<<<((Vv * K2_M) / 4 + 255) / 256, 256>>>(hw, hw_h);

        // lin_in (absolute launch #5 when l=0 — profiled)
        gemm_bf16x3<128, 0><<<dim3(H2 / 128, BS / 128), 256, SM128>>>(
            xp_h, xp_l,
            liw_h + (size_t)l * H2 * K2_M, liw_l + (size_t)l * H2 * K2_M,
            K2_M, lib + (size_t)l * H2, xr, H2);

        conv_silu_kernel<<<(BS * (Hh / 4) + 255) / 256, 256>>>(
            xr, cw + (size_t)l * Hh * Kk, cb + (size_t)l * Hh, u);

        linx_kernel<<<(BS / 8) * (XD / 4), 256>>>(
            u, lxw + (size_t)l * XD * Hh, lxb + (size_t)l * XD, xdbl,
            act_h, act_l);

        gemm_bf16x3<128, 1><<<dim3(Hh / 128, BS / 128), 256, SM128>>>(
            act_h, act_l,
            ldw_h + (size_t)l * Hh * K2_DT, ldw_l + (size_t)l * Hh * K2_DT,
            K2_DT, ldb + (size_t)l * Hh, delta, Hh);

        scan_gate_kernel<<<(Bb * (Hh / 2) * 32 + 255) / 256, 256>>>(
            delta, u, xdbl, Dp + (size_t)l * Hh, xr, act_h, act_l);

        // lin_out: bf16x3 (precision-critical — feeds residual stream)
        gemm_bf16x3<64, 0><<<dim3(Mdim / 64, BS / 128), 256, SM64>>>(
            act_h, act_l,
            low_h + (size_t)l * Mdim * K2_H, low_l + (size_t)l * Mdim * K2_H,
            K2_H, lob + (size_t)l * Mdim, mo, Mdim);

        rmsnorm_add_kernel<<<BS, 256>>>(x, mo, bnw + (size_t)l * Mdim, xp_h, xp_l);
    }

    rmsnorm_final_kernel<<<BS, 256>>>(x, fnw, act_h);

    gemm_fp16<128><<<dim3(Vv / 128, BS / 128), 256, SMF128>>>(
        act_h, hw_h, K2_M, hb, out, Vv);
}

// round 13
// speedup vs baseline: 3.6359x; 1.2187x over previous
#include <cuda_runtime.h>
#include <cuda_bf16.h>
#include <cuda_fp16.h>
#include <math.h>
#include <stdint.h>

#define DEV_INLINE __device__ __forceinline__

// Problem constants
constexpr int Mdim = 768;
constexpr int Vv   = 32000;
constexpr int Rr   = 48;
constexpr int Nn   = 16;
constexpr int Kk   = 4;
constexpr int Ll   = 2;
constexpr int Hh   = 1536;
constexpr int Bb   = 2;
constexpr int Ss   = 1024;
constexpr int BS   = Bb * Ss;     // 2048
constexpr int H2   = 2 * Hh;      // 3072
constexpr int XD   = Rr + 2 * Nn; // 80

constexpr int K2_M  = Mdim / 2;   // 384
constexpr int K2_H  = Hh / 2;     // 768
constexpr int K2_DT = 32;         // 48/2=24 -> pad 32

// ---------------- fp32 scratch ----------------
__device__ float g_x    [BS * Mdim];
__device__ float g_xr   [BS * H2];
__device__ float g_u    [BS * Hh];
__device__ float g_xdbl [BS * XD];
__device__ float g_delta[BS * Hh];
__device__ float g_mo   [BS * Mdim];

// ---------------- packed 16-bit planes ----------------
__device__ __align__(16) uint32_t g_xp_h [BS * K2_M];
__device__ __align__(16) uint32_t g_xp_l [BS * K2_M];
__device__ __align__(16) uint32_t g_act_h[BS * K2_H];
__device__ __align__(16) uint32_t g_act_l[BS * K2_H];
__device__ __align__(16) uint32_t g_liw_h[Ll * H2 * K2_M];
__device__ __align__(16) uint32_t g_liw_l[Ll * H2 * K2_M];
__device__ __align__(16) uint32_t g_ldw_h[Ll * Hh * K2_DT];
__device__ __align__(16) uint32_t g_ldw_l[Ll * Hh * K2_DT];
__device__ __align__(16) uint32_t g_low_h[Ll * Mdim * K2_H];
__device__ __align__(16) uint32_t g_low_l[Ll * Mdim * K2_H];
__device__ __align__(16) uint32_t g_hw_h [Vv * K2_M];          // fp16 single

// ---------------- helpers ----------------
DEV_INLINE float siluf(float v)     { return v / (1.f + expf(-v)); }
DEV_INLINE float softplusf(float v) { return v > 20.f ? v : log1pf(expf(v)); }

DEV_INLINE float warp_sum(float v) {
    #pragma unroll
    for (int o = 16; o; o >>= 1) v += __shfl_xor_sync(0xffffffffu, v, o);
    return v;
}

DEV_INLINE uint32_t packsplit(float f0, float f1, uint32_t& lo) {
    __nv_bfloat16 h0 = __float2bfloat16(f0);
    __nv_bfloat16 h1 = __float2bfloat16(f1);
    __nv_bfloat16 l0 = __float2bfloat16(f0 - __bfloat162float(h0));
    __nv_bfloat16 l1 = __float2bfloat16(f1 - __bfloat162float(h1));
    lo = (uint32_t)__bfloat16_as_ushort(l0) | ((uint32_t)__bfloat16_as_ushort(l1) << 16);
    return (uint32_t)__bfloat16_as_ushort(h0) | ((uint32_t)__bfloat16_as_ushort(h1) << 16);
}

DEV_INLINE uint32_t pack_f16(float f0, float f1) {
    __half2 h = __floats2half2_rn(f0, f1);
    return *(uint32_t*)&h;
}

DEV_INLINE void packsplit8(float4 a, float4 b, uint4& hi, uint4& lo) {
    hi.x = packsplit(a.x, a.y, lo.x);
    hi.y = packsplit(a.z, a.w, lo.y);
    hi.z = packsplit(b.x, b.y, lo.z);
    hi.w = packsplit(b.z, b.w, lo.w);
}

DEV_INLINE void mma_bf16(float* d, const uint32_t* a, const uint32_t* b) {
    asm volatile(
        "mma.sync.aligned.m16n8k16.row.col.f32.bf16.bf16.f32 "
        "{%0,%1,%2,%3}, {%4,%5,%6,%7}, {%8,%9}, {%0,%1,%2,%3};"
        : "+f"(d[0]), "+f"(d[1]), "+f"(d[2]), "+f"(d[3])
        : "r"(a[0]), "r"(a[1]), "r"(a[2]), "r"(a[3]),
          "r"(b[0]), "r"(b[1]));
}

DEV_INLINE void mma_f16(float* d, const uint32_t* a, const uint32_t* b) {
    asm volatile(
        "mma.sync.aligned.m16n8k16.row.col.f32.f16.f16.f32 "
        "{%0,%1,%2,%3}, {%4,%5,%6,%7}, {%8,%9}, {%0,%1,%2,%3};"
        : "+f"(d[0]), "+f"(d[1]), "+f"(d[2]), "+f"(d[3])
        : "r"(a[0]), "r"(a[1]), "r"(a[2]), "r"(a[3]),
          "r"(b[0]), "r"(b[1]));
}

DEV_INLINE void ldsm_x4(uint32_t& r0, uint32_t& r1, uint32_t& r2, uint32_t& r3,
                        uint32_t addr) {
    asm volatile("ldmatrix.sync.aligned.m8n8.x4.shared.b16 {%0,%1,%2,%3}, [%4];"
                 : "=r"(r0), "=r"(r1), "=r"(r2), "=r"(r3) : "r"(addr));
}

DEV_INLINE void cp_async16(uint32_t dst, const void* src) {
    asm volatile("cp.async.cg.shared.global [%0], [%1], 16;" :: "r"(dst), "l"(src));
}
DEV_INLINE void cp_commit() { asm volatile("cp.async.commit_group;"); }
template<int N> DEV_INLINE void cp_wait() {
    asm volatile("cp.async.wait_group %0;" :: "n"(N));
}

// ---------------- fused per-layer weight split (vectorized) ----------------
constexpr int SEG0 = H2 * K2_M;
constexpr int SEG1 = Hh * K2_DT;
constexpr int SEG2 = Mdim * K2_H;
constexpr int Q0 = SEG0 / 4;
constexpr int Q1 = SEG1 / 4;
constexpr int Q2 = SEG2 / 4;
constexpr int QT = Q0 + Q1 + Q2;

__global__ void split_layer_kernel(const float* __restrict__ liw,
                                   const float* __restrict__ ldw,
                                   const float* __restrict__ low,
                                   uint32_t* __restrict__ liw_h, uint32_t* __restrict__ liw_l,
                                   uint32_t* __restrict__ ldw_h, uint32_t* __restrict__ ldw_l,
                                   uint32_t* __restrict__ low_h, uint32_t* __restrict__ low_l) {
    int idx = blockIdx.x * blockDim.x + threadIdx.x;
    if (idx >= QT) return;
    if (idx < Q0) {
        int u = idx * 4;
        int r = u / K2_M, j = u - r * K2_M;
        const float4* p = (const float4*)(liw + (size_t)r * Mdim + 2 * j);
        uint4 hi, lo;
        packsplit8(p[0], p[1], hi, lo);
        *(uint4*)(liw_h + u) = hi;
        *(uint4*)(liw_l + u) = lo;
    } else if (idx < Q0 + Q1) {
        int u = (idx - Q0) * 4;
        int r = u / K2_DT, j = u - r * K2_DT;
        uint4 hi, lo;
        if (2 * j >= Rr) {
            hi = make_uint4(0, 0, 0, 0);
            lo = make_uint4(0, 0, 0, 0);
        } else {
            const float4* p = (const float4*)(ldw + (size_t)r * Rr + 2 * j);
            packsplit8(p[0], p[1], hi, lo);
        }
        *(uint4*)(ldw_h + u) = hi;
        *(uint4*)(ldw_l + u) = lo;
    } else {
        int u = (idx - Q0 - Q1) * 4;
        int r = u / K2_H, j = u - r * K2_H;
        const float4* p = (const float4*)(low + (size_t)r * Hh + 2 * j);
        uint4 hi, lo;
        packsplit8(p[0], p[1], hi, lo);
        *(uint4*)(low_h + u) = hi;
        *(uint4*)(low_l + u) = lo;
    }
}

// ---------------- fp16 split for head weights (vectorized) ----------------
__global__ void split_hw_f16_kernel(const float* __restrict__ in,
                                    uint32_t* __restrict__ out) {
    int idx = blockIdx.x * blockDim.x + threadIdx.x;
    if (idx >= (Vv * K2_M) / 4) return;
    int u = idx * 4;
    int r = u / K2_M, j = u - r * K2_M;
    const float4* p = (const float4*)(in + (size_t)r * Mdim + 2 * j);
    float4 a = p[0], b = p[1];
    uint4 o;
    o.x = pack_f16(a.x, a.y);
    o.y = pack_f16(a.z, a.w);
    o.z = pack_f16(b.x, b.y);
    o.w = pack_f16(b.z, b.w);
    *(uint4*)(out + u) = o;
}

// ---------------- embedding gather + planes ----------------
__global__ void embed_kernel(const int* __restrict__ ids,
                             const float* __restrict__ emb,
                             float* __restrict__ x,
                             uint32_t* __restrict__ xph,
                             uint32_t* __restrict__ xpl) {
    int idx = blockIdx.x * blockDim.x + threadIdx.x;
    if (idx >= BS * K2_M) return;
    int row = idx / K2_M;
    int m2  = idx - row * K2_M;
    const float* e = emb + (size_t)ids[row] * Mdim + 2 * m2;
    float f0 = e[0], f1 = e[1];
    x[(size_t)row * Mdim + 2 * m2]     = f0;
    x[(size_t)row * Mdim + 2 * m2 + 1] = f1;
    uint32_t l;
    uint32_t h = packsplit(f0, f1, l);
    xph[idx] = h;
    xpl[idx] = l;
}

// ---------------- bf16x3 GEMM, 2-stage double buffer, 2 CTAs/SM ----------
template<int BN, int ACT>
__global__ __launch_bounds__(256, 2)
void gemm_bf16x3(const uint32_t* __restrict__ Ah, const uint32_t* __restrict__ Al,
                 const uint32_t* __restrict__ Wh, const uint32_t* __restrict__ Wl,
                 int K2,
                 const float* __restrict__ bias,
                 float* __restrict__ C, int ldc) {
    constexpr int NTt  = BN / 32;
    constexpr int ROWB = 80;
    constexpr int APB  = 128 * ROWB;
    constexpr int WPB  = BN * ROWB;
    constexpr int STGB = 2 * APB + 2 * WPB;
    constexpr int NCH  = (256 + 2 * BN) * 4 / 256;

    extern __shared__ __align__(16) uint32_t smu[];

    const int tid  = threadIdx.x;
    const int lane = tid & 31;
    const int wid  = tid >> 5;
    const int wm   = wid >> 2;
    const int wn   = wid & 3;
    const int i0   = blockIdx.y * 128;
    const int j0   = blockIdx.x * BN;
    const int lq   = lane & 3;
    const int lg   = lane >> 2;

    const uint32_t sb = (uint32_t)__cvta_generic_to_shared(smu);

    const uint32_t* src[NCH];
    uint32_t dst[NCH];
    #pragma unroll
    for (int uu = 0; uu < NCH; uu++) {
        int c  = uu * 256 + tid;
        int r2 = c >> 2;
        int q  = c & 3;
        const uint32_t* gbase;
        int pofs, r;
        if (r2 < 128)            { r = r2;            gbase = Ah + (size_t)i0 * K2; pofs = 0; }
        else if (r2 < 256)       { r = r2 - 128;      gbase = Al + (size_t)i0 * K2; pofs = APB; }
        else if (r2 < 256 + BN)  { r = r2 - 256;      gbase = Wh + (size_t)j0 * K2; pofs = 2 * APB; }
        else                     { r = r2 - 256 - BN; gbase = Wl + (size_t)j0 * K2; pofs = 2 * APB + WPB; }
        src[uu] = gbase + (size_t)r * K2 + q * 4;
        dst[uu] = sb + pofs + r * ROWB + q * 16;
    }

    const uint32_t aRow = (uint32_t)((wm * 64 + (lane & 15)) * ROWB + ((lane >> 4) << 4));
    const uint32_t bRow = (uint32_t)((wn * (NTt * 8) + ((lane >> 4) << 3) + (lane & 7)) * ROWB
                                     + (((lane >> 3) & 1) << 4));

    float acc[4][NTt][4];
    #pragma unroll
    for (int m = 0; m < 4; m++)
        #pragma unroll
        for (int n = 0; n < NTt; n++)
            #pragma unroll
            for (int c = 0; c < 4; c++) acc[m][n][c] = 0.f;

    const int nk = K2 >> 4;

    #pragma unroll
    for (int uu = 0; uu < NCH; uu++) cp_async16(dst[uu], src[uu]);
    cp_commit();

    for (int t = 0; t < nk; t++) {
        cp_wait<0>();
        __syncthreads();
        if (t + 1 < nk) {
            uint32_t so = (uint32_t)((t + 1) & 1) * STGB;
            int ko = (t + 1) * 16;
            #pragma unroll
            for (int uu = 0; uu < NCH; uu++)
                cp_async16(dst[uu] + so, src[uu] + ko);
            cp_commit();
        }

        const uint32_t st = sb + (uint32_t)(t & 1) * STGB;

        #pragma unroll
        for (int h = 0; h < 2; h++) {
            uint32_t ah[4][4], al[4][4], bh[NTt][2], bl[NTt][2];
            #pragma unroll
            for (int m = 0; m < 4; m++) {
                uint32_t a0 = st + aRow + m * (16 * ROWB) + h * 32;
                ldsm_x4(ah[m][0], ah[m][1], ah[m][2], ah[m][3], a0);
                ldsm_x4(al[m][0], al[m][1], al[m][2], al[m][3], a0 + APB);
            }
            #pragma unroll
            for (int j = 0; j < NTt / 2; j++) {
                uint32_t b0 = st + 2 * APB + bRow + j * (16 * ROWB) + h * 32;
                ldsm_x4(bh[2*j][0], bh[2*j][1], bh[2*j+1][0], bh[2*j+1][1], b0);
                ldsm_x4(bl[2*j][0], bl[2*j][1], bl[2*j+1][0], bl[2*j+1][1], b0 + WPB);
            }
            #pragma unroll
            for (int m = 0; m < 4; m++)
                #pragma unroll
                for (int n = 0; n < NTt; n++)
                    mma_bf16(acc[m][n], ah[m], bh[n]);
            #pragma unroll
            for (int m = 0; m < 4; m++)
                #pragma unroll
                for (int n = 0; n < NTt; n++)
                    mma_bf16(acc[m][n], ah[m], bl[n]);
            #pragma unroll
            for (int m = 0; m < 4; m++)
                #pragma unroll
                for (int n = 0; n < NTt; n++)
                    mma_bf16(acc[m][n], al[m], bh[n]);
        }
    }

    #pragma unroll
    for (int m = 0; m < 4; m++) {
        int gi = i0 + wm * 64 + m * 16 + lg;
        #pragma unroll
        for (int n = 0; n < NTt; n++) {
            int gj = j0 + wn * (NTt * 8) + n * 8 + 2 * lq;
            float b0 = bias[gj], b1 = bias[gj + 1];
            float v0 = acc[m][n][0] + b0;
            float v1 = acc[m][n][1] + b1;
            float v2 = acc[m][n][2] + b0;
            float v3 = acc[m][n][3] + b1;
            if (ACT == 1) {
                v0 = softplusf(v0); v1 = softplusf(v1);
                v2 = softplusf(v2); v3 = softplusf(v3);
            }
            *(float2*)(C + (size_t)gi * ldc + gj)       = make_float2(v0, v1);
            *(float2*)(C + (size_t)(gi + 8) * ldc + gj) = make_float2(v2, v3);
        }
    }
}

// ---------------- fp16 single-pass GEMM (head), 3-stage ----------------
template<int BN>
__global__ __launch_bounds__(256, 2)
void gemm_fp16(const uint32_t* __restrict__ Ah, const uint32_t* __restrict__ Wh,
               int K2,
               const float* __restrict__ bias,
               float* __restrict__ C, int ldc) {
    constexpr int NTt  = BN / 32;
    constexpr int ROWB = 80;
    constexpr int APB  = 128 * ROWB;
    constexpr int WPB  = BN * ROWB;
    constexpr int STGB = APB + WPB;
    constexpr int NCH  = (128 + BN) * 4 / 256;

    extern __shared__ __align__(16) uint32_t smu[];

    const int tid  = threadIdx.x;
    const int lane = tid & 31;
    const int wid  = tid >> 5;
    const int wm   = wid >> 2;
    const int wn   = wid & 3;
    const int i0   = blockIdx.y * 128;
    const int j0   = blockIdx.x * BN;
    const int lq   = lane & 3;
    const int lg   = lane >> 2;

    const uint32_t sb = (uint32_t)__cvta_generic_to_shared(smu);

    const uint32_t* src[NCH];
    uint32_t dst[NCH];
    #pragma unroll
    for (int uu = 0; uu < NCH; uu++) {
        int c  = uu * 256 + tid;
        int r2 = c >> 2;
        int q  = c & 3;
        const uint32_t* gbase;
        int pofs, r;
        if (r2 < 128) { r = r2;       gbase = Ah + (size_t)i0 * K2; pofs = 0; }
        else          { r = r2 - 128; gbase = Wh + (size_t)j0 * K2; pofs = APB; }
        src[uu] = gbase + (size_t)r * K2 + q * 4;
        dst[uu] = sb + pofs + r * ROWB + q * 16;
    }

    const uint32_t aRow = (uint32_t)((wm * 64 + (lane & 15)) * ROWB + ((lane >> 4) << 4));
    const uint32_t bRow = (uint32_t)((wn * (NTt * 8) + ((lane >> 4) << 3) + (lane & 7)) * ROWB
                                     + (((lane >> 3) & 1) << 4));

    float acc[4][NTt][4];
    #pragma unroll
    for (int m = 0; m < 4; m++)
        #pragma unroll
        for (int n = 0; n < NTt; n++)
            #pragma unroll
            for (int c = 0; c < 4; c++) acc[m][n][c] = 0.f;

    const int nk = K2 >> 4;

    #pragma unroll
    for (int uu = 0; uu < NCH; uu++) cp_async16(dst[uu], src[uu]);
    cp_commit();
    #pragma unroll
    for (int uu = 0; uu < NCH; uu++) cp_async16(dst[uu] + STGB, src[uu] + 16);
    cp_commit();

    for (int t = 0; t < nk; t++) {
        if (t + 1 < nk) { cp_wait<1>(); } else { cp_wait<0>(); }
        __syncthreads();
        if (t + 2 < nk) {
            uint32_t so = (uint32_t)((t + 2) % 3) * STGB;
            int ko = (t + 2) * 16;
            #pragma unroll
            for (int uu = 0; uu < NCH; uu++)
                cp_async16(dst[uu] + so, src[uu] + ko);
            cp_commit();
        }

        const uint32_t st = sb + (uint32_t)(t % 3) * STGB;

        uint32_t ah2[2][4][4], bh2[2][NTt][2];
        #pragma unroll
        for (int h = 0; h < 2; h++) {
            #pragma unroll
            for (int m = 0; m < 4; m++) {
                uint32_t a0 = st + aRow + m * (16 * ROWB) + h * 32;
                ldsm_x4(ah2[h][m][0], ah2[h][m][1], ah2[h][m][2], ah2[h][m][3], a0);
            }
            #pragma unroll
            for (int j = 0; j < NTt / 2; j++) {
                uint32_t b0 = st + APB + bRow + j * (16 * ROWB) + h * 32;
                ldsm_x4(bh2[h][2*j][0], bh2[h][2*j][1],
                        bh2[h][2*j+1][0], bh2[h][2*j+1][1], b0);
            }
        }
        #pragma unroll
        for (int h = 0; h < 2; h++)
            #pragma unroll
            for (int m = 0; m < 4; m++)
                #pragma unroll
                for (int n = 0; n < NTt; n++)
                    mma_f16(acc[m][n], ah2[h][m], bh2[h][n]);
    }

    #pragma unroll
    for (int m = 0; m < 4; m++) {
        int gi = i0 + wm * 64 + m * 16 + lg;
        #pragma unroll
        for (int n = 0; n < NTt; n++) {
            int gj = j0 + wn * (NTt * 8) + n * 8 + 2 * lq;
            float b0 = bias[gj], b1 = bias[gj + 1];
            *(float2*)(C + (size_t)gi * ldc + gj) =
                make_float2(acc[m][n][0] + b0, acc[m][n][1] + b1);
            *(float2*)(C + (size_t)(gi + 8) * ldc + gj) =
                make_float2(acc[m][n][2] + b0, acc[m][n][3] + b1);
        }
    }
}

// ---------------- lin_x: u-resident warp-per-row + fused dt emit ----------
__global__ __launch_bounds__(256)
void linx_kernel(const float* __restrict__ u,
                 const float* __restrict__ w,
                 const float* __restrict__ bias,
                 float* __restrict__ xdbl,
                 uint32_t* __restrict__ dth,
                 uint32_t* __restrict__ dtl) {
    int wid  = threadIdx.x >> 5;
    int lane = threadIdx.x & 31;
    int i = blockIdx.x * 8 + wid;

    const float4* u4 = (const float4*)(u + (size_t)i * Hh);
    float4 ur[12];
    #pragma unroll
    for (int t = 0; t < 12; t++) ur[t] = u4[t * 32 + lane];

    #pragma unroll 2
    for (int j0 = 0; j0 < XD; j0 += 4) {
        float p0 = 0.f, p1 = 0.f, p2 = 0.f, p3 = 0.f;
        const float4* w0 = (const float4*)(w + (size_t)(j0 + 0) * Hh);
        const float4* w1 = (const float4*)(w + (size_t)(j0 + 1) * Hh);
        const float4* w2 = (const float4*)(w + (size_t)(j0 + 2) * Hh);
        const float4* w3 = (const float4*)(w + (size_t)(j0 + 3) * Hh);
        #pragma unroll
        for (int t = 0; t < 12; t++) {
            int k = t * 32 + lane;
            float4 a = w0[k];
            p0 += ur[t].x * a.x + ur[t].y * a.y + ur[t].z * a.z + ur[t].w * a.w;
            a = w1[k];
            p1 += ur[t].x * a.x + ur[t].y * a.y + ur[t].z * a.z + ur[t].w * a.w;
            a = w2[k];
            p2 += ur[t].x * a.x + ur[t].y * a.y + ur[t].z * a.z + ur[t].w * a.w;
            a = w3[k];
            p3 += ur[t].x * a.x + ur[t].y * a.y + ur[t].z * a.z + ur[t].w * a.w;
        }
        p0 = warp_sum(p0); p1 = warp_sum(p1);
        p2 = warp_sum(p2); p3 = warp_sum(p3);
        if (lane == 0) {
            float v0 = p0 + bias[j0];
            float v1 = p1 + bias[j0 + 1];
            float v2 = p2 + bias[j0 + 2];
            float v3 = p3 + bias[j0 + 3];
            float* o = xdbl + (size_t)i * XD + j0;
            o[0] = v0; o[1] = v1; o[2] = v2; o[3] = v3;
            if (j0 < Rr) {
                int j2 = j0 >> 1;
                uint32_t l0, l1;
                uint32_t h0 = packsplit(v0, v1, l0);
                uint32_t h1 = packsplit(v2, v3, l1);
                dth[(size_t)i * K2_DT + j2]     = h0;
                dtl[(size_t)i * K2_DT + j2]     = l0;
                dth[(size_t)i * K2_DT + j2 + 1] = h1;
                dtl[(size_t)i * K2_DT + j2 + 1] = l1;
            }
        }
    }
    if (lane < 8) {   // zero K padding cols 24..31
        dth[(size_t)i * K2_DT + 24 + lane] = 0;
        dtl[(size_t)i * K2_DT + 24 + lane] = 0;
    }
}

// ---------------- depthwise causal conv (K=4) + silu, float4 --------------
__global__ void conv_silu_kernel(const float* __restrict__ xr,
                                 const float* __restrict__ cw,
                                 const float* __restrict__ cb,
                                 float* __restrict__ u) {
    int idx = blockIdx.x * blockDim.x + threadIdx.x;
    if (idx >= BS * (Hh / 4)) return;
    int h4  = idx % (Hh / 4);
    int row = idx / (Hh / 4);
    int h   = h4 * 4;
    int s   = row % Ss;
    int b   = row / Ss;

    const float4* cw4 = (const float4*)cw;
    float4 t0 = cw4[h], t1 = cw4[h + 1], t2 = cw4[h + 2], t3 = cw4[h + 3];
    float4 acc = ((const float4*)cb)[h4];

    #pragma unroll
    for (int k = 0; k < Kk; k++) {
        int sp = s - (Kk - 1) + k;
        if (sp >= 0) {
            float4 xv = *(const float4*)(xr + (size_t)(b * Ss + sp) * H2 + h);
            float ta = (k == 0) ? t0.x : (k == 1) ? t0.y : (k == 2) ? t0.z : t0.w;
            float tb = (k == 0) ? t1.x : (k == 1) ? t1.y : (k == 2) ? t1.z : t1.w;
            float tc = (k == 0) ? t2.x : (k == 1) ? t2.y : (k == 2) ? t2.z : t2.w;
            float td = (k == 0) ? t3.x : (k == 1) ? t3.y : (k == 2) ? t3.z : t3.w;
            acc.x += ta * xv.x;
            acc.y += tb * xv.y;
            acc.z += tc * xv.z;
            acc.w += td * xv.w;
        }
    }
    float4 o;
    o.x = siluf(acc.x); o.y = siluf(acc.y);
    o.z = siluf(acc.z); o.w = siluf(acc.w);
    *(float4*)(u + (size_t)row * Hh + h) = o;
}

// ---------------- scan + gate, depth-4 load prefetch, bf16 hi/lo y out -----
__global__ void scan_gate_kernel(const float* __restrict__ delta,
                                 const float* __restrict__ u,
                                 const float* __restrict__ xdbl,
                                 const float* __restrict__ Dp,
                                 const float* __restrict__ xr,
                                 uint32_t* __restrict__ yh,
                                 uint32_t* __restrict__ yl) {
    int gwarp = (blockIdx.x * blockDim.x + threadIdx.x) >> 5;
    if (gwarp >= Bb * (Hh / 2)) return;
    int lane = threadIdx.x & 31;
    int half = lane >> 4;
    int n    = lane & 15;
    int b    = gwarp / (Hh / 2);
    int hp   = gwarp % (Hh / 2);
    int h    = hp * 2 + half;

    const float An = -(float)(n + 1);
    const float Dh = Dp[h];
    float state = 0.f;

    const int base = b * Ss;

    // 4-deep register prefetch buffers
    float pd[4], pu[4], pB[4], pC[4], pr[4];
    #pragma unroll
    for (int k = 0; k < 4; k++) {
        int r = base + k;
        pd[k] = __ldg(delta + (size_t)r * Hh + h);
        pu[k] = __ldg(u + (size_t)r * Hh + h);
        pB[k] = __ldg(xdbl + r * XD + Rr + n);
        pC[k] = __ldg(xdbl + r * XD + Rr + Nn + n);
        pr[k] = __ldg(xr + (size_t)r * H2 + Hh + h);
    }

    // dA/dBu pipeline: 1 ahead
    float dA  = expf(pd[0] * An);
    float dBu = pd[0] * pB[0] * pu[0];

    #pragma unroll 4
    for (int s = 0; s < Ss; s++) {
        const int slot = s & 3;
        const int ns   = (s + 1) & 3;
        int row = base + s;

        float uv  = pu[slot];
        float Cn  = pC[slot];
        float res = pr[slot];

        // recurrence (critical path: one FFMA)
        state = dA * state + dBu;

        // prefetch s+4 into this slot (4-iteration latency slack)
        if (s + 4 < Ss) {
            int r = row + 4;
            pd[slot] = __ldg(delta + (size_t)r * Hh + h);
            pu[slot] = __ldg(u + (size_t)r * Hh + h);
            pB[slot] = __ldg(xdbl + r * XD + Rr + n);
            pC[slot] = __ldg(xdbl + r * XD + Rr + Nn + n);
            pr[slot] = __ldg(xr + (size_t)r * H2 + Hh + h);
        }

        // next step's dA/dBu (slot ns loaded >=3 iterations ago)
        dA  = expf(pd[ns] * An);
        dBu = pd[ns] * pB[ns] * pu[ns];

        // output reduction
        float val = state * Cn;
        val += __shfl_xor_sync(0xffffffffu, val, 8);
        val += __shfl_xor_sync(0xffffffffu, val, 4);
        val += __shfl_xor_sync(0xffffffffu, val, 2);
        val += __shfl_xor_sync(0xffffffffu, val, 1);
        float yv = (val + uv * Dh) * siluf(res);
        float y1 = __shfl_sync(0xffffffffu, yv, 16);
        if (lane == 0) {
            uint32_t lo;
            uint32_t hi = packsplit(yv, y1, lo);
            yh[(size_t)row * K2_H + hp] = hi;
            yl[(size_t)row * K2_H + hp] = lo;
        }
    }
}

// ---------------- x += rmsnorm(mo) * w ; emit x planes ----------------
__global__ void rmsnorm_add_kernel(float* __restrict__ x,
                                   const float* __restrict__ mo,
                                   const float* __restrict__ w,
                                   uint32_t* __restrict__ xph,
                                   uint32_t* __restrict__ xpl) {
    int row = blockIdx.x;
    const float* r = mo + (size_t)row * Mdim;
    float ss = 0.f;
    for (int m = threadIdx.x; m < Mdim; m += blockDim.x) {
        float v = r[m];
        ss += v * v;
    }
    __shared__ float sh[8];
    ss = warp_sum(ss);
    int wid = threadIdx.x >> 5, lane = threadIdx.x & 31;
    if (lane == 0) sh[wid] = ss;
    __syncthreads();
    if (wid == 0) {
        float v = (lane < (int)(blockDim.x >> 5)) ? sh[lane] : 0.f;
        v = warp_sum(v);
        if (lane == 0) sh[0] = v;
    }
    __syncthreads();
    float scale = rsqrtf(sh[0] / (float)Mdim + 1e-15f);
    float* xp = x + (size_t)row * Mdim;
    for (int m2 = threadIdx.x; m2 < K2_M; m2 += blockDim.x) {
        int m = 2 * m2;
        float v0 = xp[m]     + r[m]     * scale * w[m];
        float v1 = xp[m + 1] + r[m + 1] * scale * w[m + 1];
        xp[m] = v0; xp[m + 1] = v1;
        uint32_t lo;
        uint32_t hi = packsplit(v0, v1, lo);
        xph[(size_t)row * K2_M + m2] = hi;
        xpl[(size_t)row * K2_M + m2] = lo;
    }
}

// ---------------- final rmsnorm -> fp16 planes (head input) ----------------
__global__ void rmsnorm_final_kernel(const float* __restrict__ x,
                                     const float* __restrict__ w,
                                     uint32_t* __restrict__ xnf) {
    int row = blockIdx.x;
    const float* r = x + (size_t)row * Mdim;
    float ss = 0.f;
    for (int m = threadIdx.x; m < Mdim; m += blockDim.x) {
        float v = r[m];
        ss += v * v;
    }
    __shared__ float sh[8];
    ss = warp_sum(ss);
    int wid = threadIdx.x >> 5, lane = threadIdx.x & 31;
    if (lane == 0) sh[wid] = ss;
    __syncthreads();
    if (wid == 0) {
        float v = (lane < (int)(blockDim.x >> 5)) ? sh[lane] : 0.f;
        v = warp_sum(v);
        if (lane == 0) sh[0] = v;
    }
    __syncthreads();
    float scale = rsqrtf(sh[0] / (float)Mdim + 1e-15f);
    for (int m2 = threadIdx.x; m2 < K2_M; m2 += blockDim.x) {
        int m = 2 * m2;
        xnf[(size_t)row * K2_M + m2] =
            pack_f16(r[m] * scale * w[m], r[m + 1] * scale * w[m + 1]);
    }
}

// ---------------- launch ----------------
extern "C" void kernel_launch(void* const* d_in, const int* in_sizes, int n_in,
                              void* d_out, int out_size) {
    const int*   ids = (const int*)  d_in[0];
    const float* emb = (const float*)d_in[1];
    const float* liw = (const float*)d_in[2];
    const float* lib = (const float*)d_in[3];
    const float* cw  = (const float*)d_in[4];
    const float* cb  = (const float*)d_in[5];
    const float* lxw = (const float*)d_in[6];
    const float* lxb = (const float*)d_in[7];
    const float* ldw = (const float*)d_in[8];
    const float* ldb = (const float*)d_in[9];
    const float* low = (const float*)d_in[10];
    const float* lob = (const float*)d_in[11];
    const float* Dp  = (const float*)d_in[12];
    const float* bnw = (const float*)d_in[13];
    const float* fnw = (const float*)d_in[14];
    const float* hw  = (const float*)d_in[15];
    const float* hb  = (const float*)d_in[16];
    float* out = (float*)d_out;

    float *x, *xr, *u, *xdbl, *delta, *mo;
    cudaGetSymbolAddress((void**)&x,     g_x);
    cudaGetSymbolAddress((void**)&xr,    g_xr);
    cudaGetSymbolAddress((void**)&u,     g_u);
    cudaGetSymbolAddress((void**)&xdbl,  g_xdbl);
    cudaGetSymbolAddress((void**)&delta, g_delta);
    cudaGetSymbolAddress((void**)&mo,    g_mo);

    uint32_t *xp_h, *xp_l, *act_h, *act_l;
    uint32_t *liw_h, *liw_l, *ldw_h, *ldw_l, *low_h, *low_l, *hw_h;
    cudaGetSymbolAddress((void**)&xp_h,  g_xp_h);
    cudaGetSymbolAddress((void**)&xp_l,  g_xp_l);
    cudaGetSymbolAddress((void**)&act_h, g_act_h);
    cudaGetSymbolAddress((void**)&act_l, g_act_l);
    cudaGetSymbolAddress((void**)&liw_h, g_liw_h);
    cudaGetSymbolAddress((void**)&liw_l, g_liw_l);
    cudaGetSymbolAddress((void**)&ldw_h, g_ldw_h);
    cudaGetSymbolAddress((void**)&ldw_l, g_ldw_l);
    cudaGetSymbolAddress((void**)&low_h, g_low_h);
    cudaGetSymbolAddress((void**)&low_l, g_low_l);
    cudaGetSymbolAddress((void**)&hw_h,  g_hw_h);

    const int SM128  = 2 * (2 * 128 * 80 + 2 * 128 * 80);  // 81920
    const int SM64   = 2 * (2 * 128 * 80 + 2 * 64 * 80);   // 61440
    const int SMF128 = 3 * (128 + 128) * 80;               // 61440
    cudaFuncSetAttribute((const void*)gemm_bf16x3<128, 0>,
                         cudaFuncAttributeMaxDynamicSharedMemorySize, SM128);
    cudaFuncSetAttribute((const void*)gemm_bf16x3<128, 1>,
                         cudaFuncAttributeMaxDynamicSharedMemorySize, SM128);
    cudaFuncSetAttribute((const void*)gemm_bf16x3<64, 0>,
                         cudaFuncAttributeMaxDynamicSharedMemorySize, SM64);
    cudaFuncSetAttribute((const void*)gemm_fp16<128>,
                         cudaFuncAttributeMaxDynamicSharedMemorySize, SMF128);

    embed_kernel<<<(BS * K2_M + 255) / 256, 256>>>(ids, emb, x, xp_h, xp_l);

    for (int l = 0; l < Ll; l++) {
        split_layer_kernel<<<(QT + 255) / 256, 256>>>(
            liw + (size_t)l * H2 * Mdim, ldw + (size_t)l * Hh * Rr,
            low + (size_t)l * Mdim * Hh,
            liw_h + (size_t)l * H2 * K2_M, liw_l + (size_t)l * H2 * K2_M,
            ldw_h + (size_t)l * Hh * K2_DT, ldw_l + (size_t)l * Hh * K2_DT,
            low_h + (size_t)l * Mdim * K2_H, low_l + (size_t)l * Mdim * K2_H);

        if (l == 0)
            split_hw_f16_kernel<<<((Vv * K2_M) / 4 + 255) / 256, 256>>>(hw, hw_h);

        // lin_in (absolute launch #5 when l=0 — profiled)
        gemm_bf16x3<128, 0><<<dim3(H2 / 128, BS / 128), 256, SM128>>>(
            xp_h, xp_l,
            liw_h + (size_t)l * H2 * K2_M, liw_l + (size_t)l * H2 * K2_M,
            K2_M, lib + (size_t)l * H2, xr, H2);

        conv_silu_kernel<<<(BS * (Hh / 4) + 255) / 256, 256>>>(
            xr, cw + (size_t)l * Hh * Kk, cb + (size_t)l * Hh, u);

        linx_kernel<<<BS / 8, 256>>>(
            u, lxw + (size_t)l * XD * Hh, lxb + (size_t)l * XD, xdbl,
            act_h, act_l);

        gemm_bf16x3<128, 1><<<dim3(Hh / 128, BS / 128), 256, SM128>>>(
            act_h, act_l,
            ldw_h + (size_t)l * Hh * K2_DT, ldw_l + (size_t)l * Hh * K2_DT,
            K2_DT, ldb + (size_t)l * Hh, delta, Hh);

        scan_gate_kernel<<<(Bb * (Hh / 2) * 32 + 255) / 256, 256>>>(
            delta, u, xdbl, Dp + (size_t)l * Hh, xr, act_h, act_l);

        // lin_out: bf16x3 (precision-critical — feeds residual stream)
        gemm_bf16x3<64, 0><<<dim3(Mdim / 64, BS / 128), 256, SM64>>>(
            act_h, act_l,
            low_h + (size_t)l * Mdim * K2_H, low_l + (size_t)l * Mdim * K2_H,
            K2_H, lob + (size_t)l * Mdim, mo, Mdim);

        rmsnorm_add_kernel<<<BS, 256>>>(x, mo, bnw + (size_t)l * Mdim, xp_h, xp_l);
    }

    rmsnorm_final_kernel<<<BS, 256>>>(x, fnw, act_h);

    gemm_fp16<128><<<dim3(Vv / 128, BS / 128), 256, SMF128>>>(
        act_h, hw_h, K2_M, hb, out, Vv);
}

// round 14
// speedup vs baseline: 4.1714x; 1.1473x over previous
#include <cuda_runtime.h>
#include <cuda_bf16.h>
#include <cuda_fp16.h>
#include <math.h>
#include <stdint.h>

#define DEV_INLINE __device__ __forceinline__

// Problem constants
constexpr int Mdim = 768;
constexpr int Vv   = 32000;
constexpr int Rr   = 48;
constexpr int Nn   = 16;
constexpr int Kk   = 4;
constexpr int Ll   = 2;
constexpr int Hh   = 1536;
constexpr int Bb   = 2;
constexpr int Ss   = 1024;
constexpr int BS   = Bb * Ss;     // 2048
constexpr int H2   = 2 * Hh;      // 3072
constexpr int XD   = Rr + 2 * Nn; // 80

constexpr int K2_M  = Mdim / 2;   // 384
constexpr int K2_H  = Hh / 2;     // 768
constexpr int K2_DT = 32;         // 48/2=24 -> pad 32

// ---------------- fp32 scratch ----------------
__device__ float g_x    [BS * Mdim];
__device__ float g_xr   [BS * H2];
__device__ float g_delta[BS * Hh];
__device__ float g_mo   [BS * Mdim];
__device__ __align__(16) float2 g_ures[BS * Hh];   // {u, res} per (row,h)
__device__ __align__(16) float2 g_bc  [BS * Nn];   // {B_n, C_n} per (row,n)

// ---------------- packed 16-bit planes ----------------
__device__ __align__(16) uint32_t g_xp_h [BS * K2_M];
__device__ __align__(16) uint32_t g_xp_l [BS * K2_M];
__device__ __align__(16) uint32_t g_act_h[BS * K2_H];
__device__ __align__(16) uint32_t g_act_l[BS * K2_H];
__device__ __align__(16) uint32_t g_liw_h[Ll * H2 * K2_M];
__device__ __align__(16) uint32_t g_liw_l[Ll * H2 * K2_M];
__device__ __align__(16) uint32_t g_ldw_h[Ll * Hh * K2_DT];
__device__ __align__(16) uint32_t g_ldw_l[Ll * Hh * K2_DT];
__device__ __align__(16) uint32_t g_low_h[Ll * Mdim * K2_H];
__device__ __align__(16) uint32_t g_low_l[Ll * Mdim * K2_H];
__device__ __align__(16) uint32_t g_hw_h [Vv * K2_M];          // fp16 single

// ---------------- helpers ----------------
DEV_INLINE float siluf(float v)      { return v / (1.f + expf(-v)); }
DEV_INLINE float silu_fast(float v)  { return v / (1.f + __expf(-v)); }
DEV_INLINE float softplusf(float v)  { return v > 20.f ? v : log1pf(expf(v)); }

DEV_INLINE float warp_sum(float v) {
    #pragma unroll
    for (int o = 16; o; o >>= 1) v += __shfl_xor_sync(0xffffffffu, v, o);
    return v;
}

DEV_INLINE uint32_t packsplit(float f0, float f1, uint32_t& lo) {
    __nv_bfloat16 h0 = __float2bfloat16(f0);
    __nv_bfloat16 h1 = __float2bfloat16(f1);
    __nv_bfloat16 l0 = __float2bfloat16(f0 - __bfloat162float(h0));
    __nv_bfloat16 l1 = __float2bfloat16(f1 - __bfloat162float(h1));
    lo = (uint32_t)__bfloat16_as_ushort(l0) | ((uint32_t)__bfloat16_as_ushort(l1) << 16);
    return (uint32_t)__bfloat16_as_ushort(h0) | ((uint32_t)__bfloat16_as_ushort(h1) << 16);
}

DEV_INLINE uint32_t pack_f16(float f0, float f1) {
    __half2 h = __floats2half2_rn(f0, f1);
    return *(uint32_t*)&h;
}

DEV_INLINE void packsplit8(float4 a, float4 b, uint4& hi, uint4& lo) {
    hi.x = packsplit(a.x, a.y, lo.x);
    hi.y = packsplit(a.z, a.w, lo.y);
    hi.z = packsplit(b.x, b.y, lo.z);
    hi.w = packsplit(b.z, b.w, lo.w);
}

DEV_INLINE void mma_bf16(float* d, const uint32_t* a, const uint32_t* b) {
    asm volatile(
        "mma.sync.aligned.m16n8k16.row.col.f32.bf16.bf16.f32 "
        "{%0,%1,%2,%3}, {%4,%5,%6,%7}, {%8,%9}, {%0,%1,%2,%3};"
        : "+f"(d[0]), "+f"(d[1]), "+f"(d[2]), "+f"(d[3])
        : "r"(a[0]), "r"(a[1]), "r"(a[2]), "r"(a[3]),
          "r"(b[0]), "r"(b[1]));
}

DEV_INLINE void mma_f16(float* d, const uint32_t* a, const uint32_t* b) {
    asm volatile(
        "mma.sync.aligned.m16n8k16.row.col.f32.f16.f16.f32 "
        "{%0,%1,%2,%3}, {%4,%5,%6,%7}, {%8,%9}, {%0,%1,%2,%3};"
        : "+f"(d[0]), "+f"(d[1]), "+f"(d[2]), "+f"(d[3])
        : "r"(a[0]), "r"(a[1]), "r"(a[2]), "r"(a[3]),
          "r"(b[0]), "r"(b[1]));
}

DEV_INLINE void ldsm_x4(uint32_t& r0, uint32_t& r1, uint32_t& r2, uint32_t& r3,
                        uint32_t addr) {
    asm volatile("ldmatrix.sync.aligned.m8n8.x4.shared.b16 {%0,%1,%2,%3}, [%4];"
                 : "=r"(r0), "=r"(r1), "=r"(r2), "=r"(r3) : "r"(addr));
}

DEV_INLINE void cp_async16(uint32_t dst, const void* src) {
    asm volatile("cp.async.cg.shared.global [%0], [%1], 16;" :: "r"(dst), "l"(src));
}
DEV_INLINE void cp_commit() { asm volatile("cp.async.commit_group;"); }
template<int N> DEV_INLINE void cp_wait() {
    asm volatile("cp.async.wait_group %0;" :: "n"(N));
}

// ---------------- one-shot mega weight split (both layers + head) ---------
constexpr int SEG0 = H2 * K2_M;
constexpr int SEG1 = Hh * K2_DT;
constexpr int SEG2 = Mdim * K2_H;
constexpr int Q0 = SEG0 / 4;
constexpr int Q1 = SEG1 / 4;
constexpr int Q2 = SEG2 / 4;
constexpr int QT = Q0 + Q1 + Q2;
constexpr int QH = (Vv * K2_M) / 4;
constexpr int QALL = 2 * QT + QH;

__global__ void split_all_kernel(const float* __restrict__ liw,
                                 const float* __restrict__ ldw,
                                 const float* __restrict__ low,
                                 const float* __restrict__ hw,
                                 uint32_t* __restrict__ liw_h, uint32_t* __restrict__ liw_l,
                                 uint32_t* __restrict__ ldw_h, uint32_t* __restrict__ ldw_l,
                                 uint32_t* __restrict__ low_h, uint32_t* __restrict__ low_l,
                                 uint32_t* __restrict__ hw_h) {
    int idx = blockIdx.x * blockDim.x + threadIdx.x;
    if (idx >= QALL) return;
    if (idx >= 2 * QT) {                 // head weights -> fp16
        int u = (idx - 2 * QT) * 4;
        int r = u / K2_M, j = u - r * K2_M;
        const float4* p = (const float4*)(hw + (size_t)r * Mdim + 2 * j);
        float4 a = p[0], b = p[1];
        uint4 o;
        o.x = pack_f16(a.x, a.y);
        o.y = pack_f16(a.z, a.w);
        o.z = pack_f16(b.x, b.y);
        o.w = pack_f16(b.z, b.w);
        *(uint4*)(hw_h + u) = o;
        return;
    }
    int l = (idx >= QT) ? 1 : 0;
    int q = idx - l * QT;
    if (q < Q0) {
        int u = q * 4;
        int r = u / K2_M, j = u - r * K2_M;
        const float4* p = (const float4*)(liw + (size_t)l * H2 * Mdim + (size_t)r * Mdim + 2 * j);
        uint4 hi, lo;
        packsplit8(p[0], p[1], hi, lo);
        *(uint4*)(liw_h + (size_t)l * SEG0 + u) = hi;
        *(uint4*)(liw_l + (size_t)l * SEG0 + u) = lo;
    } else if (q < Q0 + Q1) {
        int u = (q - Q0) * 4;
        int r = u / K2_DT, j = u - r * K2_DT;
        uint4 hi, lo;
        if (2 * j >= Rr) {
            hi = make_uint4(0, 0, 0, 0);
            lo = make_uint4(0, 0, 0, 0);
        } else {
            const float4* p = (const float4*)(ldw + (size_t)l * Hh * Rr + (size_t)r * Rr + 2 * j);
            packsplit8(p[0], p[1], hi, lo);
        }
        *(uint4*)(ldw_h + (size_t)l * SEG1 + u) = hi;
        *(uint4*)(ldw_l + (size_t)l * SEG1 + u) = lo;
    } else {
        int u = (q - Q0 - Q1) * 4;
        int r = u / K2_H, j = u - r * K2_H;
        const float4* p = (const float4*)(low + (size_t)l * Mdim * Hh + (size_t)r * Hh + 2 * j);
        uint4 hi, lo;
        packsplit8(p[0], p[1], hi, lo);
        *(uint4*)(low_h + (size_t)l * SEG2 + u) = hi;
        *(uint4*)(low_l + (size_t)l * SEG2 + u) = lo;
    }
}

// ---------------- embedding gather + planes ----------------
__global__ void embed_kernel(const int* __restrict__ ids,
                             const float* __restrict__ emb,
                             float* __restrict__ x,
                             uint32_t* __restrict__ xph,
                             uint32_t* __restrict__ xpl) {
    int idx = blockIdx.x * blockDim.x + threadIdx.x;
    if (idx >= BS * K2_M) return;
    int row = idx / K2_M;
    int m2  = idx - row * K2_M;
    const float* e = emb + (size_t)ids[row] * Mdim + 2 * m2;
    float f0 = e[0], f1 = e[1];
    x[(size_t)row * Mdim + 2 * m2]     = f0;
    x[(size_t)row * Mdim + 2 * m2 + 1] = f1;
    uint32_t l;
    uint32_t h = packsplit(f0, f1, l);
    xph[idx] = h;
    xpl[idx] = l;
}

// ---------------- bf16x3 GEMM, 2-stage double buffer, 2 CTAs/SM ----------
template<int BN, int ACT>
__global__ __launch_bounds__(256, 2)
void gemm_bf16x3(const uint32_t* __restrict__ Ah, const uint32_t* __restrict__ Al,
                 const uint32_t* __restrict__ Wh, const uint32_t* __restrict__ Wl,
                 int K2,
                 const float* __restrict__ bias,
                 float* __restrict__ C, int ldc) {
    constexpr int NTt  = BN / 32;
    constexpr int ROWB = 80;
    constexpr int APB  = 128 * ROWB;
    constexpr int WPB  = BN * ROWB;
    constexpr int STGB = 2 * APB + 2 * WPB;
    constexpr int NCH  = (256 + 2 * BN) * 4 / 256;

    extern __shared__ __align__(16) uint32_t smu[];

    const int tid  = threadIdx.x;
    const int lane = tid & 31;
    const int wid  = tid >> 5;
    const int wm   = wid >> 2;
    const int wn   = wid & 3;
    const int i0   = blockIdx.y * 128;
    const int j0   = blockIdx.x * BN;
    const int lq   = lane & 3;
    const int lg   = lane >> 2;

    const uint32_t sb = (uint32_t)__cvta_generic_to_shared(smu);

    const uint32_t* src[NCH];
    uint32_t dst[NCH];
    #pragma unroll
    for (int uu = 0; uu < NCH; uu++) {
        int c  = uu * 256 + tid;
        int r2 = c >> 2;
        int q  = c & 3;
        const uint32_t* gbase;
        int pofs, r;
        if (r2 < 128)            { r = r2;            gbase = Ah + (size_t)i0 * K2; pofs = 0; }
        else if (r2 < 256)       { r = r2 - 128;      gbase = Al + (size_t)i0 * K2; pofs = APB; }
        else if (r2 < 256 + BN)  { r = r2 - 256;      gbase = Wh + (size_t)j0 * K2; pofs = 2 * APB; }
        else                     { r = r2 - 256 - BN; gbase = Wl + (size_t)j0 * K2; pofs = 2 * APB + WPB; }
        src[uu] = gbase + (size_t)r * K2 + q * 4;
        dst[uu] = sb + pofs + r * ROWB + q * 16;
    }

    const uint32_t aRow = (uint32_t)((wm * 64 + (lane & 15)) * ROWB + ((lane >> 4) << 4));
    const uint32_t bRow = (uint32_t)((wn * (NTt * 8) + ((lane >> 4) << 3) + (lane & 7)) * ROWB
                                     + (((lane >> 3) & 1) << 4));

    float acc[4][NTt][4];
    #pragma unroll
    for (int m = 0; m < 4; m++)
        #pragma unroll
        for (int n = 0; n < NTt; n++)
            #pragma unroll
            for (int c = 0; c < 4; c++) acc[m][n][c] = 0.f;

    const int nk = K2 >> 4;

    #pragma unroll
    for (int uu = 0; uu < NCH; uu++) cp_async16(dst[uu], src[uu]);
    cp_commit();

    for (int t = 0; t < nk; t++) {
        cp_wait<0>();
        __syncthreads();
        if (t + 1 < nk) {
            uint32_t so = (uint32_t)((t + 1) & 1) * STGB;
            int ko = (t + 1) * 16;
            #pragma unroll
            for (int uu = 0; uu < NCH; uu++)
                cp_async16(dst[uu] + so, src[uu] + ko);
            cp_commit();
        }

        const uint32_t st = sb + (uint32_t)(t & 1) * STGB;

        #pragma unroll
        for (int h = 0; h < 2; h++) {
            uint32_t ah[4][4], al[4][4], bh[NTt][2], bl[NTt][2];
            #pragma unroll
            for (int m = 0; m < 4; m++) {
                uint32_t a0 = st + aRow + m * (16 * ROWB) + h * 32;
                ldsm_x4(ah[m][0], ah[m][1], ah[m][2], ah[m][3], a0);
                ldsm_x4(al[m][0], al[m][1], al[m][2], al[m][3], a0 + APB);
            }
            #pragma unroll
            for (int j = 0; j < NTt / 2; j++) {
                uint32_t b0 = st + 2 * APB + bRow + j * (16 * ROWB) + h * 32;
                ldsm_x4(bh[2*j][0], bh[2*j][1], bh[2*j+1][0], bh[2*j+1][1], b0);
                ldsm_x4(bl[2*j][0], bl[2*j][1], bl[2*j+1][0], bl[2*j+1][1], b0 + WPB);
            }
            #pragma unroll
            for (int m = 0; m < 4; m++)
                #pragma unroll
                for (int n = 0; n < NTt; n++)
                    mma_bf16(acc[m][n], ah[m], bh[n]);
            #pragma unroll
            for (int m = 0; m < 4; m++)
                #pragma unroll
                for (int n = 0; n < NTt; n++)
                    mma_bf16(acc[m][n], ah[m], bl[n]);
            #pragma unroll
            for (int m = 0; m < 4; m++)
                #pragma unroll
                for (int n = 0; n < NTt; n++)
                    mma_bf16(acc[m][n], al[m], bh[n]);
        }
    }

    #pragma unroll
    for (int m = 0; m < 4; m++) {
        int gi = i0 + wm * 64 + m * 16 + lg;
        #pragma unroll
        for (int n = 0; n < NTt; n++) {
            int gj = j0 + wn * (NTt * 8) + n * 8 + 2 * lq;
            float b0 = bias[gj], b1 = bias[gj + 1];
            float v0 = acc[m][n][0] + b0;
            float v1 = acc[m][n][1] + b1;
            float v2 = acc[m][n][2] + b0;
            float v3 = acc[m][n][3] + b1;
            if (ACT == 1) {
                v0 = softplusf(v0); v1 = softplusf(v1);
                v2 = softplusf(v2); v3 = softplusf(v3);
            }
            *(float2*)(C + (size_t)gi * ldc + gj)       = make_float2(v0, v1);
            *(float2*)(C + (size_t)(gi + 8) * ldc + gj) = make_float2(v2, v3);
        }
    }
}

// ---------------- fp16 single-pass GEMM (head), 3-stage ----------------
template<int BN>
__global__ __launch_bounds__(256, 2)
void gemm_fp16(const uint32_t* __restrict__ Ah, const uint32_t* __restrict__ Wh,
               int K2,
               const float* __restrict__ bias,
               float* __restrict__ C, int ldc) {
    constexpr int NTt  = BN / 32;
    constexpr int ROWB = 80;
    constexpr int APB  = 128 * ROWB;
    constexpr int WPB  = BN * ROWB;
    constexpr int STGB = APB + WPB;
    constexpr int NCH  = (128 + BN) * 4 / 256;

    extern __shared__ __align__(16) uint32_t smu[];

    const int tid  = threadIdx.x;
    const int lane = tid & 31;
    const int wid  = tid >> 5;
    const int wm   = wid >> 2;
    const int wn   = wid & 3;
    const int i0   = blockIdx.y * 128;
    const int j0   = blockIdx.x * BN;
    const int lq   = lane & 3;
    const int lg   = lane >> 2;

    const uint32_t sb = (uint32_t)__cvta_generic_to_shared(smu);

    const uint32_t* src[NCH];
    uint32_t dst[NCH];
    #pragma unroll
    for (int uu = 0; uu < NCH; uu++) {
        int c  = uu * 256 + tid;
        int r2 = c >> 2;
        int q  = c & 3;
        const uint32_t* gbase;
        int pofs, r;
        if (r2 < 128) { r = r2;       gbase = Ah + (size_t)i0 * K2; pofs = 0; }
        else          { r = r2 - 128; gbase = Wh + (size_t)j0 * K2; pofs = APB; }
        src[uu] = gbase + (size_t)r * K2 + q * 4;
        dst[uu] = sb + pofs + r * ROWB + q * 16;
    }

    const uint32_t aRow = (uint32_t)((wm * 64 + (lane & 15)) * ROWB + ((lane >> 4) << 4));
    const uint32_t bRow = (uint32_t)((wn * (NTt * 8) + ((lane >> 4) << 3) + (lane & 7)) * ROWB
                                     + (((lane >> 3) & 1) << 4));

    float acc[4][NTt][4];
    #pragma unroll
    for (int m = 0; m < 4; m++)
        #pragma unroll
        for (int n = 0; n < NTt; n++)
            #pragma unroll
            for (int c = 0; c < 4; c++) acc[m][n][c] = 0.f;

    const int nk = K2 >> 4;

    #pragma unroll
    for (int uu = 0; uu < NCH; uu++) cp_async16(dst[uu], src[uu]);
    cp_commit();
    #pragma unroll
    for (int uu = 0; uu < NCH; uu++) cp_async16(dst[uu] + STGB, src[uu] + 16);
    cp_commit();

    for (int t = 0; t < nk; t++) {
        if (t + 1 < nk) { cp_wait<1>(); } else { cp_wait<0>(); }
        __syncthreads();
        if (t + 2 < nk) {
            uint32_t so = (uint32_t)((t + 2) % 3) * STGB;
            int ko = (t + 2) * 16;
            #pragma unroll
            for (int uu = 0; uu < NCH; uu++)
                cp_async16(dst[uu] + so, src[uu] + ko);
            cp_commit();
        }

        const uint32_t st = sb + (uint32_t)(t % 3) * STGB;

        uint32_t ah2[2][4][4], bh2[2][NTt][2];
        #pragma unroll
        for (int h = 0; h < 2; h++) {
            #pragma unroll
            for (int m = 0; m < 4; m++) {
                uint32_t a0 = st + aRow + m * (16 * ROWB) + h * 32;
                ldsm_x4(ah2[h][m][0], ah2[h][m][1], ah2[h][m][2], ah2[h][m][3], a0);
            }
            #pragma unroll
            for (int j = 0; j < NTt / 2; j++) {
                uint32_t b0 = st + APB + bRow + j * (16 * ROWB) + h * 32;
                ldsm_x4(bh2[h][2*j][0], bh2[h][2*j][1],
                        bh2[h][2*j+1][0], bh2[h][2*j+1][1], b0);
            }
        }
        #pragma unroll
        for (int h = 0; h < 2; h++)
            #pragma unroll
            for (int m = 0; m < 4; m++)
                #pragma unroll
                for (int n = 0; n < NTt; n++)
                    mma_f16(acc[m][n], ah2[h][m], bh2[h][n]);
    }

    #pragma unroll
    for (int m = 0; m < 4; m++) {
        int gi = i0 + wm * 64 + m * 16 + lg;
        #pragma unroll
        for (int n = 0; n < NTt; n++) {
            int gj = j0 + wn * (NTt * 8) + n * 8 + 2 * lq;
            float b0 = bias[gj], b1 = bias[gj + 1];
            *(float2*)(C + (size_t)gi * ldc + gj) =
                make_float2(acc[m][n][0] + b0, acc[m][n][1] + b1);
            *(float2*)(C + (size_t)(gi + 8) * ldc + gj) =
                make_float2(acc[m][n][2] + b0, acc[m][n][3] + b1);
        }
    }
}

// ---------------- fused conv+silu+linx+dt/bc emit, block per row ----------
__global__ __launch_bounds__(256)
void conv_linx_kernel(const float* __restrict__ xr,
                      const float* __restrict__ cw,
                      const float* __restrict__ cb,
                      const float* __restrict__ lxw,
                      const float* __restrict__ lxb,
                      float2* __restrict__ ures,
                      uint32_t* __restrict__ dth,
                      uint32_t* __restrict__ dtl,
                      float2* __restrict__ bc) {
    const int i   = blockIdx.x;          // row
    const int tid = threadIdx.x;
    const int b   = i / Ss;
    const int s   = i % Ss;

    __shared__ float su[Hh];

    // ---- depthwise conv (K=4) + silu, 3 channel-pairs per thread ----
    const float4* cw4 = (const float4*)cw;
    #pragma unroll
    for (int g = 0; g < 3; g++) {
        int h2 = tid + g * 256;          // 0..767
        int h  = 2 * h2;
        float4 ta = cw4[h], tb = cw4[h + 1];
        float a0 = cb[h], a1 = cb[h + 1];
        #pragma unroll
        for (int k = 0; k < 4; k++) {
            int sp = s - 3 + k;
            if (sp >= 0) {
                float2 xv = *(const float2*)(xr + (size_t)(b * Ss + sp) * H2 + h);
                float wa = (k == 0) ? ta.x : (k == 1) ? ta.y : (k == 2) ? ta.z : ta.w;
                float wb = (k == 0) ? tb.x : (k == 1) ? tb.y : (k == 2) ? tb.z : tb.w;
                a0 += wa * xv.x;
                a1 += wb * xv.y;
            }
        }
        float u0 = silu_fast(a0), u1 = silu_fast(a1);
        su[h] = u0;
        su[h + 1] = u1;
        float2 rv = *(const float2*)(xr + (size_t)i * H2 + Hh + h);
        float4 o = make_float4(u0, rv.x, u1, rv.y);
        *(float4*)(ures + (size_t)i * Hh + h) = o;
    }
    __syncthreads();

    // ---- linx: 40 col-pairs, 5 per warp ----
    const int w    = tid >> 5;
    const int lane = tid & 31;
    const float4* su4 = (const float4*)su;
    #pragma unroll
    for (int pp = 0; pp < 5; pp++) {
        int p = w * 5 + pp;
        int j0, j1;
        if (p < 24) { j0 = 2 * p; j1 = 2 * p + 1; }
        else        { j0 = Rr + (p - 24); j1 = Rr + Nn + (p - 24); }
        const float4* w0 = (const float4*)(lxw + (size_t)j0 * Hh);
        const float4* w1 = (const float4*)(lxw + (size_t)j1 * Hh);
        float p0 = 0.f, p1 = 0.f;
        #pragma unroll
        for (int t = 0; t < 12; t++) {
            int k = t * 32 + lane;
            float4 uv = su4[k];
            float4 a  = w0[k];
            p0 += uv.x * a.x + uv.y * a.y + uv.z * a.z + uv.w * a.w;
            a = w1[k];
            p1 += uv.x * a.x + uv.y * a.y + uv.z * a.z + uv.w * a.w;
        }
        p0 = warp_sum(p0);
        p1 = warp_sum(p1);
        if (lane == 0) {
            float v0 = p0 + lxb[j0];
            float v1 = p1 + lxb[j1];
            if (p < 24) {
                uint32_t lo;
                uint32_t hi = packsplit(v0, v1, lo);
                dth[(size_t)i * K2_DT + p] = hi;
                dtl[(size_t)i * K2_DT + p] = lo;
            } else {
                bc[(size_t)i * Nn + (p - 24)] = make_float2(v0, v1);
            }
        }
    }
    if (tid < 8) {
        dth[(size_t)i * K2_DT + 24 + tid] = 0;
        dtl[(size_t)i * K2_DT + 24 + tid] = 0;
    }
}

// ---------------- scan + gate, depth-4 prefetch, 3 loads/iter -------------
__global__ void scan_gate_kernel(const float* __restrict__ delta,
                                 const float2* __restrict__ ures,
                                 const float2* __restrict__ bc,
                                 const float* __restrict__ Dp,
                                 uint32_t* __restrict__ yh,
                                 uint32_t* __restrict__ yl) {
    int gwarp = (blockIdx.x * blockDim.x + threadIdx.x) >> 5;
    if (gwarp >= Bb * (Hh / 2)) return;
    int lane = threadIdx.x & 31;
    int half = lane >> 4;
    int n    = lane & 15;
    int b    = gwarp / (Hh / 2);
    int hp   = gwarp % (Hh / 2);
    int h    = hp * 2 + half;

    const float An = -(float)(n + 1);
    const float Dh = Dp[h];
    float state = 0.f;

    const int base = b * Ss;

    float  pd[4];
    float2 pu[4], pb[4];
    #pragma unroll
    for (int k = 0; k < 4; k++) {
        int r = base + k;
        pd[k] = __ldg(delta + (size_t)r * Hh + h);
        pu[k] = __ldg(ures + (size_t)r * Hh + h);
        pb[k] = __ldg(bc + (size_t)r * Nn + n);
    }

    float dA  = __expf(pd[0] * An);
    float dBu = pd[0] * pb[0].x * pu[0].x;

    #pragma unroll 4
    for (int s = 0; s < Ss; s++) {
        const int slot = s & 3;
        const int ns   = (s + 1) & 3;
        int row = base + s;

        float uv  = pu[slot].x;
        float res = pu[slot].y;
        float Cn  = pb[slot].y;

        // recurrence (critical path: one FFMA)
        state = dA * state + dBu;

        if (s + 4 < Ss) {
            int r = row + 4;
            pd[slot] = __ldg(delta + (size_t)r * Hh + h);
            pu[slot] = __ldg(ures + (size_t)r * Hh + h);
            pb[slot] = __ldg(bc + (size_t)r * Nn + n);
        }

        dA  = __expf(pd[ns] * An);
        dBu = pd[ns] * pb[ns].x * pu[ns].x;

        float val = state * Cn;
        val += __shfl_xor_sync(0xffffffffu, val, 8);
        val += __shfl_xor_sync(0xffffffffu, val, 4);
        val += __shfl_xor_sync(0xffffffffu, val, 2);
        val += __shfl_xor_sync(0xffffffffu, val, 1);
        float yv = (val + uv * Dh) * silu_fast(res);
        float y1 = __shfl_sync(0xffffffffu, yv, 16);
        if (lane == 0) {
            uint32_t lo;
            uint32_t hi = packsplit(yv, y1, lo);
            yh[(size_t)row * K2_H + hp] = hi;
            yl[(size_t)row * K2_H + hp] = lo;
        }
    }
}

// ---------------- x += rmsnorm(mo) * w ; emit x planes ----------------
__global__ void rmsnorm_add_kernel(float* __restrict__ x,
                                   const float* __restrict__ mo,
                                   const float* __restrict__ w,
                                   uint32_t* __restrict__ xph,
                                   uint32_t* __restrict__ xpl) {
    int row = blockIdx.x;
    const float* r = mo + (size_t)row * Mdim;
    float ss = 0.f;
    for (int m = threadIdx.x; m < Mdim; m += blockDim.x) {
        float v = r[m];
        ss += v * v;
    }
    __shared__ float sh[8];
    ss = warp_sum(ss);
    int wid = threadIdx.x >> 5, lane = threadIdx.x & 31;
    if (lane == 0) sh[wid] = ss;
    __syncthreads();
    if (wid == 0) {
        float v = (lane < (int)(blockDim.x >> 5)) ? sh[lane] : 0.f;
        v = warp_sum(v);
        if (lane == 0) sh[0] = v;
    }
    __syncthreads();
    float scale = rsqrtf(sh[0] / (float)Mdim + 1e-15f);
    float* xp = x + (size_t)row * Mdim;
    for (int m2 = threadIdx.x; m2 < K2_M; m2 += blockDim.x) {
        int m = 2 * m2;
        float v0 = xp[m]     + r[m]     * scale * w[m];
        float v1 = xp[m + 1] + r[m + 1] * scale * w[m + 1];
        xp[m] = v0; xp[m + 1] = v1;
        uint32_t lo;
        uint32_t hi = packsplit(v0, v1, lo);
        xph[(size_t)row * K2_M + m2] = hi;
        xpl[(size_t)row * K2_M + m2] = lo;
    }
}

// ---------------- final rmsnorm -> fp16 planes (head input) ----------------
__global__ void rmsnorm_final_kernel(const float* __restrict__ x,
                                     const float* __restrict__ w,
                                     uint32_t* __restrict__ xnf) {
    int row = blockIdx.x;
    const float* r = x + (size_t)row * Mdim;
    float ss = 0.f;
    for (int m = threadIdx.x; m < Mdim; m += blockDim.x) {
        float v = r[m];
        ss += v * v;
    }
    __shared__ float sh[8];
    ss = warp_sum(ss);
    int wid = threadIdx.x >> 5, lane = threadIdx.x & 31;
    if (lane == 0) sh[wid] = ss;
    __syncthreads();
    if (wid == 0) {
        float v = (lane < (int)(blockDim.x >> 5)) ? sh[lane] : 0.f;
        v = warp_sum(v);
        if (lane == 0) sh[0] = v;
    }
    __syncthreads();
    float scale = rsqrtf(sh[0] / (float)Mdim + 1e-15f);
    for (int m2 = threadIdx.x; m2 < K2_M; m2 += blockDim.x) {
        int m = 2 * m2;
        xnf[(size_t)row * K2_M + m2] =
            pack_f16(r[m] * scale * w[m], r[m + 1] * scale * w[m + 1]);
    }
}

// ---------------- launch ----------------
extern "C" void kernel_launch(void* const* d_in, const int* in_sizes, int n_in,
                              void* d_out, int out_size) {
    const int*   ids = (const int*)  d_in[0];
    const float* emb = (const float*)d_in[1];
    const float* liw = (const float*)d_in[2];
    const float* lib = (const float*)d_in[3];
    const float* cw  = (const float*)d_in[4];
    const float* cb  = (const float*)d_in[5];
    const float* lxw = (const float*)d_in[6];
    const float* lxb = (const float*)d_in[7];
    const float* ldw = (const float*)d_in[8];
    const float* ldb = (const float*)d_in[9];
    const float* low = (const float*)d_in[10];
    const float* lob = (const float*)d_in[11];
    const float* Dp  = (const float*)d_in[12];
    const float* bnw = (const float*)d_in[13];
    const float* fnw = (const float*)d_in[14];
    const float* hw  = (const float*)d_in[15];
    const float* hb  = (const float*)d_in[16];
    float* out = (float*)d_out;

    float *x, *xr, *delta, *mo;
    float2 *ures, *bcb;
    cudaGetSymbolAddress((void**)&x,     g_x);
    cudaGetSymbolAddress((void**)&xr,    g_xr);
    cudaGetSymbolAddress((void**)&delta, g_delta);
    cudaGetSymbolAddress((void**)&mo,    g_mo);
    cudaGetSymbolAddress((void**)&ures,  g_ures);
    cudaGetSymbolAddress((void**)&bcb,   g_bc);

    uint32_t *xp_h, *xp_l, *act_h, *act_l;
    uint32_t *liw_h, *liw_l, *ldw_h, *ldw_l, *low_h, *low_l, *hw_h;
    cudaGetSymbolAddress((void**)&xp_h,  g_xp_h);
    cudaGetSymbolAddress((void**)&xp_l,  g_xp_l);
    cudaGetSymbolAddress((void**)&act_h, g_act_h);
    cudaGetSymbolAddress((void**)&act_l, g_act_l);
    cudaGetSymbolAddress((void**)&liw_h, g_liw_h);
    cudaGetSymbolAddress((void**)&liw_l, g_liw_l);
    cudaGetSymbolAddress((void**)&ldw_h, g_ldw_h);
    cudaGetSymbolAddress((void**)&ldw_l, g_ldw_l);
    cudaGetSymbolAddress((void**)&low_h, g_low_h);
    cudaGetSymbolAddress((void**)&low_l, g_low_l);
    cudaGetSymbolAddress((void**)&hw_h,  g_hw_h);

    const int SM128  = 2 * (2 * 128 * 80 + 2 * 128 * 80);  // 81920
    const int SM64   = 2 * (2 * 128 * 80 + 2 * 64 * 80);   // 61440
    const int SMF128 = 3 * (128 + 128) * 80;               // 61440
    cudaFuncSetAttribute((const void*)gemm_bf16x3<128, 0>,
                         cudaFuncAttributeMaxDynamicSharedMemorySize, SM128);
    cudaFuncSetAttribute((const void*)gemm_bf16x3<128, 1>,
                         cudaFuncAttributeMaxDynamicSharedMemorySize, SM128);
    cudaFuncSetAttribute((const void*)gemm_bf16x3<64, 0>,
                         cudaFuncAttributeMaxDynamicSharedMemorySize, SM64);
    cudaFuncSetAttribute((const void*)gemm_fp16<128>,
                         cudaFuncAttributeMaxDynamicSharedMemorySize, SMF128);

    // #0 embed, #1 mega-split
    embed_kernel<<<(BS * K2_M + 255) / 256, 256>>>(ids, emb, x, xp_h, xp_l);
    split_all_kernel<<<(QALL + 255) / 256, 256>>>(
        liw, ldw, low, hw,
        liw_h, liw_l, ldw_h, ldw_l, low_h, low_l, hw_h);

    for (int l = 0; l < Ll; l++) {
        // lin_in (#2 for l=0)
        gemm_bf16x3<128, 0><<<dim3(H2 / 128, BS / 128), 256, SM128>>>(
            xp_h, xp_l,
            liw_h + (size_t)l * SEG0, liw_l + (size_t)l * SEG0,
            K2_M, lib + (size_t)l * H2, xr, H2);

        // fused conv+linx (#3 for l=0 — profiled)
        conv_linx_kernel<<<BS, 256>>>(
            xr, cw + (size_t)l * Hh * Kk, cb + (size_t)l * Hh,
            lxw + (size_t)l * XD * Hh, lxb + (size_t)l * XD,
            ures, act_h, act_l, bcb);

        gemm_bf16x3<128, 1><<<dim3(Hh / 128, BS / 128), 256, SM128>>>(
            act_h, act_l,
            ldw_h + (size_t)l * SEG1, ldw_l + (size_t)l * SEG1,
            K2_DT, ldb + (size_t)l * Hh, delta, Hh);

        scan_gate_kernel<<<(Bb * (Hh / 2) * 32 + 255) / 256, 256>>>(
            delta, ures, bcb, Dp + (size_t)l * Hh, act_h, act_l);

        // lin_out: bf16x3 (precision-critical — feeds residual stream)
        gemm_bf16x3<64, 0><<<dim3(Mdim / 64, BS / 128), 256, SM64>>>(
            act_h, act_l,
            low_h + (size_t)l * SEG2, low_l + (size_t)l * SEG2,
            K2_H, lob + (size_t)l * Mdim, mo, Mdim);

        rmsnorm_add_kernel<<<BS, 256>>>(x, mo, bnw + (size_t)l * Mdim, xp_h, xp_l);
    }

    rmsnorm_final_kernel<<<BS, 256>>>(x, fnw, act_h);

    gemm_fp16<128><<<dim3(Vv / 128, BS / 128), 256, SMF128>>>(
        act_h, hw_h, K2_M, hb, out, Vv);
}

// round 16
// speedup vs baseline: 4.2526x; 1.0195x over previous
#include <cuda_runtime.h>
#include <cuda_bf16.h>
#include <cuda_fp16.h>
#include <math.h>
#include <stdint.h>

#define DEV_INLINE __device__ __forceinline__

// Problem constants
constexpr int Mdim = 768;
constexpr int Vv   = 32000;
constexpr int Rr   = 48;
constexpr int Nn   = 16;
constexpr int Kk   = 4;
constexpr int Ll   = 2;
constexpr int Hh   = 1536;
constexpr int Bb   = 2;
constexpr int Ss   = 1024;
constexpr int BS   = Bb * Ss;     // 2048
constexpr int H2   = 2 * Hh;      // 3072
constexpr int XD   = Rr + 2 * Nn; // 80

constexpr int K2_M  = Mdim / 2;   // 384
constexpr int K2_H  = Hh / 2;     // 768
constexpr int K2_DT = 32;         // 48/2=24 -> pad 32
constexpr int LXR   = 128;        // lxw plane rows (80 real + 48 zero)

// ---------------- fp32 scratch ----------------
__device__ float g_x    [BS * Mdim];
__device__ float g_xr   [BS * H2];
__device__ float g_delta[BS * Hh];
__device__ float g_mo   [BS * Mdim];
__device__ float g_xw   [BS * LXR];                // linx raw output (pre-bias)
__device__ float g_zb   [LXR];                     // zero bias (static zero-init)
__device__ __align__(16) float2 g_ures[BS * Hh];   // {u, res} per (row,h)
__device__ __align__(16) float  g_bcv [BS * 32];   // B at [0..16), C at [16..32)

// ---------------- packed 16-bit planes ----------------
__device__ __align__(16) uint32_t g_xp_h [BS * K2_M];
__device__ __align__(16) uint32_t g_xp_l [BS * K2_M];
__device__ __align__(16) uint32_t g_uh   [BS * K2_H];
__device__ __align__(16) uint32_t g_ul   [BS * K2_H];
__device__ __align__(16) uint32_t g_act_h[BS * K2_H];
__device__ __align__(16) uint32_t g_act_l[BS * K2_H];
__device__ __align__(16) uint32_t g_liw_h[Ll * H2 * K2_M];
__device__ __align__(16) uint32_t g_liw_l[Ll * H2 * K2_M];
__device__ __align__(16) uint32_t g_ldw_h[Ll * Hh * K2_DT];
__device__ __align__(16) uint32_t g_ldw_l[Ll * Hh * K2_DT];
__device__ __align__(16) uint32_t g_low_h[Ll * Mdim * K2_H];
__device__ __align__(16) uint32_t g_low_l[Ll * Mdim * K2_H];
__device__ __align__(16) uint32_t g_lxw_h[Ll * LXR * K2_H];
__device__ __align__(16) uint32_t g_lxw_l[Ll * LXR * K2_H];
__device__ __align__(16) uint32_t g_hw_h [Vv * K2_M];

// ---------------- helpers ----------------
DEV_INLINE float silu_fast(float v)  { return v / (1.f + __expf(-v)); }
DEV_INLINE float softplusf(float v)  { return v > 20.f ? v : log1pf(expf(v)); }

DEV_INLINE float warp_sum(float v) {
    #pragma unroll
    for (int o = 16; o; o >>= 1) v += __shfl_xor_sync(0xffffffffu, v, o);
    return v;
}

DEV_INLINE uint32_t packsplit(float f0, float f1, uint32_t& lo) {
    __nv_bfloat16 h0 = __float2bfloat16(f0);
    __nv_bfloat16 h1 = __float2bfloat16(f1);
    __nv_bfloat16 l0 = __float2bfloat16(f0 - __bfloat162float(h0));
    __nv_bfloat16 l1 = __float2bfloat16(f1 - __bfloat162float(h1));
    lo = (uint32_t)__bfloat16_as_ushort(l0) | ((uint32_t)__bfloat16_as_ushort(l1) << 16);
    return (uint32_t)__bfloat16_as_ushort(h0) | ((uint32_t)__bfloat16_as_ushort(h1) << 16);
}

DEV_INLINE uint32_t pack_f16(float f0, float f1) {
    __half2 h = __floats2half2_rn(f0, f1);
    return *(uint32_t*)&h;
}

DEV_INLINE void packsplit8(float4 a, float4 b, uint4& hi, uint4& lo) {
    hi.x = packsplit(a.x, a.y, lo.x);
    hi.y = packsplit(a.z, a.w, lo.y);
    hi.z = packsplit(b.x, b.y, lo.z);
    hi.w = packsplit(b.z, b.w, lo.w);
}

DEV_INLINE void mma_bf16(float* d, const uint32_t* a, const uint32_t* b) {
    asm volatile(
        "mma.sync.aligned.m16n8k16.row.col.f32.bf16.bf16.f32 "
        "{%0,%1,%2,%3}, {%4,%5,%6,%7}, {%8,%9}, {%0,%1,%2,%3};"
        : "+f"(d[0]), "+f"(d[1]), "+f"(d[2]), "+f"(d[3])
        : "r"(a[0]), "r"(a[1]), "r"(a[2]), "r"(a[3]),
          "r"(b[0]), "r"(b[1]));
}

DEV_INLINE void mma_f16(float* d, const uint32_t* a, const uint32_t* b) {
    asm volatile(
        "mma.sync.aligned.m16n8k16.row.col.f32.f16.f16.f32 "
        "{%0,%1,%2,%3}, {%4,%5,%6,%7}, {%8,%9}, {%0,%1,%2,%3};"
        : "+f"(d[0]), "+f"(d[1]), "+f"(d[2]), "+f"(d[3])
        : "r"(a[0]), "r"(a[1]), "r"(a[2]), "r"(a[3]),
          "r"(b[0]), "r"(b[1]));
}

DEV_INLINE void ldsm_x4(uint32_t& r0, uint32_t& r1, uint32_t& r2, uint32_t& r3,
                        uint32_t addr) {
    asm volatile("ldmatrix.sync.aligned.m8n8.x4.shared.b16 {%0,%1,%2,%3}, [%4];"
                 : "=r"(r0), "=r"(r1), "=r"(r2), "=r"(r3) : "r"(addr));
}

DEV_INLINE void cp_async16(uint32_t dst, const void* src) {
    asm volatile("cp.async.cg.shared.global [%0], [%1], 16;" :: "r"(dst), "l"(src));
}
DEV_INLINE void cp_commit() { asm volatile("cp.async.commit_group;"); }
template<int N> DEV_INLINE void cp_wait() {
    asm volatile("cp.async.wait_group %0;" :: "n"(N));
}

// ---------------- one-shot mega weight split ----------------
constexpr int SEG0 = H2 * K2_M;
constexpr int SEG1 = Hh * K2_DT;
constexpr int SEG2 = Mdim * K2_H;
constexpr int SEG3 = LXR * K2_H;
constexpr int Q0 = SEG0 / 4;
constexpr int Q1 = SEG1 / 4;
constexpr int Q2 = SEG2 / 4;
constexpr int Q3 = SEG3 / 4;
constexpr int QT = Q0 + Q1 + Q2 + Q3;
constexpr int QH = (Vv * K2_M) / 4;
constexpr int QALL = 2 * QT + QH;

__global__ void split_all_kernel(const float* __restrict__ liw,
                                 const float* __restrict__ ldw,
                                 const float* __restrict__ low,
                                 const float* __restrict__ lxw,
                                 const float* __restrict__ hw,
                                 uint32_t* __restrict__ liw_h, uint32_t* __restrict__ liw_l,
                                 uint32_t* __restrict__ ldw_h, uint32_t* __restrict__ ldw_l,
                                 uint32_t* __restrict__ low_h, uint32_t* __restrict__ low_l,
                                 uint32_t* __restrict__ lxw_h, uint32_t* __restrict__ lxw_l,
                                 uint32_t* __restrict__ hw_h) {
    int idx = blockIdx.x * blockDim.x + threadIdx.x;
    if (idx >= QALL) return;
    if (idx >= 2 * QT) {
        int u = (idx - 2 * QT) * 4;
        int r = u / K2_M, j = u - r * K2_M;
        const float4* p = (const float4*)(hw + (size_t)r * Mdim + 2 * j);
        float4 a = p[0], b = p[1];
        uint4 o;
        o.x = pack_f16(a.x, a.y);
        o.y = pack_f16(a.z, a.w);
        o.z = pack_f16(b.x, b.y);
        o.w = pack_f16(b.z, b.w);
        *(uint4*)(hw_h + u) = o;
        return;
    }
    int l = (idx >= QT) ? 1 : 0;
    int q = idx - l * QT;
    if (q < Q0) {
        int u = q * 4;
        int r = u / K2_M, j = u - r * K2_M;
        const float4* p = (const float4*)(liw + (size_t)l * H2 * Mdim + (size_t)r * Mdim + 2 * j);
        uint4 hi, lo;
        packsplit8(p[0], p[1], hi, lo);
        *(uint4*)(liw_h + (size_t)l * SEG0 + u) = hi;
        *(uint4*)(liw_l + (size_t)l * SEG0 + u) = lo;
    } else if (q < Q0 + Q1) {
        int u = (q - Q0) * 4;
        int r = u / K2_DT, j = u - r * K2_DT;
        uint4 hi, lo;
        if (2 * j >= Rr) {
            hi = make_uint4(0, 0, 0, 0);
            lo = make_uint4(0, 0, 0, 0);
        } else {
            const float4* p = (const float4*)(ldw + (size_t)l * Hh * Rr + (size_t)r * Rr + 2 * j);
            packsplit8(p[0], p[1], hi, lo);
        }
        *(uint4*)(ldw_h + (size_t)l * SEG1 + u) = hi;
        *(uint4*)(ldw_l + (size_t)l * SEG1 + u) = lo;
    } else if (q < Q0 + Q1 + Q2) {
        int u = (q - Q0 - Q1) * 4;
        int r = u / K2_H, j = u - r * K2_H;
        const float4* p = (const float4*)(low + (size_t)l * Mdim * Hh + (size_t)r * Hh + 2 * j);
        uint4 hi, lo;
        packsplit8(p[0], p[1], hi, lo);
        *(uint4*)(low_h + (size_t)l * SEG2 + u) = hi;
        *(uint4*)(low_l + (size_t)l * SEG2 + u) = lo;
    } else {
        int u = (q - Q0 - Q1 - Q2) * 4;
        int r = u / K2_H, j = u - r * K2_H;
        uint4 hi, lo;
        if (r >= XD) {
            hi = make_uint4(0, 0, 0, 0);
            lo = make_uint4(0, 0, 0, 0);
        } else {
            const float4* p = (const float4*)(lxw + (size_t)l * XD * Hh + (size_t)r * Hh + 2 * j);
            packsplit8(p[0], p[1], hi, lo);
        }
        *(uint4*)(lxw_h + (size_t)l * SEG3 + u) = hi;
        *(uint4*)(lxw_l + (size_t)l * SEG3 + u) = lo;
    }
}

// ---------------- embedding gather + planes ----------------
__global__ void embed_kernel(const int* __restrict__ ids,
                             const float* __restrict__ emb,
                             float* __restrict__ x,
                             uint32_t* __restrict__ xph,
                             uint32_t* __restrict__ xpl) {
    int idx = blockIdx.x * blockDim.x + threadIdx.x;
    if (idx >= BS * K2_M) return;
    int row = idx / K2_M;
    int m2  = idx - row * K2_M;
    const float* e = emb + (size_t)ids[row] * Mdim + 2 * m2;
    float f0 = e[0], f1 = e[1];
    x[(size_t)row * Mdim + 2 * m2]     = f0;
    x[(size_t)row * Mdim + 2 * m2 + 1] = f1;
    uint32_t l;
    uint32_t h = packsplit(f0, f1, l);
    xph[idx] = h;
    xpl[idx] = l;
}

// ---------------- bf16x3 GEMM, 2-stage double buffer, 2 CTAs/SM ----------
template<int BN, int ACT>
__global__ __launch_bounds__(256, 2)
void gemm_bf16x3(const uint32_t* __restrict__ Ah, const uint32_t* __restrict__ Al,
                 const uint32_t* __restrict__ Wh, const uint32_t* __restrict__ Wl,
                 int K2,
                 const float* __restrict__ bias,
                 float* __restrict__ C, int ldc) {
    constexpr int NTt  = BN / 32;
    constexpr int ROWB = 80;
    constexpr int APB  = 128 * ROWB;
    constexpr int WPB  = BN * ROWB;
    constexpr int STGB = 2 * APB + 2 * WPB;
    constexpr int NCH  = (256 + 2 * BN) * 4 / 256;

    extern __shared__ __align__(16) uint32_t smu[];

    const int tid  = threadIdx.x;
    const int lane = tid & 31;
    const int wid  = tid >> 5;
    const int wm   = wid >> 2;
    const int wn   = wid & 3;
    const int i0   = blockIdx.y * 128;
    const int j0   = blockIdx.x * BN;
    const int lq   = lane & 3;
    const int lg   = lane >> 2;

    const uint32_t sb = (uint32_t)__cvta_generic_to_shared(smu);

    const uint32_t* src[NCH];
    uint32_t dst[NCH];
    #pragma unroll
    for (int uu = 0; uu < NCH; uu++) {
        int c  = uu * 256 + tid;
        int r2 = c >> 2;
        int q  = c & 3;
        const uint32_t* gbase;
        int pofs, r;
        if (r2 < 128)            { r = r2;            gbase = Ah + (size_t)i0 * K2; pofs = 0; }
        else if (r2 < 256)       { r = r2 - 128;      gbase = Al + (size_t)i0 * K2; pofs = APB; }
        else if (r2 < 256 + BN)  { r = r2 - 256;      gbase = Wh + (size_t)j0 * K2; pofs = 2 * APB; }
        else                     { r = r2 - 256 - BN; gbase = Wl + (size_t)j0 * K2; pofs = 2 * APB + WPB; }
        src[uu] = gbase + (size_t)r * K2 + q * 4;
        dst[uu] = sb + pofs + r * ROWB + q * 16;
    }

    const uint32_t aRow = (uint32_t)((wm * 64 + (lane & 15)) * ROWB + ((lane >> 4) << 4));
    const uint32_t bRow = (uint32_t)((wn * (NTt * 8) + ((lane >> 4) << 3) + (lane & 7)) * ROWB
                                     + (((lane >> 3) & 1) << 4));

    float acc[4][NTt][4];
    #pragma unroll
    for (int m = 0; m < 4; m++)
        #pragma unroll
        for (int n = 0; n < NTt; n++)
            #pragma unroll
            for (int c = 0; c < 4; c++) acc[m][n][c] = 0.f;

    const int nk = K2 >> 4;

    #pragma unroll
    for (int uu = 0; uu < NCH; uu++) cp_async16(dst[uu], src[uu]);
    cp_commit();

    for (int t = 0; t < nk; t++) {
        cp_wait<0>();
        __syncthreads();
        if (t + 1 < nk) {
            uint32_t so = (uint32_t)((t + 1) & 1) * STGB;
            int ko = (t + 1) * 16;
            #pragma unroll
            for (int uu = 0; uu < NCH; uu++)
                cp_async16(dst[uu] + so, src[uu] + ko);
            cp_commit();
        }

        const uint32_t st = sb + (uint32_t)(t & 1) * STGB;

        #pragma unroll
        for (int h = 0; h < 2; h++) {
            uint32_t ah[4][4], al[4][4], bh[NTt][2], bl[NTt][2];
            #pragma unroll
            for (int m = 0; m < 4; m++) {
                uint32_t a0 = st + aRow + m * (16 * ROWB) + h * 32;
                ldsm_x4(ah[m][0], ah[m][1], ah[m][2], ah[m][3], a0);
                ldsm_x4(al[m][0], al[m][1], al[m][2], al[m][3], a0 + APB);
            }
            #pragma unroll
            for (int j = 0; j < NTt / 2; j++) {
                uint32_t b0 = st + 2 * APB + bRow + j * (16 * ROWB) + h * 32;
                ldsm_x4(bh[2*j][0], bh[2*j][1], bh[2*j+1][0], bh[2*j+1][1], b0);
                ldsm_x4(bl[2*j][0], bl[2*j][1], bl[2*j+1][0], bl[2*j+1][1], b0 + WPB);
            }
            #pragma unroll
            for (int m = 0; m < 4; m++)
                #pragma unroll
                for (int n = 0; n < NTt; n++)
                    mma_bf16(acc[m][n], ah[m], bh[n]);
            #pragma unroll
            for (int m = 0; m < 4; m++)
                #pragma unroll
                for (int n = 0; n < NTt; n++)
                    mma_bf16(acc[m][n], ah[m], bl[n]);
            #pragma unroll
            for (int m = 0; m < 4; m++)
                #pragma unroll
                for (int n = 0; n < NTt; n++)
                    mma_bf16(acc[m][n], al[m], bh[n]);
        }
    }

    #pragma unroll
    for (int m = 0; m < 4; m++) {
        int gi = i0 + wm * 64 + m * 16 + lg;
        #pragma unroll
        for (int n = 0; n < NTt; n++) {
            int gj = j0 + wn * (NTt * 8) + n * 8 + 2 * lq;
            float b0 = bias[gj], b1 = bias[gj + 1];
            float v0 = acc[m][n][0] + b0;
            float v1 = acc[m][n][1] + b1;
            float v2 = acc[m][n][2] + b0;
            float v3 = acc[m][n][3] + b1;
            if (ACT == 1) {
                v0 = softplusf(v0); v1 = softplusf(v1);
                v2 = softplusf(v2); v3 = softplusf(v3);
            }
            *(float2*)(C + (size_t)gi * ldc + gj)       = make_float2(v0, v1);
            *(float2*)(C + (size_t)(gi + 8) * ldc + gj) = make_float2(v2, v3);
        }
    }
}

// ---------------- fp16 single-pass GEMM (head), 3-stage ----------------
template<int BN>
__global__ __launch_bounds__(256, 2)
void gemm_fp16(const uint32_t* __restrict__ Ah, const uint32_t* __restrict__ Wh,
               int K2,
               const float* __restrict__ bias,
               float* __restrict__ C, int ldc) {
    constexpr int NTt  = BN / 32;
    constexpr int ROWB = 80;
    constexpr int APB  = 128 * ROWB;
    constexpr int WPB  = BN * ROWB;
    constexpr int STGB = APB + WPB;
    constexpr int NCH  = (128 + BN) * 4 / 256;

    extern __shared__ __align__(16) uint32_t smu[];

    const int tid  = threadIdx.x;
    const int lane = tid & 31;
    const int wid  = tid >> 5;
    const int wm   = wid >> 2;
    const int wn   = wid & 3;
    const int i0   = blockIdx.y * 128;
    const int j0   = blockIdx.x * BN;
    const int lq   = lane & 3;
    const int lg   = lane >> 2;

    const uint32_t sb = (uint32_t)__cvta_generic_to_shared(smu);

    const uint32_t* src[NCH];
    uint32_t dst[NCH];
    #pragma unroll
    for (int uu = 0; uu < NCH; uu++) {
        int c  = uu * 256 + tid;
        int r2 = c >> 2;
        int q  = c & 3;
        const uint32_t* gbase;
        int pofs, r;
        if (r2 < 128) { r = r2;       gbase = Ah + (size_t)i0 * K2; pofs = 0; }
        else          { r = r2 - 128; gbase = Wh + (size_t)j0 * K2; pofs = APB; }
        src[uu] = gbase + (size_t)r * K2 + q * 4;
        dst[uu] = sb + pofs + r * ROWB + q * 16;
    }

    const uint32_t aRow = (uint32_t)((wm * 64 + (lane & 15)) * ROWB + ((lane >> 4) << 4));
    const uint32_t bRow = (uint32_t)((wn * (NTt * 8) + ((lane >> 4) << 3) + (lane & 7)) * ROWB
                                     + (((lane >> 3) & 1) << 4));

    float acc[4][NTt][4];
    #pragma unroll
    for (int m = 0; m < 4; m++)
        #pragma unroll
        for (int n = 0; n < NTt; n++)
            #pragma unroll
            for (int c = 0; c < 4; c++) acc[m][n][c] = 0.f;

    const int nk = K2 >> 4;

    #pragma unroll
    for (int uu = 0; uu < NCH; uu++) cp_async16(dst[uu], src[uu]);
    cp_commit();
    #pragma unroll
    for (int uu = 0; uu < NCH; uu++) cp_async16(dst[uu] + STGB, src[uu] + 16);
    cp_commit();

    for (int t = 0; t < nk; t++) {
        if (t + 1 < nk) { cp_wait<1>(); } else { cp_wait<0>(); }
        __syncthreads();
        if (t + 2 < nk) {
            uint32_t so = (uint32_t)((t + 2) % 3) * STGB;
            int ko = (t + 2) * 16;
            #pragma unroll
            for (int uu = 0; uu < NCH; uu++)
                cp_async16(dst[uu] + so, src[uu] + ko);
            cp_commit();
        }

        const uint32_t st = sb + (uint32_t)(t % 3) * STGB;

        uint32_t ah2[2][4][4], bh2[2][NTt][2];
        #pragma unroll
        for (int h = 0; h < 2; h++) {
            #pragma unroll
            for (int m = 0; m < 4; m++) {
                uint32_t a0 = st + aRow + m * (16 * ROWB) + h * 32;
                ldsm_x4(ah2[h][m][0], ah2[h][m][1], ah2[h][m][2], ah2[h][m][3], a0);
            }
            #pragma unroll
            for (int j = 0; j < NTt / 2; j++) {
                uint32_t b0 = st + APB + bRow + j * (16 * ROWB) + h * 32;
                ldsm_x4(bh2[h][2*j][0], bh2[h][2*j][1],
                        bh2[h][2*j+1][0], bh2[h][2*j+1][1], b0);
            }
        }
        #pragma unroll
        for (int h = 0; h < 2; h++)
            #pragma unroll
            for (int m = 0; m < 4; m++)
                #pragma unroll
                for (int n = 0; n < NTt; n++)
                    mma_f16(acc[m][n], ah2[h][m], bh2[h][n]);
    }

    #pragma unroll
    for (int m = 0; m < 4; m++) {
        int gi = i0 + wm * 64 + m * 16 + lg;
        #pragma unroll
        for (int n = 0; n < NTt; n++) {
            int gj = j0 + wn * (NTt * 8) + n * 8 + 2 * lq;
            float b0 = bias[gj], b1 = bias[gj + 1];
            *(float2*)(C + (size_t)gi * ldc + gj) =
                make_float2(acc[m][n][0] + b0, acc[m][n][1] + b1);
            *(float2*)(C + (size_t)(gi + 8) * ldc + gj) =
                make_float2(acc[m][n][2] + b0, acc[m][n][3] + b1);
        }
    }
}

// ---------------- conv + silu -> ures + u planes + dt pad zero ------------
__global__ void conv_silu_kernel(const float* __restrict__ xr,
                                 const float* __restrict__ cw,
                                 const float* __restrict__ cb,
                                 float2* __restrict__ ures,
                                 uint32_t* __restrict__ uh,
                                 uint32_t* __restrict__ ul,
                                 uint32_t* __restrict__ dth,
                                 uint32_t* __restrict__ dtl) {
    int idx = blockIdx.x * blockDim.x + threadIdx.x;
    if (idx >= BS * K2_H) return;
    int row = idx / K2_H;
    int h2  = idx - row * K2_H;
    int h   = 2 * h2;
    int s   = row % Ss;
    int b   = row / Ss;

    const float4* cw4 = (const float4*)cw;
    float4 ta = cw4[h], tb = cw4[h + 1];
    float a0 = cb[h], a1 = cb[h + 1];
    #pragma unroll
    for (int k = 0; k < 4; k++) {
        int sp = s - 3 + k;
        if (sp >= 0) {
            float2 xv = *(const float2*)(xr + (size_t)(b * Ss + sp) * H2 + h);
            float wa = (k == 0) ? ta.x : (k == 1) ? ta.y : (k == 2) ? ta.z : ta.w;
            float wb = (k == 0) ? tb.x : (k == 1) ? tb.y : (k == 2) ? tb.z : tb.w;
            a0 += wa * xv.x;
            a1 += wb * xv.y;
        }
    }
    float u0 = silu_fast(a0), u1 = silu_fast(a1);
    float2 rv = *(const float2*)(xr + (size_t)row * H2 + Hh + h);
    *(float4*)(ures + (size_t)row * Hh + h) = make_float4(u0, rv.x, u1, rv.y);
    uint32_t lo;
    uint32_t hi = packsplit(u0, u1, lo);
    uh[idx] = hi;
    ul[idx] = lo;
    if (h2 < 8) {
        dth[(size_t)row * K2_DT + 24 + h2] = 0;
        dtl[(size_t)row * K2_DT + 24 + h2] = 0;
    }
}

// ---------------- post-linx: add bias, scatter dt planes + bcv ------------
__global__ void post_linx_kernel(const float* __restrict__ xw,
                                 const float* __restrict__ lxb,
                                 uint32_t* __restrict__ dth,
                                 uint32_t* __restrict__ dtl,
                                 float* __restrict__ bcv) {
    int idx = blockIdx.x * blockDim.x + threadIdx.x;
    if (idx >= BS * 40) return;
    int row = idx / 40;
    int p   = idx - row * 40;
    int j0  = 2 * p;
    float v0 = xw[(size_t)row * LXR + j0]     + lxb[j0];
    float v1 = xw[(size_t)row * LXR + j0 + 1] + lxb[j0 + 1];
    if (p < 24) {
        uint32_t lo;
        uint32_t hi = packsplit(v0, v1, lo);
        dth[(size_t)row * K2_DT + p] = hi;
        dtl[(size_t)row * K2_DT + p] = lo;
    } else {
        // cols 48..79 -> bcv[0..31]: B at [0..16), C at [16..32)
        *(float2*)(bcv + (size_t)row * 32 + (j0 - Rr)) = make_float2(v0, v1);
    }
}

// ---------------- scan + gate, depth-4 prefetch ----------------
__global__ void scan_gate_kernel(const float* __restrict__ delta,
                                 const float2* __restrict__ ures,
                                 const float* __restrict__ bcv,
                                 const float* __restrict__ Dp,
                                 uint32_t* __restrict__ yh,
                                 uint32_t* __restrict__ yl) {
    int gwarp = (blockIdx.x * blockDim.x + threadIdx.x) >> 5;
    if (gwarp >= Bb * (Hh / 2)) return;
    int lane = threadIdx.x & 31;
    int half = lane >> 4;
    int n    = lane & 15;
    int b    = gwarp / (Hh / 2);
    int hp   = gwarp % (Hh / 2);
    int h    = hp * 2 + half;

    const float An = -(float)(n + 1);
    const float Dh = Dp[h];
    float state = 0.f;

    const int base = b * Ss;

    float  pd[4], pB[4], pC[4];
    float2 pu[4];
    #pragma unroll
    for (int k = 0; k < 4; k++) {
        int r = base + k;
        pd[k] = __ldg(delta + (size_t)r * Hh + h);
        pu[k] = __ldg(ures + (size_t)r * Hh + h);
        pB[k] = __ldg(bcv + (size_t)r * 32 + n);
        pC[k] = __ldg(bcv + (size_t)r * 32 + 16 + n);
    }

    float dA  = __expf(pd[0] * An);
    float dBu = pd[0] * pB[0] * pu[0].x;

    #pragma unroll 4
    for (int s = 0; s < Ss; s++) {
        const int slot = s & 3;
        const int ns   = (s + 1) & 3;
        int row = base + s;

        float uv  = pu[slot].x;
        float res = pu[slot].y;
        float Cn  = pC[slot];

        state = dA * state + dBu;

        if (s + 4 < Ss) {
            int r = row + 4;
            pd[slot] = __ldg(delta + (size_t)r * Hh + h);
            pu[slot] = __ldg(ures + (size_t)r * Hh + h);
            pB[slot] = __ldg(bcv + (size_t)r * 32 + n);
            pC[slot] = __ldg(bcv + (size_t)r * 32 + 16 + n);
        }

        dA  = __expf(pd[ns] * An);
        dBu = pd[ns] * pB[ns] * pu[ns].x;

        float val = state * Cn;
        val += __shfl_xor_sync(0xffffffffu, val, 8);
        val += __shfl_xor_sync(0xffffffffu, val, 4);
        val += __shfl_xor_sync(0xffffffffu, val, 2);
        val += __shfl_xor_sync(0xffffffffu, val, 1);
        float yv = (val + uv * Dh) * silu_fast(res);
        float y1 = __shfl_sync(0xffffffffu, yv, 16);
        if (lane == 0) {
            uint32_t lo;
            uint32_t hi = packsplit(yv, y1, lo);
            yh[(size_t)row * K2_H + hp] = hi;
            yl[(size_t)row * K2_H + hp] = lo;
        }
    }
}

// ---------------- x += rmsnorm(mo) * w ; emit x planes ----------------
__global__ void rmsnorm_add_kernel(float* __restrict__ x,
                                   const float* __restrict__ mo,
                                   const float* __restrict__ w,
                                   uint32_t* __restrict__ xph,
                                   uint32_t* __restrict__ xpl) {
    int row = blockIdx.x;
    const float* r = mo + (size_t)row * Mdim;
    float ss = 0.f;
    for (int m = threadIdx.x; m < Mdim; m += blockDim.x) {
        float v = r[m];
        ss += v * v;
    }
    __shared__ float sh[8];
    ss = warp_sum(ss);
    int wid = threadIdx.x >> 5, lane = threadIdx.x & 31;
    if (lane == 0) sh[wid] = ss;
    __syncthreads();
    if (wid == 0) {
        float v = (lane < (int)(blockDim.x >> 5)) ? sh[lane] : 0.f;
        v = warp_sum(v);
        if (lane == 0) sh[0] = v;
    }
    __syncthreads();
    float scale = rsqrtf(sh[0] / (float)Mdim + 1e-15f);
    float* xp = x + (size_t)row * Mdim;
    for (int m2 = threadIdx.x; m2 < K2_M; m2 += blockDim.x) {
        int m = 2 * m2;
        float v0 = xp[m]     + r[m]     * scale * w[m];
        float v1 = xp[m + 1] + r[m + 1] * scale * w[m + 1];
        xp[m] = v0; xp[m + 1] = v1;
        uint32_t lo;
        uint32_t hi = packsplit(v0, v1, lo);
        xph[(size_t)row * K2_M + m2] = hi;
        xpl[(size_t)row * K2_M + m2] = lo;
    }
}

// ---------------- final rmsnorm -> fp16 planes (head input) ----------------
__global__ void rmsnorm_final_kernel(const float* __restrict__ x,
                                     const float* __restrict__ w,
                                     uint32_t* __restrict__ xnf) {
    int row = blockIdx.x;
    const float* r = x + (size_t)row * Mdim;
    float ss = 0.f;
    for (int m = threadIdx.x; m < Mdim; m += blockDim.x) {
        float v = r[m];
        ss += v * v;
    }
    __shared__ float sh[8];
    ss = warp_sum(ss);
    int wid = threadIdx.x >> 5, lane = threadIdx.x & 31;
    if (lane == 0) sh[wid] = ss;
    __syncthreads();
    if (wid == 0) {
        float v = (lane < (int)(blockDim.x >> 5)) ? sh[lane] : 0.f;
        v = warp_sum(v);
        if (lane == 0) sh[0] = v;
    }
    __syncthreads();
    float scale = rsqrtf(sh[0] / (float)Mdim + 1e-15f);
    for (int m2 = threadIdx.x; m2 < K2_M; m2 += blockDim.x) {
        int m = 2 * m2;
        xnf[(size_t)row * K2_M + m2] =
            pack_f16(r[m] * scale * w[m], r[m + 1] * scale * w[m + 1]);
    }
}

// ---------------- launch ----------------
extern "C" void kernel_launch(void* const* d_in, const int* in_sizes, int n_in,
                              void* d_out, int out_size) {
    const int*   ids = (const int*)  d_in[0];
    const float* emb = (const float*)d_in[1];
    const float* liw = (const float*)d_in[2];
    const float* lib = (const float*)d_in[3];
    const float* cw  = (const float*)d_in[4];
    const float* cb  = (const float*)d_in[5];
    const float* lxw = (const float*)d_in[6];
    const float* lxb = (const float*)d_in[7];
    const float* ldw = (const float*)d_in[8];
    const float* ldb = (const float*)d_in[9];
    const float* low = (const float*)d_in[10];
    const float* lob = (const float*)d_in[11];
    const float* Dp  = (const float*)d_in[12];
    const float* bnw = (const float*)d_in[13];
    const float* fnw = (const float*)d_in[14];
    const float* hw  = (const float*)d_in[15];
    const float* hb  = (const float*)d_in[16];
    float* out = (float*)d_out;

    float *x, *xr, *delta, *mo, *xw, *zb, *bcv;
    float2 *ures;
    cudaGetSymbolAddress((void**)&x,     g_x);
    cudaGetSymbolAddress((void**)&xr,    g_xr);
    cudaGetSymbolAddress((void**)&delta, g_delta);
    cudaGetSymbolAddress((void**)&mo,    g_mo);
    cudaGetSymbolAddress((void**)&xw,    g_xw);
    cudaGetSymbolAddress((void**)&zb,    g_zb);
    cudaGetSymbolAddress((void**)&ures,  g_ures);
    cudaGetSymbolAddress((void**)&bcv,   g_bcv);

    uint32_t *xp_h, *xp_l, *uh, *ul, *act_h, *act_l;
    uint32_t *liw_h, *liw_l, *ldw_h, *ldw_l, *low_h, *low_l, *lxw_h, *lxw_l, *hw_h;
    cudaGetSymbolAddress((void**)&xp_h,  g_xp_h);
    cudaGetSymbolAddress((void**)&xp_l,  g_xp_l);
    cudaGetSymbolAddress((void**)&uh,    g_uh);
    cudaGetSymbolAddress((void**)&ul,    g_ul);
    cudaGetSymbolAddress((void**)&act_h, g_act_h);
    cudaGetSymbolAddress((void**)&act_l, g_act_l);
    cudaGetSymbolAddress((void**)&liw_h, g_liw_h);
    cudaGetSymbolAddress((void**)&liw_l, g_liw_l);
    cudaGetSymbolAddress((void**)&ldw_h, g_ldw_h);
    cudaGetSymbolAddress((void**)&ldw_l, g_ldw_l);
    cudaGetSymbolAddress((void**)&low_h, g_low_h);
    cudaGetSymbolAddress((void**)&low_l, g_low_l);
    cudaGetSymbolAddress((void**)&lxw_h, g_lxw_h);
    cudaGetSymbolAddress((void**)&lxw_l, g_lxw_l);
    cudaGetSymbolAddress((void**)&hw_h,  g_hw_h);

    const int SM128  = 2 * (2 * 128 * 80 + 2 * 128 * 80);  // 81920
    const int SM64   = 2 * (2 * 128 * 80 + 2 * 64 * 80);   // 61440
    const int SMF128 = 3 * (128 + 128) * 80;               // 61440
    cudaFuncSetAttribute((const void*)gemm_bf16x3<128, 0>,
                         cudaFuncAttributeMaxDynamicSharedMemorySize, SM128);
    cudaFuncSetAttribute((const void*)gemm_bf16x3<128, 1>,
                         cudaFuncAttributeMaxDynamicSharedMemorySize, SM128);
    cudaFuncSetAttribute((const void*)gemm_bf16x3<64, 0>,
                         cudaFuncAttributeMaxDynamicSharedMemorySize, SM64);
    cudaFuncSetAttribute((const void*)gemm_fp16<128>,
                         cudaFuncAttributeMaxDynamicSharedMemorySize, SMF128);

    embed_kernel<<<(BS * K2_M + 255) / 256, 256>>>(ids, emb, x, xp_h, xp_l);
    split_all_kernel<<<(QALL + 255) / 256, 256>>>(
        liw, ldw, low, lxw, hw,
        liw_h, liw_l, ldw_h, ldw_l, low_h, low_l, lxw_h, lxw_l, hw_h);

    for (int l = 0; l < Ll; l++) {
        gemm_bf16x3<128, 0><<<dim3(H2 / 128, BS / 128), 256, SM128>>>(
            xp_h, xp_l,
            liw_h + (size_t)l * SEG0, liw_l + (size_t)l * SEG0,
            K2_M, lib + (size_t)l * H2, xr, H2);

        conv_silu_kernel<<<(BS * K2_H + 255) / 256, 256>>>(
            xr, cw + (size_t)l * Hh * Kk, cb + (size_t)l * Hh,
            ures, uh, ul, act_h, act_l);

        // linx via proven BN=64 template: [BS,768] x [128,768]^T -> xw[BS,128]
        gemm_bf16x3<64, 0><<<dim3(LXR / 64, BS / 128), 256, SM64>>>(
            uh, ul,
            lxw_h + (size_t)l * SEG3, lxw_l + (size_t)l * SEG3,
            K2_H, zb, xw, LXR);

        post_linx_kernel<<<(BS * 40 + 255) / 256, 256>>>(
            xw, lxb + (size_t)l * XD, act_h, act_l, bcv);

        gemm_bf16x3<128, 1><<<dim3(Hh / 128, BS / 128), 256, SM128>>>(
            act_h, act_l,
            ldw_h + (size_t)l * SEG1, ldw_l + (size_t)l * SEG1,
            K2_DT, ldb + (size_t)l * Hh, delta, Hh);

        scan_gate_kernel<<<(Bb * (Hh / 2) * 32 + 255) / 256, 256>>>(
            delta, ures, bcv, Dp + (size_t)l * Hh, act_h, act_l);

        gemm_bf16x3<64, 0><<<dim3(Mdim / 64, BS / 128), 256, SM64>>>(
            act_h, act_l,
            low_h + (size_t)l * SEG2, low_l + (size_t)l * SEG2,
            K2_H, lob + (size_t)l * Mdim, mo, Mdim);

        rmsnorm_add_kernel<<<BS, 256>>>(x, mo, bnw + (size_t)l * Mdim, xp_h, xp_l);
    }

    rmsnorm_final_kernel<<<BS, 256>>>(x, fnw, act_h);

    gemm_fp16<128><<<dim3(Vv / 128, BS / 128), 256, SMF128>>>(
        act_h, hw_h, K2_M, hb, out, Vv);
}